// round 6
// baseline (speedup 1.0000x reference)
#include <cuda_runtime.h>

#define CI 64
#define DI 128
#define SS 16
#define RR 4
#define KK 4
#define HH 48
#define WW 48
#define LL 2304
#define TT 4
#define NB 5          // slices: 0..3 = bias frames, 4 = sequential pipeline
#define SB 4
#define NCH 16
#define LCH 144

// ---------------- scratch (static device globals; no allocations) ----------------
__device__ float g_prev[CI*LL];
__device__ float g_cur [CI*LL];
__device__ float g_kl  [CI*LL];
__device__ float g_xln [TT*CI*LL];
__device__ float g_bias[TT*CI*LL];
__device__ float g_xz  [NB*2*DI*LL];   // only z-half (d>=DI) is consumed downstream
__device__ float g_xc  [NB*DI*LL];
__device__ float g_xcT [NB*DI*LL];
__device__ float g_dt  [NB*KK*DI*LL];
__device__ float g_Bt  [NB*KK*LL*SS];
__device__ float g_Ct  [NB*KK*LL*SS];
__device__ float g_y   [NB*KK*DI*LL];

// ---------------- init: y=0: prev/cur/kl(t0); y=1..4: xln[t] ----------------
// grid (72, 5), block 128
__global__ void k_init(const float* __restrict__ dz, const float* __restrict__ sigma,
                       const float* __restrict__ img,
                       const float* __restrict__ niw, const float* __restrict__ nib,
                       const float* __restrict__ ndw, const float* __restrict__ ndb){
    __shared__ float sx[CI*33];
    __shared__ float scur[CI*33];
    __shared__ float smu[32], srs[32], slp[32], slq[32];
    int l0 = blockIdx.x*32, tid = threadIdx.x;
    if (blockIdx.y == 0){
        for (int j = tid; j < CI*32; j += 128){
            int c = j >> 5, li = j & 31;
            sx[c*33 + li] = dz[c*LL + l0 + li];
        }
        __syncthreads();
        if (tid < 32){
            float s0 = 0.f, s1 = 0.f;
            for (int c = 0; c < CI; c++){ float v = sx[c*33 + tid]; s0 += v; s1 += v*v; }
            float mu = s0*(1.f/CI);
            smu[tid] = mu;
            srs[tid] = rsqrtf(s1*(1.f/CI) - mu*mu + 1e-6f);
        }
        __syncthreads();
        for (int j = tid; j < CI*32; j += 128){
            int c = j >> 5, li = j & 31;
            float pv = (sx[c*33+li] - smu[li])*srs[li]*ndw[c] + ndb[c];
            float cv = pv * __expf(sigma[c*LL + l0 + li]);
            g_prev[c*LL + l0 + li] = pv;
            g_cur [c*LL + l0 + li] = cv;
            sx  [c*33 + li] = pv;
            scur[c*33 + li] = cv;
        }
        __syncthreads();
        if (tid < 32){
            float mp = -1e30f, mq = -1e30f;
            for (int c = 0; c < CI; c++){
                mp = fmaxf(mp, sx  [c*33 + tid]);
                mq = fmaxf(mq, scur[c*33 + tid]);
            }
            float ep = 0.f, eq = 0.f;
            for (int c = 0; c < CI; c++){
                ep += __expf(sx  [c*33 + tid] - mp);
                eq += __expf(scur[c*33 + tid] - mq);
            }
            slp[tid] = mp + __logf(ep);
            slq[tid] = mq + __logf(eq);
        }
        __syncthreads();
        for (int j = tid; j < CI*32; j += 128){
            int c = j >> 5, li = j & 31;
            float lp = sx  [c*33+li] - slp[li];
            float lq = scur[c*33+li] - slq[li];
            g_kl[c*LL + l0 + li] = __expf(lp)*(lp - lq);
        }
    } else {
        int t = blockIdx.y - 1;
        for (int j = tid; j < CI*32; j += 128){
            int c = j >> 5, li = j & 31;
            sx[c*33 + li] = img[(t*CI + c)*LL + l0 + li];
        }
        __syncthreads();
        if (tid < 32){
            float s0 = 0.f, s1 = 0.f;
            for (int c = 0; c < CI; c++){ float v = sx[c*33 + tid]; s0 += v; s1 += v*v; }
            float mu = s0*(1.f/CI);
            smu[tid] = mu;
            srs[tid] = rsqrtf(s1*(1.f/CI) - mu*mu + 1e-6f);
        }
        __syncthreads();
        for (int j = tid; j < CI*32; j += 128){
            int c = j >> 5, li = j & 31;
            g_xln[(t*CI + c)*LL + l0 + li] = (sx[c*33+li] - smu[li])*srs[li]*niw[c] + nib[c];
        }
    }
}

// ---------------- fused in-projection GEMM + depthwise conv + silu ----------------
// grid (256, nf), block 256. dp<128: xc path (gemm+conv+silu -> xc,xcT); dp>=128: z path (gemm -> xz)
__global__ __launch_bounds__(256) void k_inconv(const float* __restrict__ in_w,
                                                const float* __restrict__ in_b,
                                                const float* __restrict__ cw,
                                                const float* __restrict__ cb,
                                                int m, int srcsel, int bofs){
    __shared__ float sw[64];
    __shared__ float sin[LL];
    __shared__ float sc[48*49];
    int dp = blockIdx.x;
    int fb = blockIdx.y, slice = fb + bofs;
    int tid = threadIdx.x;
    if (tid < 64) sw[tid] = __ldg(&in_w[(m*256 + dp)*64 + tid]);
    bool isx = (dp < DI);
    float w9[9]; float cbias = 0.f;
    if (isx){
        #pragma unroll
        for (int j = 0; j < 9; j++) w9[j] = __ldg(&cw[(m*DI + dp)*9 + j]);
        cbias = __ldg(&cb[m*DI + dp]);
    }
    float bin = __ldg(&in_b[m*256 + dp]);
    __syncthreads();
    const float* src = (srcsel ? (g_xln + fb*CI*LL) : g_kl);
    float acc[9];
    #pragma unroll
    for (int j = 0; j < 9; j++) acc[j] = bin;
    for (int c = 0; c < 64; c++){
        float wv = sw[c];
        const float* xr = src + c*LL + tid;
        #pragma unroll
        for (int j = 0; j < 9; j++) acc[j] += wv * __ldg(&xr[j*256]);
    }
    if (!isx){
        float* o = g_xz + ((size_t)slice*2*DI + dp)*LL + tid;
        #pragma unroll
        for (int j = 0; j < 9; j++) o[j*256] = acc[j];
        return;
    }
    #pragma unroll
    for (int j = 0; j < 9; j++) sin[tid + j*256] = acc[j];
    __syncthreads();
    for (int i = tid; i < LL; i += 256){
        int h = i/48, w = i%48;
        float a = 0.f;
        #pragma unroll
        for (int ky = 0; ky < 3; ky++){
            int hy = h + ky - 1;
            if (hy < 0 || hy >= 48) continue;
            #pragma unroll
            for (int kx = 0; kx < 3; kx++){
                int wx = w + kx - 1;
                if (wx < 0 || wx >= 48) continue;
                a += w9[ky*3+kx] * sin[hy*48 + wx];
            }
        }
        a += cbias;
        a = a / (1.f + __expf(-a));
        sc[h*49 + w] = a;
    }
    __syncthreads();
    float* oc = g_xc  + ((size_t)slice*DI + dp)*LL;
    float* ot = g_xcT + ((size_t)slice*DI + dp)*LL;
    for (int i = tid; i < LL; i += 256){
        int h = i/48, w = i%48;
        oc[i] = sc[h*49 + w];
        ot[i] = sc[w*49 + h];
    }
}

// ---------------- x-projection + dt(softplus) + B/C transpose; grid(48,K,nf), block 192 ----------------
__global__ void k_xproj(const float* __restrict__ xpw, const float* __restrict__ dtw,
                        const float* __restrict__ dtb, int m, int bofs){
    __shared__ float s1[DI*48];
    __shared__ float s2[36*DI];
    __shared__ float sdw[DI*RR];
    __shared__ float sdb[DI];
    int lt = blockIdx.x, k = blockIdx.y, slice = blockIdx.z + bofs, tid = threadIdx.x;
    const float* wk = xpw + (m*KK + k)*36*DI;
    for (int j = tid; j < 36*DI; j += 192) s2[j] = __ldg(&wk[j]);
    const float* dwk = dtw + (m*KK + k)*DI*RR;
    for (int j = tid; j < DI*RR; j += 192) sdw[j] = __ldg(&dwk[j]);
    if (tid < DI) sdb[tid] = __ldg(&dtb[(m*KK + k)*DI + tid]);
    bool fwd = (k < 2);
    const float* src = ((k & 1) ? g_xcT : g_xc) + (size_t)slice*DI*LL;
    for (int j = tid; j < DI*48; j += 192){
        int d = j/48, ls = j%48;
        int gl = fwd ? (lt*48 + ls) : (LL-1 - (lt*48 + ls));
        s1[j] = src[d*LL + gl];
    }
    __syncthreads();
    int ls = tid % 48, rg = tid / 48;
    float acc[9];
    #pragma unroll
    for (int i = 0; i < 9; i++) acc[i] = 0.f;
    for (int c = 0; c < DI; c++){
        float xv = s1[c*48 + ls];
        #pragma unroll
        for (int i = 0; i < 9; i++) acc[i] += s2[(rg*9 + i)*DI + c] * xv;
    }
    __syncthreads();
    #pragma unroll
    for (int i = 0; i < 9; i++) s1[(rg*9 + i)*48 + ls] = acc[i];
    __syncthreads();
    float* dto = g_dt + ((size_t)(slice*KK + k)*DI)*LL + lt*48;
    #pragma unroll 4
    for (int i = 0; i < 32; i++){
        int d = rg + 4*i;
        float v = sdb[d];
        #pragma unroll
        for (int r = 0; r < 4; r++) v += sdw[d*4 + r] * s1[r*48 + ls];
        v = fmaxf(v, 0.f) + log1pf(__expf(-fabsf(v)));
        dto[d*LL + ls] = v;
    }
    float* bt = g_Bt + ((size_t)(slice*KK + k)*LL + lt*48)*SS;
    float* ct = g_Ct + ((size_t)(slice*KK + k)*LL + lt*48)*SS;
    for (int j = tid; j < 48*SS; j += 192){
        int lls = j/SS, s = j%SS;
        bt[lls*SS + s] = s1[(4 + s)*48 + lls];
        ct[lls*SS + s] = s1[(20 + s)*48 + lls];
    }
}

// ---------------- chunked scan + y = sum_s h*C; grid(DI,KK,nf), 256 thr ----------------
__global__ void k_scan(const float* __restrict__ A_logs, int m, int bofs){
    __shared__ float sdt [LL];
    __shared__ float sdtx[LL];
    __shared__ float pA[256], pH[256], hI[256];
    int d = blockIdx.x, k = blockIdx.y, slice = blockIdx.z + bofs, tid = threadIdx.x;
    int s = tid & 15, c = tid >> 4;
    float Av = -__expf(__ldg(&A_logs[((m*KK + k)*DI + d)*SS + s]));
    const float* dtrow = g_dt + ((size_t)(slice*KK + k)*DI + d)*LL;
    const float* xrow  = ((k & 1) ? g_xcT : g_xc) + ((size_t)slice*DI + d)*LL;
    bool fwd = (k < 2);
    for (int i = tid; i < LL; i += 256){
        float dv = dtrow[i];
        float xv = fwd ? xrow[i] : xrow[LL-1-i];
        sdt[i]  = dv;
        sdtx[i] = dv * xv;
    }
    __syncthreads();
    const float* bt = g_Bt + ((size_t)(slice*KK + k)*LL)*SS;
    const float* ct = g_Ct + ((size_t)(slice*KK + k)*LL)*SS;
    float ap = 1.f, h = 0.f;
    int l0 = c*LCH;
    #pragma unroll 4
    for (int i = 0; i < LCH; i++){
        int l = l0 + i;
        float da = __expf(Av * sdt[l]);
        ap *= da;
        h = da*h + sdtx[l] * __ldg(&bt[l*SS + s]);
    }
    pA[tid] = ap; pH[tid] = h;
    __syncthreads();
    if (tid < 16){
        float hh = 0.f;
        #pragma unroll
        for (int cc = 0; cc < NCH; cc++){
            hI[cc*16 + tid] = hh;
            hh = pA[cc*16 + tid]*hh + pH[cc*16 + tid];
        }
    }
    __syncthreads();
    h = hI[tid];
    float* yrow = g_y + ((size_t)(slice*KK + k)*DI + d)*LL;
    #pragma unroll 2
    for (int i = 0; i < LCH; i++){
        int l = l0 + i;
        float da = __expf(Av * sdt[l]);
        h = da*h + sdtx[l] * __ldg(&bt[l*SS + s]);
        float v = h * __ldg(&ct[l*SS + s]);
        v += __shfl_xor_sync(0xffffffffu, v, 1);
        v += __shfl_xor_sync(0xffffffffu, v, 2);
        v += __shfl_xor_sync(0xffffffffu, v, 4);
        v += __shfl_xor_sync(0xffffffffu, v, 8);
        if (s == 0){
            int ol = fwd ? l : (LL-1-l);
            yrow[ol] = v;
        }
    }
}

// ---------------- merge + LN + gate + out-proj + recurrent update + next-step KL ----------------
// grid(72, nf), block 256 = 32 lsub x 8 dg
__global__ void k_merge(const float* __restrict__ onw, const float* __restrict__ onb,
                        const float* __restrict__ ow,  const float* __restrict__ ob,
                        const float* __restrict__ Dsp,
                        int m, int mode, int t, int bofs, int doKL,
                        float* __restrict__ outp){
    __shared__ float syy[DI*32];
    __shared__ float sow[CI*DI];
    __shared__ float red0[8*32], red1[8*32];
    __shared__ float ssum[DI], sonw[DI], sonb[DI], sob[CI];
    int tid = threadIdx.x;
    int lsub = tid & 31, dg = tid >> 5;
    int fb = blockIdx.y, slice = fb + bofs;
    int l = blockIdx.x*32 + lsub;
    int tl = (l % 48)*48 + l/48;
    for (int j = tid; j < CI*DI; j += 256) sow[j] = __ldg(&ow[m*CI*DI + j]);
    if (tid < DI){
        float s = 0.f;
        #pragma unroll
        for (int k = 0; k < KK; k++) s += __ldg(&Dsp[(m*KK + k)*DI + tid]);
        ssum[tid] = s;
        sonw[tid] = __ldg(&onw[m*DI + tid]);
        sonb[tid] = __ldg(&onb[m*DI + tid]);
    }
    if (tid < CI) sob[tid] = __ldg(&ob[m*CI + tid]);
    __syncthreads();
    float ps = 0.f, pq = 0.f;
    for (int i = 0; i < 16; i++){
        int d = dg*16 + i;
        const float* y0 = g_y + ((size_t)(slice*KK + 0)*DI + d)*LL;
        const float* y1 = g_y + ((size_t)(slice*KK + 1)*DI + d)*LL;
        const float* y2 = g_y + ((size_t)(slice*KK + 2)*DI + d)*LL;
        const float* y3 = g_y + ((size_t)(slice*KK + 3)*DI + d)*LL;
        float v = y0[l] + y2[l] + y1[tl] + y3[tl]
                + ssum[d] * g_xc[((size_t)slice*DI + d)*LL + l];
        syy[d*32 + lsub] = v;
        ps += v; pq += v*v;
    }
    red0[dg*32 + lsub] = ps; red1[dg*32 + lsub] = pq;
    __syncthreads();
    if (dg == 0){
        float s0 = 0.f, s1 = 0.f;
        #pragma unroll
        for (int j = 0; j < 8; j++){ s0 += red0[j*32 + lsub]; s1 += red1[j*32 + lsub]; }
        float mu  = s0 * (1.f/DI);
        float var = s1 * (1.f/DI) - mu*mu;
        red0[lsub] = mu;
        red1[lsub] = rsqrtf(var + 1e-6f);
    }
    __syncthreads();
    float mu = red0[lsub], rs = red1[lsub];
    for (int i = 0; i < 16; i++){
        int d = dg*16 + i;
        float v  = syy[d*32 + lsub];
        float wn = (v - mu)*rs*sonw[d] + sonb[d];
        float z  = g_xz[((size_t)slice*2*DI + DI + d)*LL + l];
        float sz = z / (1.f + __expf(-z));
        syy[d*32 + lsub] = wn * sz;
    }
    __syncthreads();
    int cg = dg;
    float acc[8];
    #pragma unroll
    for (int i = 0; i < 8; i++) acc[i] = sob[cg*8 + i];
    for (int d = 0; d < DI; d++){
        float v = syy[d*32 + lsub];
        #pragma unroll
        for (int i = 0; i < 8; i++) acc[i] += sow[(cg*8 + i)*DI + d] * v;
    }
    if (mode == 1){
        #pragma unroll
        for (int i = 0; i < 8; i++)
            g_bias[(fb*CI + cg*8 + i)*LL + l] = acc[i];
        return;
    }
    float co[8], nv[8];
    #pragma unroll
    for (int i = 0; i < 8; i++){
        int cc = cg*8 + i;
        int idx = cc*LL + l;
        co[i] = g_cur[idx];
        g_prev[idx] = co[i];
        nv[i] = co[i] * __expf(acc[i]) + g_bias[(t*CI + cc)*LL + l];
        g_cur[idx] = nv[i];
        if (outp) outp[idx] = nv[i];
    }
    if (!doKL) return;
    __syncthreads();
    #pragma unroll
    for (int i = 0; i < 8; i++){
        int cc = cg*8 + i;
        syy[cc*32 + lsub]        = co[i];
        syy[2048 + cc*32 + lsub] = nv[i];
    }
    __syncthreads();
    if (tid < 32){
        float mp = -1e30f, mq = -1e30f;
        for (int cc = 0; cc < CI; cc++){
            mp = fmaxf(mp, syy[cc*32 + tid]);
            mq = fmaxf(mq, syy[2048 + cc*32 + tid]);
        }
        float ep = 0.f, eq = 0.f;
        for (int cc = 0; cc < CI; cc++){
            ep += __expf(syy[cc*32 + tid] - mp);
            eq += __expf(syy[2048 + cc*32 + tid] - mq);
        }
        red0[tid] = mp + __logf(ep);
        red1[tid] = mq + __logf(eq);
    }
    __syncthreads();
    float lsep = red0[lsub], lseq = red1[lsub];
    #pragma unroll
    for (int i = 0; i < 8; i++){
        int cc = cg*8 + i;
        float lp = syy[cc*32 + lsub] - lsep;
        float lq = syy[2048 + cc*32 + lsub] - lseq;
        g_kl[cc*LL + l] = __expf(lp)*(lp - lq);
    }
}

// ---------------- launch ----------------
extern "C" void kernel_launch(void* const* d_in, const int* in_sizes, int n_in,
                              void* d_out, int out_size){
    const float* img    = (const float*)d_in[0];
    const float* dz     = (const float*)d_in[1];
    const float* sigma  = (const float*)d_in[2];
    const float* in_w   = (const float*)d_in[3];
    const float* in_b   = (const float*)d_in[4];
    const float* conv_w = (const float*)d_in[5];
    const float* conv_b = (const float*)d_in[6];
    const float* xp_w   = (const float*)d_in[7];
    const float* dt_w   = (const float*)d_in[8];
    const float* dt_b   = (const float*)d_in[9];
    const float* A_logs = (const float*)d_in[10];
    const float* Ds     = (const float*)d_in[11];
    const float* onw    = (const float*)d_in[12];
    const float* onb    = (const float*)d_in[13];
    const float* ow     = (const float*)d_in[14];
    const float* ob     = (const float*)d_in[15];
    const float* niw    = (const float*)d_in[16];
    const float* nib    = (const float*)d_in[17];
    const float* ndw    = (const float*)d_in[18];
    const float* ndb    = (const float*)d_in[19];
    float* outp = (float*)d_out;

    // fork/join stream for the independent bias pipeline (fallback: same stream)
    cudaStream_t s2 = 0;
    cudaEvent_t evF = 0, evJ = 0;
    bool fork = (cudaStreamCreateWithFlags(&s2, cudaStreamNonBlocking) == cudaSuccess);
    if (fork) fork = (cudaEventCreateWithFlags(&evF, cudaEventDisableTiming) == cudaSuccess);
    if (fork) fork = (cudaEventCreateWithFlags(&evJ, cudaEventDisableTiming) == cudaSuccess);
    cudaStream_t sb = fork ? s2 : (cudaStream_t)0;

    k_init<<<dim3(72,5,1), 128>>>(dz, sigma, img, niw, nib, ndw, ndb);

    if (fork){
        cudaEventRecord(evF, 0);
        cudaStreamWaitEvent(s2, evF, 0);
    }

    // bias pipeline, all 4 frames batched (m = 1), slices 0..3
    k_inconv<<<dim3(256,TT,1), 256, 0, sb>>>(in_w, in_b, conv_w, conv_b, 1, 1, 0);
    k_xproj <<<dim3(48,KK,TT), 192, 0, sb>>>(xp_w, dt_w, dt_b, 1, 0);
    k_scan  <<<dim3(DI,KK,TT), 256, 0, sb>>>(A_logs, 1, 0);
    k_merge <<<dim3(72,TT,1),  256, 0, sb>>>(onw, onb, ow, ob, Ds, 1, 1, 0, 0, 0, nullptr);

    if (fork) cudaEventRecord(evJ, s2);

    // sequential recurrence (m = 0), slice 4
    for (int t = 0; t < TT; t++){
        k_inconv<<<dim3(256,1,1), 256>>>(in_w, in_b, conv_w, conv_b, 0, 0, SB);
        k_xproj <<<dim3(48,KK,1), 192>>>(xp_w, dt_w, dt_b, 0, SB);
        k_scan  <<<dim3(DI,KK,1), 256>>>(A_logs, 0, SB);
        if (fork && t == 0) cudaStreamWaitEvent((cudaStream_t)0, evJ, 0);
        k_merge <<<dim3(72,1,1),  256>>>(onw, onb, ow, ob, Ds, 0, 0, t, SB,
                                         (t < TT-1) ? 1 : 0,
                                         (t == TT-1) ? outp : nullptr);
    }
}

// round 7
// speedup vs baseline: 1.2943x; 1.2943x over previous
#include <cuda_runtime.h>

#define CI 64
#define DI 128
#define SS 16
#define RR 4
#define KK 4
#define HH 48
#define WW 48
#define LL 2304
#define TT 4
#define NB 5          // slices: 0..3 = bias frames, 4 = sequential pipeline
#define SB 4
#define NCH 16
#define LCH 144
#define LOG2E 1.4426950408889634f

// ---------------- scratch (static device globals; no allocations) ----------------
__device__ float g_prev[CI*LL];
__device__ float g_cur [CI*LL];
__device__ float g_kl  [CI*LL];
__device__ float g_xln [TT*CI*LL];
__device__ float g_bias[TT*CI*LL];
__device__ float g_xz  [NB*2*DI*LL];
__device__ float g_xc  [NB*DI*LL];
__device__ float g_xcT [NB*DI*LL];
__device__ float g_dt  [NB*KK*DI*LL];
__device__ float g_dtx [NB*KK*DI*LL];
__device__ float g_B4  [NB*KK*LL*SS];   // [(slice,k)][l/4][s][4]
__device__ float g_C4  [NB*KK*LL*SS];
__device__ float g_y   [NB*KK*DI*LL];

// ---------------- init: y=0: prev/cur/kl(t0); y=1..4: xln[t]; grid(72,5), 128 thr ----------------
__global__ void k_init(const float* __restrict__ dz, const float* __restrict__ sigma,
                       const float* __restrict__ img,
                       const float* __restrict__ niw, const float* __restrict__ nib,
                       const float* __restrict__ ndw, const float* __restrict__ ndb){
    __shared__ float sx[CI*33];
    __shared__ float scur[CI*33];
    __shared__ float smu[32], srs[32], slp[32], slq[32];
    int l0 = blockIdx.x*32, tid = threadIdx.x;
    if (blockIdx.y == 0){
        for (int j = tid; j < CI*32; j += 128){
            int c = j >> 5, li = j & 31;
            sx[c*33 + li] = dz[c*LL + l0 + li];
        }
        __syncthreads();
        if (tid < 32){
            float s0 = 0.f, s1 = 0.f;
            for (int c = 0; c < CI; c++){ float v = sx[c*33 + tid]; s0 += v; s1 += v*v; }
            float mu = s0*(1.f/CI);
            smu[tid] = mu;
            srs[tid] = rsqrtf(s1*(1.f/CI) - mu*mu + 1e-6f);
        }
        __syncthreads();
        for (int j = tid; j < CI*32; j += 128){
            int c = j >> 5, li = j & 31;
            float pv = (sx[c*33+li] - smu[li])*srs[li]*ndw[c] + ndb[c];
            float cv = pv * __expf(sigma[c*LL + l0 + li]);
            g_prev[c*LL + l0 + li] = pv;
            g_cur [c*LL + l0 + li] = cv;
            sx  [c*33 + li] = pv;
            scur[c*33 + li] = cv;
        }
        __syncthreads();
        if (tid < 32){
            float mp = -1e30f, mq = -1e30f;
            for (int c = 0; c < CI; c++){
                mp = fmaxf(mp, sx  [c*33 + tid]);
                mq = fmaxf(mq, scur[c*33 + tid]);
            }
            float ep = 0.f, eq = 0.f;
            for (int c = 0; c < CI; c++){
                ep += __expf(sx  [c*33 + tid] - mp);
                eq += __expf(scur[c*33 + tid] - mq);
            }
            slp[tid] = mp + __logf(ep);
            slq[tid] = mq + __logf(eq);
        }
        __syncthreads();
        for (int j = tid; j < CI*32; j += 128){
            int c = j >> 5, li = j & 31;
            float lp = sx  [c*33+li] - slp[li];
            float lq = scur[c*33+li] - slq[li];
            g_kl[c*LL + l0 + li] = __expf(lp)*(lp - lq);
        }
    } else {
        int t = blockIdx.y - 1;
        for (int j = tid; j < CI*32; j += 128){
            int c = j >> 5, li = j & 31;
            sx[c*33 + li] = img[(t*CI + c)*LL + l0 + li];
        }
        __syncthreads();
        if (tid < 32){
            float s0 = 0.f, s1 = 0.f;
            for (int c = 0; c < CI; c++){ float v = sx[c*33 + tid]; s0 += v; s1 += v*v; }
            float mu = s0*(1.f/CI);
            smu[tid] = mu;
            srs[tid] = rsqrtf(s1*(1.f/CI) - mu*mu + 1e-6f);
        }
        __syncthreads();
        for (int j = tid; j < CI*32; j += 128){
            int c = j >> 5, li = j & 31;
            g_xln[(t*CI + c)*LL + l0 + li] = (sx[c*33+li] - smu[li])*srs[li]*niw[c] + nib[c];
        }
    }
}

// ---------------- in-projection GEMM (R4-proven tiled form); grid(18,8,nf), 128 thr ----------------
__global__ void k_inproj(const float* __restrict__ in_w, const float* __restrict__ in_b,
                         int m, int srcsel, int bofs){
    __shared__ float sx[64*128];
    __shared__ float swT[64*33];
    const int lt = blockIdx.x, dtile = blockIdx.y, fb = blockIdx.z, tid = threadIdx.x;
    const int slice = fb + bofs;
    const float* src = (srcsel ? (g_xln + fb*CI*LL) : g_kl) + lt*128;
    for (int j = tid; j < 64*128; j += 128){
        int c = j >> 7;
        sx[j] = src[c*LL + tid];
    }
    for (int j = tid; j < 32*64; j += 128){
        int dp = j >> 6, c = j & 63;
        swT[c*33 + dp] = __ldg(&in_w[(m*256 + dtile*32 + dp)*64 + c]);
    }
    __syncthreads();
    int lq = tid & 31, dq = tid >> 5;
    float acc[8][4];
    #pragma unroll
    for (int i = 0; i < 8; i++){
        float bb = __ldg(&in_b[m*256 + dtile*32 + dq*8 + i]);
        #pragma unroll
        for (int j = 0; j < 4; j++) acc[i][j] = bb;
    }
    #pragma unroll 4
    for (int c = 0; c < 64; c++){
        float4 xv = *(const float4*)&sx[c*128 + lq*4];
        float xa[4] = {xv.x, xv.y, xv.z, xv.w};
        float wv[8];
        #pragma unroll
        for (int i = 0; i < 8; i++) wv[i] = swT[c*33 + dq*8 + i];
        #pragma unroll
        for (int i = 0; i < 8; i++)
            #pragma unroll
            for (int j = 0; j < 4; j++) acc[i][j] += wv[i]*xa[j];
    }
    #pragma unroll
    for (int i = 0; i < 8; i++){
        int d = dtile*32 + dq*8 + i;
        float* o = g_xz + ((size_t)slice*2*DI + d)*LL + lt*128 + lq*4;
        *(float4*)o = make_float4(acc[i][0], acc[i][1], acc[i][2], acc[i][3]);
    }
}

// ---------------- depthwise 3x3 conv + bias + silu (smem-staged); grid(DI,nf), 256 thr ----------------
__global__ void k_conv(const float* __restrict__ cw, const float* __restrict__ cb,
                       int m, int bofs){
    __shared__ float sin[LL];
    __shared__ float sc[48*49];
    int d = blockIdx.x, slice = blockIdx.y + bofs, tid = threadIdx.x;
    const float* in = g_xz + ((size_t)slice*2*DI + d)*LL;
    for (int i = tid; i < LL; i += 256) sin[i] = in[i];
    float w9[9];
    #pragma unroll
    for (int j = 0; j < 9; j++) w9[j] = __ldg(&cw[(m*DI + d)*9 + j]);
    float bias = __ldg(&cb[m*DI + d]);
    __syncthreads();
    for (int i = tid; i < LL; i += 256){
        int h = i/48, w = i%48;
        float acc = 0.f;
        #pragma unroll
        for (int ky = 0; ky < 3; ky++){
            int hy = h + ky - 1;
            if (hy < 0 || hy >= 48) continue;
            #pragma unroll
            for (int kx = 0; kx < 3; kx++){
                int wx = w + kx - 1;
                if (wx < 0 || wx >= 48) continue;
                acc += w9[ky*3+kx] * sin[hy*48 + wx];
            }
        }
        acc += bias;
        acc = acc / (1.f + __expf(-acc));
        sc[h*49 + w] = acc;
    }
    __syncthreads();
    float* oc = g_xc  + ((size_t)slice*DI + d)*LL;
    float* ot = g_xcT + ((size_t)slice*DI + d)*LL;
    for (int i = tid; i < LL; i += 256){
        int h = i/48, w = i%48;
        oc[i] = sc[h*49 + w];
        ot[i] = sc[w*49 + h];
    }
}

// ---------------- x-projection + dt + dtx + B/C (vec4 layout); grid(48,K,nf), 192 thr ----------------
__global__ void k_xproj(const float* __restrict__ xpw, const float* __restrict__ dtw,
                        const float* __restrict__ dtb, int m, int bofs){
    __shared__ float s1[DI*48];     // xs tile (preserved)
    __shared__ float s2[36*DI];     // xp_w, reused as xdbl[36*48] after GEMM
    __shared__ float sdw[DI*RR];
    __shared__ float sdb[DI];
    int lt = blockIdx.x, k = blockIdx.y, slice = blockIdx.z + bofs, tid = threadIdx.x;
    const float* wk = xpw + (m*KK + k)*36*DI;
    for (int j = tid; j < 36*DI; j += 192) s2[j] = __ldg(&wk[j]);
    const float* dwk = dtw + (m*KK + k)*DI*RR;
    for (int j = tid; j < DI*RR; j += 192) sdw[j] = __ldg(&dwk[j]);
    if (tid < DI) sdb[tid] = __ldg(&dtb[(m*KK + k)*DI + tid]);
    bool fwd = (k < 2);
    const float* src = ((k & 1) ? g_xcT : g_xc) + (size_t)slice*DI*LL;
    for (int j = tid; j < DI*48; j += 192){
        int d = j/48, ls = j%48;
        int gl = fwd ? (lt*48 + ls) : (LL-1 - (lt*48 + ls));
        s1[j] = src[d*LL + gl];
    }
    __syncthreads();
    int ls = tid % 48, rg = tid / 48;
    float acc[9];
    #pragma unroll
    for (int i = 0; i < 9; i++) acc[i] = 0.f;
    for (int c = 0; c < DI; c++){
        float xv = s1[c*48 + ls];
        #pragma unroll
        for (int i = 0; i < 9; i++) acc[i] += s2[(rg*9 + i)*DI + c] * xv;
    }
    __syncthreads();                 // all reads of s2 weights done
    float* xdbl = s2;                // reuse
    #pragma unroll
    for (int i = 0; i < 9; i++) xdbl[(rg*9 + i)*48 + ls] = acc[i];
    __syncthreads();
    float* dto  = g_dt  + ((size_t)(slice*KK + k)*DI)*LL + lt*48;
    float* dtxo = g_dtx + ((size_t)(slice*KK + k)*DI)*LL + lt*48;
    #pragma unroll 4
    for (int i = 0; i < 32; i++){
        int d = rg + 4*i;
        float v = sdb[d];
        #pragma unroll
        for (int r = 0; r < 4; r++) v += sdw[d*4 + r] * xdbl[r*48 + ls];
        v = fmaxf(v, 0.f) + log1pf(__expf(-fabsf(v)));   // stable softplus
        dto [d*LL + ls] = v;
        dtxo[d*LL + ls] = v * s1[d*48 + ls];
    }
    // B, C in [l/4][s][4] layout
    float* b4 = g_B4 + (size_t)(slice*KK + k)*LL*SS;
    float* c4 = g_C4 + (size_t)(slice*KK + k)*LL*SS;
    for (int j = tid; j < 48*SS; j += 192){
        int lls = j/SS, s = j%SS;
        int gl = lt*48 + lls;
        size_t o = (size_t)(gl >> 2)*64 + s*4 + (gl & 3);
        b4[o] = xdbl[(4 + s)*48 + lls];
        c4[o] = xdbl[(20 + s)*48 + lls];
    }
}

// ---------------- scan v3: vec4 loads, no staging, smem transpose-reduce; grid(DI,K,nf), 256 thr ----
__global__ __launch_bounds__(256) void k_scan(const float* __restrict__ A_logs, int m, int bofs){
    __shared__ float pA[256], pH[256], hI[256];
    __shared__ float tv[8][544];     // per warp: 2 groups x 16x17 tiles (group offset 272)
    int d = blockIdx.x, k = blockIdx.y, slice = blockIdx.z + bofs, tid = threadIdx.x;
    int s = tid & 15, c = tid >> 4;
    int w = tid >> 5, g = (tid >> 4) & 1;
    float* tile = &tv[w][g*272];
    float A2 = -__expf(__ldg(&A_logs[((m*KK + k)*DI + d)*SS + s])) * LOG2E;
    const float4* dt4 = (const float4*)(g_dt  + ((size_t)(slice*KK + k)*DI + d)*LL);
    const float4* dx4 = (const float4*)(g_dtx + ((size_t)(slice*KK + k)*DI + d)*LL);
    const float4* b4  = (const float4*)(g_B4 + (size_t)(slice*KK + k)*LL*SS);
    const float4* c4  = (const float4*)(g_C4 + (size_t)(slice*KK + k)*LL*SS);
    int q0 = c*36;                   // 36 float4-groups per chunk of 144
    // pass 1: chunk-local (aProd, hEnd)
    float ap = 1.f, h = 0.f;
    #pragma unroll 4
    for (int q = 0; q < 36; q++){
        float4 dt = __ldg(&dt4[q0 + q]);
        float4 dx = __ldg(&dx4[q0 + q]);
        float4 bb = __ldg(&b4[(size_t)(q0 + q)*16 + s]);
        float da;
        da = exp2f(A2*dt.x); ap *= da; h = da*h + dx.x*bb.x;
        da = exp2f(A2*dt.y); ap *= da; h = da*h + dx.y*bb.y;
        da = exp2f(A2*dt.z); ap *= da; h = da*h + dx.z*bb.z;
        da = exp2f(A2*dt.w); ap *= da; h = da*h + dx.w*bb.w;
    }
    pA[tid] = ap; pH[tid] = h;
    __syncthreads();
    // pass 2: serial scan over 16 chunk summaries (one thread per s)
    if (tid < 16){
        float hh = 0.f;
        #pragma unroll
        for (int cc = 0; cc < NCH; cc++){
            hI[cc*16 + tid] = hh;
            hh = pA[cc*16 + tid]*hh + pH[cc*16 + tid];
        }
    }
    __syncthreads();
    // pass 3: recompute with true h_init; transpose-reduce y via smem tile
    h = hI[tid];
    bool fwd = (k < 2);
    float* yrow = g_y + ((size_t)(slice*KK + k)*DI + d)*LL;
    int l0 = c*LCH;
    for (int blk = 0; blk < 9; blk++){
        #pragma unroll
        for (int qq = 0; qq < 4; qq++){
            int q = q0 + blk*4 + qq;
            float4 dt = __ldg(&dt4[q]);
            float4 dx = __ldg(&dx4[q]);
            float4 bb = __ldg(&b4[(size_t)q*16 + s]);
            float4 cc = __ldg(&c4[(size_t)q*16 + s]);
            float da;
            da = exp2f(A2*dt.x); h = da*h + dx.x*bb.x; tile[(qq*4+0)*17 + s] = h*cc.x;
            da = exp2f(A2*dt.y); h = da*h + dx.y*bb.y; tile[(qq*4+1)*17 + s] = h*cc.y;
            da = exp2f(A2*dt.z); h = da*h + dx.z*bb.z; tile[(qq*4+2)*17 + s] = h*cc.z;
            da = exp2f(A2*dt.w); h = da*h + dx.w*bb.w; tile[(qq*4+3)*17 + s] = h*cc.w;
        }
        __syncwarp();
        float sum = 0.f;
        #pragma unroll
        for (int s2 = 0; s2 < 16; s2++) sum += tile[s*17 + s2];
        int l = l0 + blk*16 + s;
        yrow[fwd ? l : (LL-1-l)] = sum;
        __syncwarp();
    }
}

// ---------------- merge + LN + gate + out-proj + recurrent update + next-step KL ----------------
// grid(72, nf), block 256 = 32 lsub x 8 dg
__global__ void k_merge(const float* __restrict__ onw, const float* __restrict__ onb,
                        const float* __restrict__ ow,  const float* __restrict__ ob,
                        const float* __restrict__ Dsp,
                        int m, int mode, int t, int bofs, int doKL,
                        float* __restrict__ outp){
    __shared__ float syy[DI*32];
    __shared__ float sow[CI*DI];
    __shared__ float red0[8*32], red1[8*32];
    __shared__ float ssum[DI], sonw[DI], sonb[DI], sob[CI];
    int tid = threadIdx.x;
    int lsub = tid & 31, dg = tid >> 5;
    int fb = blockIdx.y, slice = fb + bofs;
    int l = blockIdx.x*32 + lsub;
    int tl = (l % 48)*48 + l/48;
    for (int j = tid; j < CI*DI; j += 256) sow[j] = __ldg(&ow[m*CI*DI + j]);
    if (tid < DI){
        float s = 0.f;
        #pragma unroll
        for (int k = 0; k < KK; k++) s += __ldg(&Dsp[(m*KK + k)*DI + tid]);
        ssum[tid] = s;
        sonw[tid] = __ldg(&onw[m*DI + tid]);
        sonb[tid] = __ldg(&onb[m*DI + tid]);
    }
    if (tid < CI) sob[tid] = __ldg(&ob[m*CI + tid]);
    __syncthreads();
    float ps = 0.f, pq = 0.f;
    for (int i = 0; i < 16; i++){
        int d = dg*16 + i;
        const float* y0 = g_y + ((size_t)(slice*KK + 0)*DI + d)*LL;
        const float* y1 = g_y + ((size_t)(slice*KK + 1)*DI + d)*LL;
        const float* y2 = g_y + ((size_t)(slice*KK + 2)*DI + d)*LL;
        const float* y3 = g_y + ((size_t)(slice*KK + 3)*DI + d)*LL;
        float v = y0[l] + y2[l] + y1[tl] + y3[tl]
                + ssum[d] * g_xc[((size_t)slice*DI + d)*LL + l];
        syy[d*32 + lsub] = v;
        ps += v; pq += v*v;
    }
    red0[dg*32 + lsub] = ps; red1[dg*32 + lsub] = pq;
    __syncthreads();
    if (dg == 0){
        float s0 = 0.f, s1 = 0.f;
        #pragma unroll
        for (int j = 0; j < 8; j++){ s0 += red0[j*32 + lsub]; s1 += red1[j*32 + lsub]; }
        float mu  = s0 * (1.f/DI);
        float var = s1 * (1.f/DI) - mu*mu;
        red0[lsub] = mu;
        red1[lsub] = rsqrtf(var + 1e-6f);
    }
    __syncthreads();
    float mu = red0[lsub], rs = red1[lsub];
    for (int i = 0; i < 16; i++){
        int d = dg*16 + i;
        float v  = syy[d*32 + lsub];
        float wn = (v - mu)*rs*sonw[d] + sonb[d];
        float z  = g_xz[((size_t)slice*2*DI + DI + d)*LL + l];
        float sz = z / (1.f + __expf(-z));
        syy[d*32 + lsub] = wn * sz;
    }
    __syncthreads();
    int cg = dg;
    float acc[8];
    #pragma unroll
    for (int i = 0; i < 8; i++) acc[i] = sob[cg*8 + i];
    for (int d = 0; d < DI; d++){
        float v = syy[d*32 + lsub];
        #pragma unroll
        for (int i = 0; i < 8; i++) acc[i] += sow[(cg*8 + i)*DI + d] * v;
    }
    if (mode == 1){
        #pragma unroll
        for (int i = 0; i < 8; i++)
            g_bias[(fb*CI + cg*8 + i)*LL + l] = acc[i];
        return;
    }
    float co[8], nv[8];
    #pragma unroll
    for (int i = 0; i < 8; i++){
        int cc = cg*8 + i;
        int idx = cc*LL + l;
        co[i] = g_cur[idx];
        g_prev[idx] = co[i];
        nv[i] = co[i] * __expf(acc[i]) + g_bias[(t*CI + cc)*LL + l];
        g_cur[idx] = nv[i];
        if (outp) outp[idx] = nv[i];
    }
    if (!doKL) return;
    __syncthreads();
    #pragma unroll
    for (int i = 0; i < 8; i++){
        int cc = cg*8 + i;
        syy[cc*32 + lsub]        = co[i];
        syy[2048 + cc*32 + lsub] = nv[i];
    }
    __syncthreads();
    if (tid < 32){
        float mp = -1e30f, mq = -1e30f;
        for (int cc = 0; cc < CI; cc++){
            mp = fmaxf(mp, syy[cc*32 + tid]);
            mq = fmaxf(mq, syy[2048 + cc*32 + tid]);
        }
        float ep = 0.f, eq = 0.f;
        for (int cc = 0; cc < CI; cc++){
            ep += __expf(syy[cc*32 + tid] - mp);
            eq += __expf(syy[2048 + cc*32 + tid] - mq);
        }
        red0[tid] = mp + __logf(ep);
        red1[tid] = mq + __logf(eq);
    }
    __syncthreads();
    float lsep = red0[lsub], lseq = red1[lsub];
    #pragma unroll
    for (int i = 0; i < 8; i++){
        int cc = cg*8 + i;
        float lp = syy[cc*32 + lsub] - lsep;
        float lq = syy[2048 + cc*32 + lsub] - lseq;
        g_kl[cc*LL + l] = __expf(lp)*(lp - lq);
    }
}

// ---------------- launch ----------------
extern "C" void kernel_launch(void* const* d_in, const int* in_sizes, int n_in,
                              void* d_out, int out_size){
    const float* img    = (const float*)d_in[0];
    const float* dz     = (const float*)d_in[1];
    const float* sigma  = (const float*)d_in[2];
    const float* in_w   = (const float*)d_in[3];
    const float* in_b   = (const float*)d_in[4];
    const float* conv_w = (const float*)d_in[5];
    const float* conv_b = (const float*)d_in[6];
    const float* xp_w   = (const float*)d_in[7];
    const float* dt_w   = (const float*)d_in[8];
    const float* dt_b   = (const float*)d_in[9];
    const float* A_logs = (const float*)d_in[10];
    const float* Ds     = (const float*)d_in[11];
    const float* onw    = (const float*)d_in[12];
    const float* onb    = (const float*)d_in[13];
    const float* ow     = (const float*)d_in[14];
    const float* ob     = (const float*)d_in[15];
    const float* niw    = (const float*)d_in[16];
    const float* nib    = (const float*)d_in[17];
    const float* ndw    = (const float*)d_in[18];
    const float* ndb    = (const float*)d_in[19];
    float* outp = (float*)d_out;

    // fork/join stream for the independent bias pipeline (fallback: same stream)
    cudaStream_t s2 = 0;
    cudaEvent_t evF = 0, evJ = 0;
    bool fork = (cudaStreamCreateWithFlags(&s2, cudaStreamNonBlocking) == cudaSuccess);
    if (fork) fork = (cudaEventCreateWithFlags(&evF, cudaEventDisableTiming) == cudaSuccess);
    if (fork) fork = (cudaEventCreateWithFlags(&evJ, cudaEventDisableTiming) == cudaSuccess);
    cudaStream_t sb = fork ? s2 : (cudaStream_t)0;

    k_init<<<dim3(72,5,1), 128>>>(dz, sigma, img, niw, nib, ndw, ndb);

    if (fork){
        cudaEventRecord(evF, 0);
        cudaStreamWaitEvent(s2, evF, 0);
    }

    // bias pipeline, all 4 frames batched (m = 1), slices 0..3
    k_inproj<<<dim3(18,8,TT), 128, 0, sb>>>(in_w, in_b, 1, 1, 0);
    k_conv  <<<dim3(DI,TT,1), 256, 0, sb>>>(conv_w, conv_b, 1, 0);
    k_xproj <<<dim3(48,KK,TT), 192, 0, sb>>>(xp_w, dt_w, dt_b, 1, 0);
    k_scan  <<<dim3(DI,KK,TT), 256, 0, sb>>>(A_logs, 1, 0);
    k_merge <<<dim3(72,TT,1),  256, 0, sb>>>(onw, onb, ow, ob, Ds, 1, 1, 0, 0, 0, nullptr);

    if (fork) cudaEventRecord(evJ, s2);

    // sequential recurrence (m = 0), slice 4
    for (int t = 0; t < TT; t++){
        k_inproj<<<dim3(18,8,1), 128>>>(in_w, in_b, 0, 0, SB);
        k_conv  <<<dim3(DI,1,1), 256>>>(conv_w, conv_b, 0, SB);
        k_xproj <<<dim3(48,KK,1), 192>>>(xp_w, dt_w, dt_b, 0, SB);
        k_scan  <<<dim3(DI,KK,1), 256>>>(A_logs, 0, SB);
        if (fork && t == 0) cudaStreamWaitEvent((cudaStream_t)0, evJ, 0);
        k_merge <<<dim3(72,1,1),  256>>>(onw, onb, ow, ob, Ds, 0, 0, t, SB,
                                         (t < TT-1) ? 1 : 0,
                                         (t == TT-1) ? outp : nullptr);
    }
}

// round 8
// speedup vs baseline: 1.3467x; 1.0405x over previous
#include <cuda_runtime.h>

#define CI 64
#define DI 128
#define SS 16
#define RR 4
#define KK 4
#define HH 48
#define WW 48
#define LL 2304
#define TT 4
#define NB 5          // slices: 0..3 = bias frames, 4 = sequential pipeline
#define SB 4
#define NCH 16
#define LCH 144
#define LOG2E 1.4426950408889634f
#define LTX 96        // xproj l-tile
#define XP_SMEM ((DI*LTX + 36*DI + DI*RR + DI)*4)

// ---------------- scratch (static device globals; no allocations) ----------------
__device__ float g_prev[CI*LL];
__device__ float g_cur [CI*LL];
__device__ float g_kl  [CI*LL];
__device__ float g_xln [TT*CI*LL];
__device__ float g_bias[TT*CI*LL];
__device__ float g_xz  [NB*2*DI*LL];
__device__ float g_xc  [NB*DI*LL];
__device__ float g_xcT [NB*DI*LL];
__device__ float g_dt  [NB*KK*DI*LL];
__device__ float g_dtx [NB*KK*DI*LL];
__device__ float g_B4  [NB*KK*LL*SS];   // [(slice,k)][l/4][s][4]
__device__ float g_C4  [NB*KK*LL*SS];
__device__ float g_y   [NB*KK*DI*LL];

// ---------------- init: y=0: prev/cur/kl(t0); y=1..4: xln[t]; grid(72,5), 128 thr ----------------
__global__ void k_init(const float* __restrict__ dz, const float* __restrict__ sigma,
                       const float* __restrict__ img,
                       const float* __restrict__ niw, const float* __restrict__ nib,
                       const float* __restrict__ ndw, const float* __restrict__ ndb){
    __shared__ float sx[CI*33];
    __shared__ float scur[CI*33];
    __shared__ float smu[32], srs[32], slp[32], slq[32];
    int l0 = blockIdx.x*32, tid = threadIdx.x;
    if (blockIdx.y == 0){
        for (int j = tid; j < CI*32; j += 128){
            int c = j >> 5, li = j & 31;
            sx[c*33 + li] = dz[c*LL + l0 + li];
        }
        __syncthreads();
        if (tid < 32){
            float s0 = 0.f, s1 = 0.f;
            for (int c = 0; c < CI; c++){ float v = sx[c*33 + tid]; s0 += v; s1 += v*v; }
            float mu = s0*(1.f/CI);
            smu[tid] = mu;
            srs[tid] = rsqrtf(s1*(1.f/CI) - mu*mu + 1e-6f);
        }
        __syncthreads();
        for (int j = tid; j < CI*32; j += 128){
            int c = j >> 5, li = j & 31;
            float pv = (sx[c*33+li] - smu[li])*srs[li]*ndw[c] + ndb[c];
            float cv = pv * __expf(sigma[c*LL + l0 + li]);
            g_prev[c*LL + l0 + li] = pv;
            g_cur [c*LL + l0 + li] = cv;
            sx  [c*33 + li] = pv;
            scur[c*33 + li] = cv;
        }
        __syncthreads();
        if (tid < 32){
            float mp = -1e30f, mq = -1e30f;
            for (int c = 0; c < CI; c++){
                mp = fmaxf(mp, sx  [c*33 + tid]);
                mq = fmaxf(mq, scur[c*33 + tid]);
            }
            float ep = 0.f, eq = 0.f;
            for (int c = 0; c < CI; c++){
                ep += __expf(sx  [c*33 + tid] - mp);
                eq += __expf(scur[c*33 + tid] - mq);
            }
            slp[tid] = mp + __logf(ep);
            slq[tid] = mq + __logf(eq);
        }
        __syncthreads();
        for (int j = tid; j < CI*32; j += 128){
            int c = j >> 5, li = j & 31;
            float lp = sx  [c*33+li] - slp[li];
            float lq = scur[c*33+li] - slq[li];
            g_kl[c*LL + l0 + li] = __expf(lp)*(lp - lq);
        }
    } else {
        int t = blockIdx.y - 1;
        for (int j = tid; j < CI*32; j += 128){
            int c = j >> 5, li = j & 31;
            sx[c*33 + li] = img[(t*CI + c)*LL + l0 + li];
        }
        __syncthreads();
        if (tid < 32){
            float s0 = 0.f, s1 = 0.f;
            for (int c = 0; c < CI; c++){ float v = sx[c*33 + tid]; s0 += v; s1 += v*v; }
            float mu = s0*(1.f/CI);
            smu[tid] = mu;
            srs[tid] = rsqrtf(s1*(1.f/CI) - mu*mu + 1e-6f);
        }
        __syncthreads();
        for (int j = tid; j < CI*32; j += 128){
            int c = j >> 5, li = j & 31;
            g_xln[(t*CI + c)*LL + l0 + li] = (sx[c*33+li] - smu[li])*srs[li]*niw[c] + nib[c];
        }
    }
}

// ---------------- in-projection GEMM; grid(18,8,nf), 128 thr ----------------
__global__ void k_inproj(const float* __restrict__ in_w, const float* __restrict__ in_b,
                         int m, int srcsel, int bofs){
    __shared__ float sx[64*128];
    __shared__ float swT[64*33];
    const int lt = blockIdx.x, dtile = blockIdx.y, fb = blockIdx.z, tid = threadIdx.x;
    const int slice = fb + bofs;
    const float* src = (srcsel ? (g_xln + fb*CI*LL) : g_kl) + lt*128;
    for (int j = tid; j < 64*128; j += 128){
        int c = j >> 7;
        sx[j] = src[c*LL + tid];
    }
    for (int j = tid; j < 32*64; j += 128){
        int dp = j >> 6, c = j & 63;
        swT[c*33 + dp] = __ldg(&in_w[(m*256 + dtile*32 + dp)*64 + c]);
    }
    __syncthreads();
    int lq = tid & 31, dq = tid >> 5;
    float acc[8][4];
    #pragma unroll
    for (int i = 0; i < 8; i++){
        float bb = __ldg(&in_b[m*256 + dtile*32 + dq*8 + i]);
        #pragma unroll
        for (int j = 0; j < 4; j++) acc[i][j] = bb;
    }
    #pragma unroll 4
    for (int c = 0; c < 64; c++){
        float4 xv = *(const float4*)&sx[c*128 + lq*4];
        float xa[4] = {xv.x, xv.y, xv.z, xv.w};
        float wv[8];
        #pragma unroll
        for (int i = 0; i < 8; i++) wv[i] = swT[c*33 + dq*8 + i];
        #pragma unroll
        for (int i = 0; i < 8; i++)
            #pragma unroll
            for (int j = 0; j < 4; j++) acc[i][j] += wv[i]*xa[j];
    }
    #pragma unroll
    for (int i = 0; i < 8; i++){
        int d = dtile*32 + dq*8 + i;
        float* o = g_xz + ((size_t)slice*2*DI + d)*LL + lt*128 + lq*4;
        *(float4*)o = make_float4(acc[i][0], acc[i][1], acc[i][2], acc[i][3]);
    }
}

// ---------------- depthwise 3x3 conv + bias + silu (smem-staged); grid(DI,nf), 256 thr ----------------
__global__ void k_conv(const float* __restrict__ cw, const float* __restrict__ cb,
                       int m, int bofs){
    __shared__ float sin[LL];
    __shared__ float sc[48*49];
    int d = blockIdx.x, slice = blockIdx.y + bofs, tid = threadIdx.x;
    const float* in = g_xz + ((size_t)slice*2*DI + d)*LL;
    for (int i = tid; i < LL; i += 256) sin[i] = in[i];
    float w9[9];
    #pragma unroll
    for (int j = 0; j < 9; j++) w9[j] = __ldg(&cw[(m*DI + d)*9 + j]);
    float bias = __ldg(&cb[m*DI + d]);
    __syncthreads();
    for (int i = tid; i < LL; i += 256){
        int h = i/48, w = i%48;
        float acc = 0.f;
        #pragma unroll
        for (int ky = 0; ky < 3; ky++){
            int hy = h + ky - 1;
            if (hy < 0 || hy >= 48) continue;
            #pragma unroll
            for (int kx = 0; kx < 3; kx++){
                int wx = w + kx - 1;
                if (wx < 0 || wx >= 48) continue;
                acc += w9[ky*3+kx] * sin[hy*48 + wx];
            }
        }
        acc += bias;
        acc = acc / (1.f + __expf(-acc));
        sc[h*49 + w] = acc;
    }
    __syncthreads();
    float* oc = g_xc  + ((size_t)slice*DI + d)*LL;
    float* ot = g_xcT + ((size_t)slice*DI + d)*LL;
    for (int i = tid; i < LL; i += 256){
        int h = i/48, w = i%48;
        oc[i] = sc[h*49 + w];
        ot[i] = sc[w*49 + h];
    }
}

// ---------------- x-projection v2: register-tiled GEMM; grid(24,K,nf), 192 thr, dynamic smem ----------
__global__ __launch_bounds__(192) void k_xproj(const float* __restrict__ xpw,
                                               const float* __restrict__ dtw,
                                               const float* __restrict__ dtb,
                                               int m, int bofs){
    extern __shared__ float sm[];
    float* s1  = sm;                     // [c][LTX] x-tile, DI*LTX
    float* s2  = sm + DI*LTX;            // weights [36][DI], reused as xdbl[36][LTX]
    float* sdw = s2 + 36*DI;             // DI*RR
    float* sdb = sdw + DI*RR;            // DI
    int lt = blockIdx.x, k = blockIdx.y, slice = blockIdx.z + bofs, tid = threadIdx.x;
    const float* wk = xpw + (m*KK + k)*36*DI;
    for (int j = tid; j < 36*DI; j += 192) s2[j] = __ldg(&wk[j]);
    const float* dwk = dtw + (m*KK + k)*DI*RR;
    for (int j = tid; j < DI*RR; j += 192) sdw[j] = __ldg(&dwk[j]);
    if (tid < DI) sdb[tid] = __ldg(&dtb[(m*KK + k)*DI + tid]);
    bool fwd = (k < 2);
    const float* src = ((k & 1) ? g_xcT : g_xc) + (size_t)slice*DI*LL;
    for (int j = tid; j < DI*LTX; j += 192){
        int d = j/LTX, ls = j%LTX;
        int gl = fwd ? (lt*LTX + ls) : (LL-1 - (lt*LTX + ls));
        s1[j] = src[d*LL + gl];
    }
    __syncthreads();
    // GEMM: xdbl[36][96] = W[36][128] @ xs[128][96]; thread = (rg 0..3)x(lq 0..47), 9r x 2l
    int lq = tid % 48, rg = tid / 48;
    const float4* w4 = (const float4*)s2;    // [r][c/4]
    float acc[9][2];
    #pragma unroll
    for (int i = 0; i < 9; i++){ acc[i][0] = 0.f; acc[i][1] = 0.f; }
    #pragma unroll 2
    for (int c4 = 0; c4 < 32; c4++){
        float4 w[9];
        #pragma unroll
        for (int i = 0; i < 9; i++) w[i] = w4[(rg*9 + i)*32 + c4];
        float2 x0 = *(const float2*)&s1[(c4*4 + 0)*LTX + lq*2];
        float2 x1 = *(const float2*)&s1[(c4*4 + 1)*LTX + lq*2];
        float2 x2 = *(const float2*)&s1[(c4*4 + 2)*LTX + lq*2];
        float2 x3 = *(const float2*)&s1[(c4*4 + 3)*LTX + lq*2];
        #pragma unroll
        for (int i = 0; i < 9; i++){
            acc[i][0] += w[i].x*x0.x + w[i].y*x1.x + w[i].z*x2.x + w[i].w*x3.x;
            acc[i][1] += w[i].x*x0.y + w[i].y*x1.y + w[i].z*x2.y + w[i].w*x3.y;
        }
    }
    __syncthreads();                 // weight reads done; reuse s2 as xdbl[36][LTX]
    float* xdbl = s2;
    #pragma unroll
    for (int i = 0; i < 9; i++){
        xdbl[(rg*9 + i)*LTX + lq*2    ] = acc[i][0];
        xdbl[(rg*9 + i)*LTX + lq*2 + 1] = acc[i][1];
    }
    __syncthreads();
    // dt = softplus(dt_w @ xdbl[0:4] + dt_b); dtx = dt*x
    int ls2 = tid % LTX, rg2 = tid / LTX;   // 96 x 2
    float* dto  = g_dt  + ((size_t)(slice*KK + k)*DI)*LL + lt*LTX;
    float* dtxo = g_dtx + ((size_t)(slice*KK + k)*DI)*LL + lt*LTX;
    float xr0 = xdbl[0*LTX + ls2], xr1 = xdbl[1*LTX + ls2];
    float xr2 = xdbl[2*LTX + ls2], xr3 = xdbl[3*LTX + ls2];
    #pragma unroll 4
    for (int i = 0; i < 64; i++){
        int d = rg2 + 2*i;
        float v = sdb[d] + sdw[d*4+0]*xr0 + sdw[d*4+1]*xr1 + sdw[d*4+2]*xr2 + sdw[d*4+3]*xr3;
        v = fmaxf(v, 0.f) + log1pf(__expf(-fabsf(v)));   // stable softplus
        dto [d*LL + ls2] = v;
        dtxo[d*LL + ls2] = v * s1[d*LTX + ls2];
    }
    // B, C in [l/4][s][4] layout
    float* b4 = g_B4 + (size_t)(slice*KK + k)*LL*SS;
    float* c4o = g_C4 + (size_t)(slice*KK + k)*LL*SS;
    for (int j = tid; j < LTX*SS; j += 192){
        int lls = j/SS, s = j%SS;
        int gl = lt*LTX + lls;
        size_t o = (size_t)(gl >> 2)*64 + s*4 + (gl & 3);
        b4 [o] = xdbl[(4 + s)*LTX + lls];
        c4o[o] = xdbl[(20 + s)*LTX + lls];
    }
}

// ---------------- scan v3: vec4 loads, no staging, smem transpose-reduce; grid(DI,K,nf), 256 thr ----
__global__ __launch_bounds__(256) void k_scan(const float* __restrict__ A_logs, int m, int bofs){
    __shared__ float pA[256], pH[256], hI[256];
    __shared__ float tv[8][544];     // per warp: 2 groups x 16x17 tiles
    int d = blockIdx.x, k = blockIdx.y, slice = blockIdx.z + bofs, tid = threadIdx.x;
    int s = tid & 15, c = tid >> 4;
    int w = tid >> 5, g = (tid >> 4) & 1;
    float* tile = &tv[w][g*272];
    float A2 = -__expf(__ldg(&A_logs[((m*KK + k)*DI + d)*SS + s])) * LOG2E;
    const float4* dt4 = (const float4*)(g_dt  + ((size_t)(slice*KK + k)*DI + d)*LL);
    const float4* dx4 = (const float4*)(g_dtx + ((size_t)(slice*KK + k)*DI + d)*LL);
    const float4* b4  = (const float4*)(g_B4 + (size_t)(slice*KK + k)*LL*SS);
    const float4* c4  = (const float4*)(g_C4 + (size_t)(slice*KK + k)*LL*SS);
    int q0 = c*36;
    float ap = 1.f, h = 0.f;
    #pragma unroll 4
    for (int q = 0; q < 36; q++){
        float4 dt = __ldg(&dt4[q0 + q]);
        float4 dx = __ldg(&dx4[q0 + q]);
        float4 bb = __ldg(&b4[(size_t)(q0 + q)*16 + s]);
        float da;
        da = exp2f(A2*dt.x); ap *= da; h = da*h + dx.x*bb.x;
        da = exp2f(A2*dt.y); ap *= da; h = da*h + dx.y*bb.y;
        da = exp2f(A2*dt.z); ap *= da; h = da*h + dx.z*bb.z;
        da = exp2f(A2*dt.w); ap *= da; h = da*h + dx.w*bb.w;
    }
    pA[tid] = ap; pH[tid] = h;
    __syncthreads();
    if (tid < 16){
        float hh = 0.f;
        #pragma unroll
        for (int cc = 0; cc < NCH; cc++){
            hI[cc*16 + tid] = hh;
            hh = pA[cc*16 + tid]*hh + pH[cc*16 + tid];
        }
    }
    __syncthreads();
    h = hI[tid];
    bool fwd = (k < 2);
    float* yrow = g_y + ((size_t)(slice*KK + k)*DI + d)*LL;
    int l0 = c*LCH;
    for (int blk = 0; blk < 9; blk++){
        #pragma unroll
        for (int qq = 0; qq < 4; qq++){
            int q = q0 + blk*4 + qq;
            float4 dt = __ldg(&dt4[q]);
            float4 dx = __ldg(&dx4[q]);
            float4 bb = __ldg(&b4[(size_t)q*16 + s]);
            float4 cc = __ldg(&c4[(size_t)q*16 + s]);
            float da;
            da = exp2f(A2*dt.x); h = da*h + dx.x*bb.x; tile[(qq*4+0)*17 + s] = h*cc.x;
            da = exp2f(A2*dt.y); h = da*h + dx.y*bb.y; tile[(qq*4+1)*17 + s] = h*cc.y;
            da = exp2f(A2*dt.z); h = da*h + dx.z*bb.z; tile[(qq*4+2)*17 + s] = h*cc.z;
            da = exp2f(A2*dt.w); h = da*h + dx.w*bb.w; tile[(qq*4+3)*17 + s] = h*cc.w;
        }
        __syncwarp();
        float sum = 0.f;
        #pragma unroll
        for (int s2 = 0; s2 < 16; s2++) sum += tile[s*17 + s2];
        int l = l0 + blk*16 + s;
        yrow[fwd ? l : (LL-1-l)] = sum;
        __syncwarp();
    }
}

// ---------------- merge + LN + gate + out-proj + recurrent update + next-step KL ----------------
__global__ void k_merge(const float* __restrict__ onw, const float* __restrict__ onb,
                        const float* __restrict__ ow,  const float* __restrict__ ob,
                        const float* __restrict__ Dsp,
                        int m, int mode, int t, int bofs, int doKL,
                        float* __restrict__ outp){
    __shared__ float syy[DI*32];
    __shared__ float sow[CI*DI];
    __shared__ float red0[8*32], red1[8*32];
    __shared__ float ssum[DI], sonw[DI], sonb[DI], sob[CI];
    int tid = threadIdx.x;
    int lsub = tid & 31, dg = tid >> 5;
    int fb = blockIdx.y, slice = fb + bofs;
    int l = blockIdx.x*32 + lsub;
    int tl = (l % 48)*48 + l/48;
    for (int j = tid; j < CI*DI; j += 256) sow[j] = __ldg(&ow[m*CI*DI + j]);
    if (tid < DI){
        float s = 0.f;
        #pragma unroll
        for (int k = 0; k < KK; k++) s += __ldg(&Dsp[(m*KK + k)*DI + tid]);
        ssum[tid] = s;
        sonw[tid] = __ldg(&onw[m*DI + tid]);
        sonb[tid] = __ldg(&onb[m*DI + tid]);
    }
    if (tid < CI) sob[tid] = __ldg(&ob[m*CI + tid]);
    __syncthreads();
    float ps = 0.f, pq = 0.f;
    for (int i = 0; i < 16; i++){
        int d = dg*16 + i;
        const float* y0 = g_y + ((size_t)(slice*KK + 0)*DI + d)*LL;
        const float* y1 = g_y + ((size_t)(slice*KK + 1)*DI + d)*LL;
        const float* y2 = g_y + ((size_t)(slice*KK + 2)*DI + d)*LL;
        const float* y3 = g_y + ((size_t)(slice*KK + 3)*DI + d)*LL;
        float v = y0[l] + y2[l] + y1[tl] + y3[tl]
                + ssum[d] * g_xc[((size_t)slice*DI + d)*LL + l];
        syy[d*32 + lsub] = v;
        ps += v; pq += v*v;
    }
    red0[dg*32 + lsub] = ps; red1[dg*32 + lsub] = pq;
    __syncthreads();
    if (dg == 0){
        float s0 = 0.f, s1 = 0.f;
        #pragma unroll
        for (int j = 0; j < 8; j++){ s0 += red0[j*32 + lsub]; s1 += red1[j*32 + lsub]; }
        float mu  = s0 * (1.f/DI);
        float var = s1 * (1.f/DI) - mu*mu;
        red0[lsub] = mu;
        red1[lsub] = rsqrtf(var + 1e-6f);
    }
    __syncthreads();
    float mu = red0[lsub], rs = red1[lsub];
    for (int i = 0; i < 16; i++){
        int d = dg*16 + i;
        float v  = syy[d*32 + lsub];
        float wn = (v - mu)*rs*sonw[d] + sonb[d];
        float z  = g_xz[((size_t)slice*2*DI + DI + d)*LL + l];
        float sz = z / (1.f + __expf(-z));
        syy[d*32 + lsub] = wn * sz;
    }
    __syncthreads();
    int cg = dg;
    float acc[8];
    #pragma unroll
    for (int i = 0; i < 8; i++) acc[i] = sob[cg*8 + i];
    for (int d = 0; d < DI; d++){
        float v = syy[d*32 + lsub];
        #pragma unroll
        for (int i = 0; i < 8; i++) acc[i] += sow[(cg*8 + i)*DI + d] * v;
    }
    if (mode == 1){
        #pragma unroll
        for (int i = 0; i < 8; i++)
            g_bias[(fb*CI + cg*8 + i)*LL + l] = acc[i];
        return;
    }
    float co[8], nv[8];
    #pragma unroll
    for (int i = 0; i < 8; i++){
        int cc = cg*8 + i;
        int idx = cc*LL + l;
        co[i] = g_cur[idx];
        g_prev[idx] = co[i];
        nv[i] = co[i] * __expf(acc[i]) + g_bias[(t*CI + cc)*LL + l];
        g_cur[idx] = nv[i];
        if (outp) outp[idx] = nv[i];
    }
    if (!doKL) return;
    __syncthreads();
    #pragma unroll
    for (int i = 0; i < 8; i++){
        int cc = cg*8 + i;
        syy[cc*32 + lsub]        = co[i];
        syy[2048 + cc*32 + lsub] = nv[i];
    }
    __syncthreads();
    if (tid < 32){
        float mp = -1e30f, mq = -1e30f;
        for (int cc = 0; cc < CI; cc++){
            mp = fmaxf(mp, syy[cc*32 + tid]);
            mq = fmaxf(mq, syy[2048 + cc*32 + tid]);
        }
        float ep = 0.f, eq = 0.f;
        for (int cc = 0; cc < CI; cc++){
            ep += __expf(syy[cc*32 + tid] - mp);
            eq += __expf(syy[2048 + cc*32 + tid] - mq);
        }
        red0[tid] = mp + __logf(ep);
        red1[tid] = mq + __logf(eq);
    }
    __syncthreads();
    float lsep = red0[lsub], lseq = red1[lsub];
    #pragma unroll
    for (int i = 0; i < 8; i++){
        int cc = cg*8 + i;
        float lp = syy[cc*32 + lsub] - lsep;
        float lq = syy[2048 + cc*32 + lsub] - lseq;
        g_kl[cc*LL + l] = __expf(lp)*(lp - lq);
    }
}

// ---------------- launch ----------------
extern "C" void kernel_launch(void* const* d_in, const int* in_sizes, int n_in,
                              void* d_out, int out_size){
    const float* img    = (const float*)d_in[0];
    const float* dz     = (const float*)d_in[1];
    const float* sigma  = (const float*)d_in[2];
    const float* in_w   = (const float*)d_in[3];
    const float* in_b   = (const float*)d_in[4];
    const float* conv_w = (const float*)d_in[5];
    const float* conv_b = (const float*)d_in[6];
    const float* xp_w   = (const float*)d_in[7];
    const float* dt_w   = (const float*)d_in[8];
    const float* dt_b   = (const float*)d_in[9];
    const float* A_logs = (const float*)d_in[10];
    const float* Ds     = (const float*)d_in[11];
    const float* onw    = (const float*)d_in[12];
    const float* onb    = (const float*)d_in[13];
    const float* ow     = (const float*)d_in[14];
    const float* ob     = (const float*)d_in[15];
    const float* niw    = (const float*)d_in[16];
    const float* nib    = (const float*)d_in[17];
    const float* ndw    = (const float*)d_in[18];
    const float* ndb    = (const float*)d_in[19];
    float* outp = (float*)d_out;

    cudaFuncSetAttribute(k_xproj, cudaFuncAttributeMaxDynamicSharedMemorySize, XP_SMEM);

    // fork/join stream for the independent bias pipeline (fallback: same stream)
    cudaStream_t s2 = 0;
    cudaEvent_t evF = 0, evJ = 0;
    bool fork = (cudaStreamCreateWithFlags(&s2, cudaStreamNonBlocking) == cudaSuccess);
    if (fork) fork = (cudaEventCreateWithFlags(&evF, cudaEventDisableTiming) == cudaSuccess);
    if (fork) fork = (cudaEventCreateWithFlags(&evJ, cudaEventDisableTiming) == cudaSuccess);
    cudaStream_t sb = fork ? s2 : (cudaStream_t)0;

    k_init<<<dim3(72,5,1), 128>>>(dz, sigma, img, niw, nib, ndw, ndb);

    if (fork){
        cudaEventRecord(evF, 0);
        cudaStreamWaitEvent(s2, evF, 0);
    }

    // bias pipeline, all 4 frames batched (m = 1), slices 0..3
    k_inproj<<<dim3(18,8,TT), 128, 0, sb>>>(in_w, in_b, 1, 1, 0);
    k_conv  <<<dim3(DI,TT,1), 256, 0, sb>>>(conv_w, conv_b, 1, 0);
    k_xproj <<<dim3(24,KK,TT), 192, XP_SMEM, sb>>>(xp_w, dt_w, dt_b, 1, 0);
    k_scan  <<<dim3(DI,KK,TT), 256, 0, sb>>>(A_logs, 1, 0);
    k_merge <<<dim3(72,TT,1),  256, 0, sb>>>(onw, onb, ow, ob, Ds, 1, 1, 0, 0, 0, nullptr);

    if (fork) cudaEventRecord(evJ, s2);

    // sequential recurrence (m = 0), slice 4
    for (int t = 0; t < TT; t++){
        k_inproj<<<dim3(18,8,1), 128>>>(in_w, in_b, 0, 0, SB);
        k_conv  <<<dim3(DI,1,1), 256>>>(conv_w, conv_b, 0, SB);
        k_xproj <<<dim3(24,KK,1), 192, XP_SMEM>>>(xp_w, dt_w, dt_b, 0, SB);
        k_scan  <<<dim3(DI,KK,1), 256>>>(A_logs, 0, SB);
        if (fork && t == 0) cudaStreamWaitEvent((cudaStream_t)0, evJ, 0);
        k_merge <<<dim3(72,1,1),  256>>>(onw, onb, ow, ob, Ds, 0, 0, t, SB,
                                         (t < TT-1) ? 1 : 0,
                                         (t == TT-1) ? outp : nullptr);
    }
}

// round 9
// speedup vs baseline: 1.4382x; 1.0679x over previous
#include <cuda_runtime.h>

#define CI 64
#define DI 128
#define SS 16
#define RR 4
#define KK 4
#define HH 48
#define WW 48
#define LL 2304
#define TT 4
#define NB 5          // slices: 0..3 = bias frames, 4 = sequential pipeline
#define SB 4
#define NCH 16
#define LCH 144
#define LOG2E 1.4426950408889634f
#define LTX 96        // xproj l-tile
#define XP_SMEM ((DI*LTX + 36*DI + DI*RR + DI)*4)
#define MS_SMEM ((4096+8192+256+256+128+128+128+64+2048+64*260+256)*4)

// ---------------- scratch (static device globals; no allocations) ----------------
__device__ float g_prev[CI*LL];
__device__ float g_cur [CI*LL];
__device__ float g_kl  [CI*LL];
__device__ float g_xln [TT*CI*LL];
__device__ float g_bias[TT*CI*LL];
__device__ float g_xz  [NB*2*DI*LL];
__device__ float g_xc  [NB*DI*LL];
__device__ float g_xcT [NB*DI*LL];
__device__ float g_dt  [NB*KK*DI*LL];
__device__ float g_dtx [NB*KK*DI*LL];
__device__ float g_B4  [NB*KK*LL*SS];   // [(slice,k)][l/4][s][4]
__device__ float g_C4  [NB*KK*LL*SS];
__device__ float g_y   [NB*KK*DI*LL];

// ---------------- init: y=0: prev/cur/kl(t0); y=1..4: xln[t]; grid(72,5), 128 thr ----------------
__global__ void k_init(const float* __restrict__ dz, const float* __restrict__ sigma,
                       const float* __restrict__ img,
                       const float* __restrict__ niw, const float* __restrict__ nib,
                       const float* __restrict__ ndw, const float* __restrict__ ndb){
    __shared__ float sx[CI*33];
    __shared__ float scur[CI*33];
    __shared__ float smu[32], srs[32], slp[32], slq[32];
    int l0 = blockIdx.x*32, tid = threadIdx.x;
    if (blockIdx.y == 0){
        for (int j = tid; j < CI*32; j += 128){
            int c = j >> 5, li = j & 31;
            sx[c*33 + li] = dz[c*LL + l0 + li];
        }
        __syncthreads();
        if (tid < 32){
            float s0 = 0.f, s1 = 0.f;
            for (int c = 0; c < CI; c++){ float v = sx[c*33 + tid]; s0 += v; s1 += v*v; }
            float mu = s0*(1.f/CI);
            smu[tid] = mu;
            srs[tid] = rsqrtf(s1*(1.f/CI) - mu*mu + 1e-6f);
        }
        __syncthreads();
        for (int j = tid; j < CI*32; j += 128){
            int c = j >> 5, li = j & 31;
            float pv = (sx[c*33+li] - smu[li])*srs[li]*ndw[c] + ndb[c];
            float cv = pv * __expf(sigma[c*LL + l0 + li]);
            g_prev[c*LL + l0 + li] = pv;
            g_cur [c*LL + l0 + li] = cv;
            sx  [c*33 + li] = pv;
            scur[c*33 + li] = cv;
        }
        __syncthreads();
        if (tid < 32){
            float mp = -1e30f, mq = -1e30f;
            for (int c = 0; c < CI; c++){
                mp = fmaxf(mp, sx  [c*33 + tid]);
                mq = fmaxf(mq, scur[c*33 + tid]);
            }
            float ep = 0.f, eq = 0.f;
            for (int c = 0; c < CI; c++){
                ep += __expf(sx  [c*33 + tid] - mp);
                eq += __expf(scur[c*33 + tid] - mq);
            }
            slp[tid] = mp + __logf(ep);
            slq[tid] = mq + __logf(eq);
        }
        __syncthreads();
        for (int j = tid; j < CI*32; j += 128){
            int c = j >> 5, li = j & 31;
            float lp = sx  [c*33+li] - slp[li];
            float lq = scur[c*33+li] - slq[li];
            g_kl[c*LL + l0 + li] = __expf(lp)*(lp - lq);
        }
    } else {
        int t = blockIdx.y - 1;
        for (int j = tid; j < CI*32; j += 128){
            int c = j >> 5, li = j & 31;
            sx[c*33 + li] = img[(t*CI + c)*LL + l0 + li];
        }
        __syncthreads();
        if (tid < 32){
            float s0 = 0.f, s1 = 0.f;
            for (int c = 0; c < CI; c++){ float v = sx[c*33 + tid]; s0 += v; s1 += v*v; }
            float mu = s0*(1.f/CI);
            smu[tid] = mu;
            srs[tid] = rsqrtf(s1*(1.f/CI) - mu*mu + 1e-6f);
        }
        __syncthreads();
        for (int j = tid; j < CI*32; j += 128){
            int c = j >> 5, li = j & 31;
            g_xln[(t*CI + c)*LL + l0 + li] = (sx[c*33+li] - smu[li])*srs[li]*niw[c] + nib[c];
        }
    }
}

// ---------------- in-projection GEMM (combined first wave only); grid(18,8,5), 128 thr ----------------
__global__ void k_inproj(const float* __restrict__ in_w, const float* __restrict__ in_b){
    __shared__ float sx[64*128];
    __shared__ float swT[64*33];
    const int lt = blockIdx.x, dtile = blockIdx.y, fb = blockIdx.z, tid = threadIdx.x;
    const int m = (fb < 4) ? 1 : 0;
    const int slice = fb;
    const float* src = ((fb < 4) ? (g_xln + fb*CI*LL) : g_kl) + lt*128;
    for (int j = tid; j < 64*128; j += 128){
        int c = j >> 7;
        sx[j] = src[c*LL + tid];
    }
    for (int j = tid; j < 32*64; j += 128){
        int dp = j >> 6, c = j & 63;
        swT[c*33 + dp] = __ldg(&in_w[(m*256 + dtile*32 + dp)*64 + c]);
    }
    __syncthreads();
    int lq = tid & 31, dq = tid >> 5;
    float acc[8][4];
    #pragma unroll
    for (int i = 0; i < 8; i++){
        float bb = __ldg(&in_b[m*256 + dtile*32 + dq*8 + i]);
        #pragma unroll
        for (int j = 0; j < 4; j++) acc[i][j] = bb;
    }
    #pragma unroll 4
    for (int c = 0; c < 64; c++){
        float4 xv = *(const float4*)&sx[c*128 + lq*4];
        float xa[4] = {xv.x, xv.y, xv.z, xv.w};
        float wv[8];
        #pragma unroll
        for (int i = 0; i < 8; i++) wv[i] = swT[c*33 + dq*8 + i];
        #pragma unroll
        for (int i = 0; i < 8; i++)
            #pragma unroll
            for (int j = 0; j < 4; j++) acc[i][j] += wv[i]*xa[j];
    }
    #pragma unroll
    for (int i = 0; i < 8; i++){
        int d = dtile*32 + dq*8 + i;
        float* o = g_xz + ((size_t)slice*2*DI + d)*LL + lt*128 + lq*4;
        *(float4*)o = make_float4(acc[i][0], acc[i][1], acc[i][2], acc[i][3]);
    }
}

// ---------------- depthwise 3x3 conv + bias + silu; grid(DI,ny), 256 thr ----------------
__global__ void k_conv(const float* __restrict__ cw, const float* __restrict__ cb, int bofs){
    __shared__ float sin[LL];
    __shared__ float sc[48*49];
    int d = blockIdx.x, slice = blockIdx.y + bofs, tid = threadIdx.x;
    int m = (slice < SB) ? 1 : 0;
    const float* in = g_xz + ((size_t)slice*2*DI + d)*LL;
    for (int i = tid; i < LL; i += 256) sin[i] = in[i];
    float w9[9];
    #pragma unroll
    for (int j = 0; j < 9; j++) w9[j] = __ldg(&cw[(m*DI + d)*9 + j]);
    float bias = __ldg(&cb[m*DI + d]);
    __syncthreads();
    for (int i = tid; i < LL; i += 256){
        int h = i/48, w = i%48;
        float acc = 0.f;
        #pragma unroll
        for (int ky = 0; ky < 3; ky++){
            int hy = h + ky - 1;
            if (hy < 0 || hy >= 48) continue;
            #pragma unroll
            for (int kx = 0; kx < 3; kx++){
                int wx = w + kx - 1;
                if (wx < 0 || wx >= 48) continue;
                acc += w9[ky*3+kx] * sin[hy*48 + wx];
            }
        }
        acc += bias;
        acc = acc / (1.f + __expf(-acc));
        sc[h*49 + w] = acc;
    }
    __syncthreads();
    float* oc = g_xc  + ((size_t)slice*DI + d)*LL;
    float* ot = g_xcT + ((size_t)slice*DI + d)*LL;
    for (int i = tid; i < LL; i += 256){
        int h = i/48, w = i%48;
        oc[i] = sc[h*49 + w];
        ot[i] = sc[w*49 + h];
    }
}

// ---------------- x-projection: register-tiled GEMM; grid(24,K,nz), 192 thr, dynamic smem ----------
__global__ __launch_bounds__(192) void k_xproj(const float* __restrict__ xpw,
                                               const float* __restrict__ dtw,
                                               const float* __restrict__ dtb,
                                               int bofs){
    extern __shared__ float sm[];
    float* s1  = sm;                     // [c][LTX] x-tile
    float* s2  = sm + DI*LTX;            // weights [36][DI] -> xdbl[36][LTX]
    float* sdw = s2 + 36*DI;
    float* sdb = sdw + DI*RR;
    int lt = blockIdx.x, k = blockIdx.y, slice = blockIdx.z + bofs, tid = threadIdx.x;
    int m = (slice < SB) ? 1 : 0;
    const float* wk = xpw + (m*KK + k)*36*DI;
    for (int j = tid; j < 36*DI; j += 192) s2[j] = __ldg(&wk[j]);
    const float* dwk = dtw + (m*KK + k)*DI*RR;
    for (int j = tid; j < DI*RR; j += 192) sdw[j] = __ldg(&dwk[j]);
    if (tid < DI) sdb[tid] = __ldg(&dtb[(m*KK + k)*DI + tid]);
    bool fwd = (k < 2);
    const float* src = ((k & 1) ? g_xcT : g_xc) + (size_t)slice*DI*LL;
    for (int j = tid; j < DI*LTX; j += 192){
        int d = j/LTX, ls = j%LTX;
        int gl = fwd ? (lt*LTX + ls) : (LL-1 - (lt*LTX + ls));
        s1[j] = src[d*LL + gl];
    }
    __syncthreads();
    int lq = tid % 48, rg = tid / 48;
    const float4* w4 = (const float4*)s2;
    float acc[9][2];
    #pragma unroll
    for (int i = 0; i < 9; i++){ acc[i][0] = 0.f; acc[i][1] = 0.f; }
    #pragma unroll 2
    for (int c4 = 0; c4 < 32; c4++){
        float4 w[9];
        #pragma unroll
        for (int i = 0; i < 9; i++) w[i] = w4[(rg*9 + i)*32 + c4];
        float2 x0 = *(const float2*)&s1[(c4*4 + 0)*LTX + lq*2];
        float2 x1 = *(const float2*)&s1[(c4*4 + 1)*LTX + lq*2];
        float2 x2 = *(const float2*)&s1[(c4*4 + 2)*LTX + lq*2];
        float2 x3 = *(const float2*)&s1[(c4*4 + 3)*LTX + lq*2];
        #pragma unroll
        for (int i = 0; i < 9; i++){
            acc[i][0] += w[i].x*x0.x + w[i].y*x1.x + w[i].z*x2.x + w[i].w*x3.x;
            acc[i][1] += w[i].x*x0.y + w[i].y*x1.y + w[i].z*x2.y + w[i].w*x3.y;
        }
    }
    __syncthreads();
    float* xdbl = s2;
    #pragma unroll
    for (int i = 0; i < 9; i++){
        xdbl[(rg*9 + i)*LTX + lq*2    ] = acc[i][0];
        xdbl[(rg*9 + i)*LTX + lq*2 + 1] = acc[i][1];
    }
    __syncthreads();
    int ls2 = tid % LTX, rg2 = tid / LTX;
    float* dto  = g_dt  + ((size_t)(slice*KK + k)*DI)*LL + lt*LTX;
    float* dtxo = g_dtx + ((size_t)(slice*KK + k)*DI)*LL + lt*LTX;
    float xr0 = xdbl[0*LTX + ls2], xr1 = xdbl[1*LTX + ls2];
    float xr2 = xdbl[2*LTX + ls2], xr3 = xdbl[3*LTX + ls2];
    #pragma unroll 4
    for (int i = 0; i < 64; i++){
        int d = rg2 + 2*i;
        float v = sdb[d] + sdw[d*4+0]*xr0 + sdw[d*4+1]*xr1 + sdw[d*4+2]*xr2 + sdw[d*4+3]*xr3;
        v = fmaxf(v, 0.f) + log1pf(__expf(-fabsf(v)));
        dto [d*LL + ls2] = v;
        dtxo[d*LL + ls2] = v * s1[d*LTX + ls2];
    }
    float* b4 = g_B4 + (size_t)(slice*KK + k)*LL*SS;
    float* c4o = g_C4 + (size_t)(slice*KK + k)*LL*SS;
    for (int j = tid; j < LTX*SS; j += 192){
        int lls = j/SS, s = j%SS;
        int gl = lt*LTX + lls;
        size_t o = (size_t)(gl >> 2)*64 + s*4 + (gl & 3);
        b4 [o] = xdbl[(4 + s)*LTX + lls];
        c4o[o] = xdbl[(20 + s)*LTX + lls];
    }
}

// ---------------- scan: vec4 loads, smem transpose-reduce; grid(DI,K,nz), 256 thr ----------------
__global__ __launch_bounds__(256) void k_scan(const float* __restrict__ A_logs, int bofs){
    __shared__ float pA[256], pH[256], hI[256];
    __shared__ float tv[8][544];
    int d = blockIdx.x, k = blockIdx.y, slice = blockIdx.z + bofs, tid = threadIdx.x;
    int m = (slice < SB) ? 1 : 0;
    int s = tid & 15, c = tid >> 4;
    int w = tid >> 5, g = (tid >> 4) & 1;
    float* tile = &tv[w][g*272];
    float A2 = -__expf(__ldg(&A_logs[((m*KK + k)*DI + d)*SS + s])) * LOG2E;
    const float4* dt4 = (const float4*)(g_dt  + ((size_t)(slice*KK + k)*DI + d)*LL);
    const float4* dx4 = (const float4*)(g_dtx + ((size_t)(slice*KK + k)*DI + d)*LL);
    const float4* b4  = (const float4*)(g_B4 + (size_t)(slice*KK + k)*LL*SS);
    const float4* c4  = (const float4*)(g_C4 + (size_t)(slice*KK + k)*LL*SS);
    int q0 = c*36;
    float ap = 1.f, h = 0.f;
    #pragma unroll 4
    for (int q = 0; q < 36; q++){
        float4 dt = __ldg(&dt4[q0 + q]);
        float4 dx = __ldg(&dx4[q0 + q]);
        float4 bb = __ldg(&b4[(size_t)(q0 + q)*16 + s]);
        float da;
        da = exp2f(A2*dt.x); ap *= da; h = da*h + dx.x*bb.x;
        da = exp2f(A2*dt.y); ap *= da; h = da*h + dx.y*bb.y;
        da = exp2f(A2*dt.z); ap *= da; h = da*h + dx.z*bb.z;
        da = exp2f(A2*dt.w); ap *= da; h = da*h + dx.w*bb.w;
    }
    pA[tid] = ap; pH[tid] = h;
    __syncthreads();
    if (tid < 16){
        float hh = 0.f;
        #pragma unroll
        for (int cc = 0; cc < NCH; cc++){
            hI[cc*16 + tid] = hh;
            hh = pA[cc*16 + tid]*hh + pH[cc*16 + tid];
        }
    }
    __syncthreads();
    h = hI[tid];
    bool fwd = (k < 2);
    float* yrow = g_y + ((size_t)(slice*KK + k)*DI + d)*LL;
    int l0 = c*LCH;
    for (int blk = 0; blk < 9; blk++){
        #pragma unroll
        for (int qq = 0; qq < 4; qq++){
            int q = q0 + blk*4 + qq;
            float4 dt = __ldg(&dt4[q]);
            float4 dx = __ldg(&dx4[q]);
            float4 bb = __ldg(&b4[(size_t)q*16 + s]);
            float4 cc = __ldg(&c4[(size_t)q*16 + s]);
            float da;
            da = exp2f(A2*dt.x); h = da*h + dx.x*bb.x; tile[(qq*4+0)*17 + s] = h*cc.x;
            da = exp2f(A2*dt.y); h = da*h + dx.y*bb.y; tile[(qq*4+1)*17 + s] = h*cc.y;
            da = exp2f(A2*dt.z); h = da*h + dx.z*bb.z; tile[(qq*4+2)*17 + s] = h*cc.z;
            da = exp2f(A2*dt.w); h = da*h + dx.w*bb.w; tile[(qq*4+3)*17 + s] = h*cc.w;
        }
        __syncwarp();
        float sum = 0.f;
        #pragma unroll
        for (int s2 = 0; s2 < 16; s2++) sum += tile[s*17 + s2];
        int l = l0 + blk*16 + s;
        yrow[fwd ? l : (LL-1-l)] = sum;
        __syncwarp();
    }
}

// ---------------- bias merge (frames 0..3, m=1): grid(72,4), 256 thr ----------------
__global__ void k_mergeBias(const float* __restrict__ onw, const float* __restrict__ onb,
                            const float* __restrict__ ow,  const float* __restrict__ ob,
                            const float* __restrict__ Dsp){
    __shared__ float syy[DI*32];
    __shared__ float sow[CI*DI];
    __shared__ float red0[8*32], red1[8*32];
    __shared__ float ssum[DI], sonw[DI], sonb[DI], sob[CI];
    int tid = threadIdx.x;
    int lsub = tid & 31, dg = tid >> 5;
    int fb = blockIdx.y, slice = fb;
    int l = blockIdx.x*32 + lsub;
    int tl = (l % 48)*48 + l/48;
    for (int j = tid; j < CI*DI; j += 256) sow[j] = __ldg(&ow[CI*DI + j]);
    if (tid < DI){
        float s = 0.f;
        #pragma unroll
        for (int k = 0; k < KK; k++) s += __ldg(&Dsp[(KK + k)*DI + tid]);
        ssum[tid] = s;
        sonw[tid] = __ldg(&onw[DI + tid]);
        sonb[tid] = __ldg(&onb[DI + tid]);
    }
    if (tid < CI) sob[tid] = __ldg(&ob[CI + tid]);
    __syncthreads();
    float ps = 0.f, pq = 0.f;
    for (int i = 0; i < 16; i++){
        int d = dg*16 + i;
        const float* y0 = g_y + ((size_t)(slice*KK + 0)*DI + d)*LL;
        const float* y1 = g_y + ((size_t)(slice*KK + 1)*DI + d)*LL;
        const float* y2 = g_y + ((size_t)(slice*KK + 2)*DI + d)*LL;
        const float* y3 = g_y + ((size_t)(slice*KK + 3)*DI + d)*LL;
        float v = y0[l] + y2[l] + y1[tl] + y3[tl]
                + ssum[d] * g_xc[((size_t)slice*DI + d)*LL + l];
        syy[d*32 + lsub] = v;
        ps += v; pq += v*v;
    }
    red0[dg*32 + lsub] = ps; red1[dg*32 + lsub] = pq;
    __syncthreads();
    if (dg == 0){
        float s0 = 0.f, s1 = 0.f;
        #pragma unroll
        for (int j = 0; j < 8; j++){ s0 += red0[j*32 + lsub]; s1 += red1[j*32 + lsub]; }
        float mu  = s0 * (1.f/DI);
        float var = s1 * (1.f/DI) - mu*mu;
        red0[lsub] = mu;
        red1[lsub] = rsqrtf(var + 1e-6f);
    }
    __syncthreads();
    float mu = red0[lsub], rs = red1[lsub];
    for (int i = 0; i < 16; i++){
        int d = dg*16 + i;
        float v  = syy[d*32 + lsub];
        float wn = (v - mu)*rs*sonw[d] + sonb[d];
        float z  = g_xz[((size_t)slice*2*DI + DI + d)*LL + l];
        float sz = z / (1.f + __expf(-z));
        syy[d*32 + lsub] = wn * sz;
    }
    __syncthreads();
    float acc[8];
    #pragma unroll
    for (int i = 0; i < 8; i++) acc[i] = sob[dg*8 + i];
    for (int d = 0; d < DI; d++){
        float v = syy[d*32 + lsub];
        #pragma unroll
        for (int i = 0; i < 8; i++) acc[i] += sow[(dg*8 + i)*DI + d] * v;
    }
    #pragma unroll
    for (int i = 0; i < 8; i++)
        g_bias[(fb*CI + dg*8 + i)*LL + l] = acc[i];
}

// ---------------- sequential merge: update + KL + fused in-projection for t+1 ----------------
// grid(72), 256 thr, dynamic smem
__global__ __launch_bounds__(256) void k_mergeSeq(
        const float* __restrict__ onw, const float* __restrict__ onb,
        const float* __restrict__ ow,  const float* __restrict__ ob,
        const float* __restrict__ Dsp,
        const float* __restrict__ in_w, const float* __restrict__ in_b,
        int t, int last, float* __restrict__ outp){
    extern __shared__ float sm[];
    float* syy  = sm;              // 4096
    float* sow  = syy + 4096;      // 8192
    float* red0 = sow + 8192;      // 256
    float* red1 = red0 + 256;      // 256
    float* ssum = red1 + 256;      // 128
    float* sonw = ssum + 128;      // 128
    float* sonb = sonw + 128;      // 128
    float* sob  = sonb + 128;      // 64
    float* skl  = sob + 64;        // 2048
    float* swT  = skl + 2048;      // 64*260
    float* sbin = swT + 64*260;    // 256
    const int slice = SB;
    int tid = threadIdx.x;
    int lsub = tid & 31, dg = tid >> 5;
    int l = blockIdx.x*32 + lsub;
    int tl = (l % 48)*48 + l/48;
    // stage weights (m = 0)
    for (int j = tid; j < CI*DI; j += 256) sow[j] = __ldg(&ow[j]);
    if (tid < DI){
        float s = 0.f;
        #pragma unroll
        for (int k = 0; k < KK; k++) s += __ldg(&Dsp[k*DI + tid]);
        ssum[tid] = s;
        sonw[tid] = __ldg(&onw[tid]);
        sonb[tid] = __ldg(&onb[tid]);
    }
    if (tid < CI) sob[tid] = __ldg(&ob[tid]);
    if (!last){
        for (int j = tid; j < 256*64; j += 256){
            int row = j >> 6, c = j & 63;
            swT[c*260 + row] = __ldg(&in_w[row*64 + c]);
        }
        sbin[tid] = __ldg(&in_b[tid]);
    }
    __syncthreads();
    // direction merge + LN + gate + out-proj
    float ps = 0.f, pq = 0.f;
    for (int i = 0; i < 16; i++){
        int d = dg*16 + i;
        const float* y0 = g_y + ((size_t)(slice*KK + 0)*DI + d)*LL;
        const float* y1 = g_y + ((size_t)(slice*KK + 1)*DI + d)*LL;
        const float* y2 = g_y + ((size_t)(slice*KK + 2)*DI + d)*LL;
        const float* y3 = g_y + ((size_t)(slice*KK + 3)*DI + d)*LL;
        float v = y0[l] + y2[l] + y1[tl] + y3[tl]
                + ssum[d] * g_xc[((size_t)slice*DI + d)*LL + l];
        syy[d*32 + lsub] = v;
        ps += v; pq += v*v;
    }
    red0[dg*32 + lsub] = ps; red1[dg*32 + lsub] = pq;
    __syncthreads();
    if (dg == 0){
        float s0 = 0.f, s1 = 0.f;
        #pragma unroll
        for (int j = 0; j < 8; j++){ s0 += red0[j*32 + lsub]; s1 += red1[j*32 + lsub]; }
        float mu  = s0 * (1.f/DI);
        float var = s1 * (1.f/DI) - mu*mu;
        red0[lsub] = mu;
        red1[lsub] = rsqrtf(var + 1e-6f);
    }
    __syncthreads();
    float mu = red0[lsub], rs = red1[lsub];
    for (int i = 0; i < 16; i++){
        int d = dg*16 + i;
        float v  = syy[d*32 + lsub];
        float wn = (v - mu)*rs*sonw[d] + sonb[d];
        float z  = g_xz[((size_t)slice*2*DI + DI + d)*LL + l];
        float sz = z / (1.f + __expf(-z));
        syy[d*32 + lsub] = wn * sz;
    }
    __syncthreads();
    float acc[8];
    #pragma unroll
    for (int i = 0; i < 8; i++) acc[i] = sob[dg*8 + i];
    for (int d = 0; d < DI; d++){
        float v = syy[d*32 + lsub];
        #pragma unroll
        for (int i = 0; i < 8; i++) acc[i] += sow[(dg*8 + i)*DI + d] * v;
    }
    // recurrent update
    float co[8], nv[8];
    #pragma unroll
    for (int i = 0; i < 8; i++){
        int cc = dg*8 + i;
        int idx = cc*LL + l;
        co[i] = g_cur[idx];
        g_prev[idx] = co[i];
        nv[i] = co[i] * __expf(acc[i]) + g_bias[(t*CI + cc)*LL + l];
        g_cur[idx] = nv[i];
    }
    if (last){
        #pragma unroll
        for (int i = 0; i < 8; i++) outp[(dg*8 + i)*LL + l] = nv[i];
        return;
    }
    // KL into skl
    __syncthreads();
    #pragma unroll
    for (int i = 0; i < 8; i++){
        int cc = dg*8 + i;
        syy[cc*32 + lsub]        = co[i];
        syy[2048 + cc*32 + lsub] = nv[i];
    }
    __syncthreads();
    if (tid < 32){
        float mp = -1e30f, mq = -1e30f;
        for (int cc = 0; cc < CI; cc++){
            mp = fmaxf(mp, syy[cc*32 + tid]);
            mq = fmaxf(mq, syy[2048 + cc*32 + tid]);
        }
        float ep = 0.f, eq = 0.f;
        for (int cc = 0; cc < CI; cc++){
            ep += __expf(syy[cc*32 + tid] - mp);
            eq += __expf(syy[2048 + cc*32 + tid] - mq);
        }
        red0[tid] = mp + __logf(ep);
        red1[tid] = mq + __logf(eq);
    }
    __syncthreads();
    float lsep = red0[lsub], lseq = red1[lsub];
    #pragma unroll
    for (int i = 0; i < 8; i++){
        int cc = dg*8 + i;
        float lp = syy[cc*32 + lsub] - lsep;
        float lq = syy[2048 + cc*32 + lsub] - lseq;
        skl[cc*32 + lsub] = __expf(lp)*(lp - lq);
    }
    __syncthreads();
    // fused in-projection for t+1: xz[256, 32pix] = W0 @ kl + b0
    int rowq = tid >> 2, pixq = tid & 3;   // warp: 8 rowq x 4 pixq
    float a2[4][8];
    #pragma unroll
    for (int i = 0; i < 4; i++){
        float bb = sbin[rowq*4 + i];
        #pragma unroll
        for (int p = 0; p < 8; p++) a2[i][p] = bb;
    }
    #pragma unroll 2
    for (int c4 = 0; c4 < 16; c4++){
        float4 w0 = *(const float4*)&swT[(c4*4+0)*260 + rowq*4];
        float4 w1 = *(const float4*)&swT[(c4*4+1)*260 + rowq*4];
        float4 w2 = *(const float4*)&swT[(c4*4+2)*260 + rowq*4];
        float4 w3 = *(const float4*)&swT[(c4*4+3)*260 + rowq*4];
        float k0[8], k1[8], k2[8], k3[8];
        *(float4*)&k0[0] = *(const float4*)&skl[(c4*4+0)*32 + pixq*8];
        *(float4*)&k0[4] = *(const float4*)&skl[(c4*4+0)*32 + pixq*8 + 4];
        *(float4*)&k1[0] = *(const float4*)&skl[(c4*4+1)*32 + pixq*8];
        *(float4*)&k1[4] = *(const float4*)&skl[(c4*4+1)*32 + pixq*8 + 4];
        *(float4*)&k2[0] = *(const float4*)&skl[(c4*4+2)*32 + pixq*8];
        *(float4*)&k2[4] = *(const float4*)&skl[(c4*4+2)*32 + pixq*8 + 4];
        *(float4*)&k3[0] = *(const float4*)&skl[(c4*4+3)*32 + pixq*8];
        *(float4*)&k3[4] = *(const float4*)&skl[(c4*4+3)*32 + pixq*8 + 4];
        float wr0[4] = {w0.x, w0.y, w0.z, w0.w};
        float wr1[4] = {w1.x, w1.y, w1.z, w1.w};
        float wr2[4] = {w2.x, w2.y, w2.z, w2.w};
        float wr3[4] = {w3.x, w3.y, w3.z, w3.w};
        #pragma unroll
        for (int i = 0; i < 4; i++)
            #pragma unroll
            for (int p = 0; p < 8; p++)
                a2[i][p] += wr0[i]*k0[p] + wr1[i]*k1[p] + wr2[i]*k2[p] + wr3[i]*k3[p];
    }
    #pragma unroll
    for (int i = 0; i < 4; i++){
        int r = rowq*4 + i;
        float* o = g_xz + ((size_t)SB*2*DI + r)*LL + blockIdx.x*32 + pixq*8;
        *(float4*)&o[0] = make_float4(a2[i][0], a2[i][1], a2[i][2], a2[i][3]);
        *(float4*)&o[4] = make_float4(a2[i][4], a2[i][5], a2[i][6], a2[i][7]);
    }
}

// ---------------- launch ----------------
extern "C" void kernel_launch(void* const* d_in, const int* in_sizes, int n_in,
                              void* d_out, int out_size){
    const float* img    = (const float*)d_in[0];
    const float* dz     = (const float*)d_in[1];
    const float* sigma  = (const float*)d_in[2];
    const float* in_w   = (const float*)d_in[3];
    const float* in_b   = (const float*)d_in[4];
    const float* conv_w = (const float*)d_in[5];
    const float* conv_b = (const float*)d_in[6];
    const float* xp_w   = (const float*)d_in[7];
    const float* dt_w   = (const float*)d_in[8];
    const float* dt_b   = (const float*)d_in[9];
    const float* A_logs = (const float*)d_in[10];
    const float* Ds     = (const float*)d_in[11];
    const float* onw    = (const float*)d_in[12];
    const float* onb    = (const float*)d_in[13];
    const float* ow     = (const float*)d_in[14];
    const float* ob     = (const float*)d_in[15];
    const float* niw    = (const float*)d_in[16];
    const float* nib    = (const float*)d_in[17];
    const float* ndw    = (const float*)d_in[18];
    const float* ndb    = (const float*)d_in[19];
    float* outp = (float*)d_out;

    cudaFuncSetAttribute(k_xproj, cudaFuncAttributeMaxDynamicSharedMemorySize, XP_SMEM);
    cudaFuncSetAttribute(k_mergeSeq, cudaFuncAttributeMaxDynamicSharedMemorySize, MS_SMEM);

    k_init<<<dim3(72,5,1), 128>>>(dz, sigma, img, niw, nib, ndw, ndb);

    // combined first wave: frames 0..3 (m=1) + sequential t=0 (m=0)
    k_inproj<<<dim3(18,8,5), 128>>>(in_w, in_b);
    k_conv  <<<dim3(DI,5,1), 256>>>(conv_w, conv_b, 0);
    k_xproj <<<dim3(24,KK,5), 192, XP_SMEM>>>(xp_w, dt_w, dt_b, 0);
    k_scan  <<<dim3(DI,KK,5), 256>>>(A_logs, 0);
    k_mergeBias<<<dim3(72,4,1), 256>>>(onw, onb, ow, ob, Ds);
    k_mergeSeq <<<dim3(72,1,1), 256, MS_SMEM>>>(onw, onb, ow, ob, Ds, in_w, in_b,
                                                0, 0, nullptr);

    // t = 1..3 (4 kernels per step; inproj fused into previous merge)
    for (int t = 1; t < TT; t++){
        k_conv  <<<dim3(DI,1,1), 256>>>(conv_w, conv_b, SB);
        k_xproj <<<dim3(24,KK,1), 192, XP_SMEM>>>(xp_w, dt_w, dt_b, SB);
        k_scan  <<<dim3(DI,KK,1), 256>>>(A_logs, SB);
        k_mergeSeq<<<dim3(72,1,1), 256, MS_SMEM>>>(onw, onb, ow, ob, Ds, in_w, in_b,
                                                   t, (t == TT-1) ? 1 : 0,
                                                   (t == TT-1) ? outp : nullptr);
    }
}

// round 10
// speedup vs baseline: 1.4660x; 1.0193x over previous
#include <cuda_runtime.h>

#define CI 64
#define DI 128
#define SS 16
#define RR 4
#define KK 4
#define HH 48
#define WW 48
#define LL 2304
#define TT 4
#define NB 5          // slices: 0..3 = bias frames, 4 = sequential pipeline
#define SB 4
#define NCH 16
#define LCH 144
#define LOG2E 1.4426950408889634f
#define LTX 96        // xproj l-tile
#define XP_SMEM ((64*LTX + 36*DI + DI*RR + DI)*4)
#define MS_SMEM ((4096+8192+256+256+128+128+128+64+2048+64*260+256)*4)

// ---------------- scratch (static device globals; no allocations) ----------------
__device__ float g_prev[CI*LL];
__device__ float g_cur [CI*LL];
__device__ float g_kl  [CI*LL];
__device__ float g_xln [TT*CI*LL];
__device__ float g_bias[TT*CI*LL];
__device__ float g_xz  [NB*2*DI*LL];
__device__ float g_xc  [NB*DI*LL];
__device__ float g_xcT [NB*DI*LL];
__device__ float g_dt  [NB*KK*DI*LL];
__device__ float g_dtx [NB*KK*DI*LL];
__device__ float g_B4  [NB*KK*LL*SS];   // [(slice,k)][l/4][s][4]
__device__ float g_C4  [NB*KK*LL*SS];
__device__ float g_y   [NB*KK*DI*LL];

// ---------------- init: y=0: prev/cur/kl(t0); y=1..4: xln[t]; grid(72,5), 128 thr ----------------
__global__ void k_init(const float* __restrict__ dz, const float* __restrict__ sigma,
                       const float* __restrict__ img,
                       const float* __restrict__ niw, const float* __restrict__ nib,
                       const float* __restrict__ ndw, const float* __restrict__ ndb){
    __shared__ float sx[CI*33];
    __shared__ float scur[CI*33];
    __shared__ float smu[32], srs[32], slp[32], slq[32];
    int l0 = blockIdx.x*32, tid = threadIdx.x;
    if (blockIdx.y == 0){
        for (int j = tid; j < CI*32; j += 128){
            int c = j >> 5, li = j & 31;
            sx[c*33 + li] = dz[c*LL + l0 + li];
        }
        __syncthreads();
        if (tid < 32){
            float s0 = 0.f, s1 = 0.f;
            for (int c = 0; c < CI; c++){ float v = sx[c*33 + tid]; s0 += v; s1 += v*v; }
            float mu = s0*(1.f/CI);
            smu[tid] = mu;
            srs[tid] = rsqrtf(s1*(1.f/CI) - mu*mu + 1e-6f);
        }
        __syncthreads();
        for (int j = tid; j < CI*32; j += 128){
            int c = j >> 5, li = j & 31;
            float pv = (sx[c*33+li] - smu[li])*srs[li]*ndw[c] + ndb[c];
            float cv = pv * __expf(sigma[c*LL + l0 + li]);
            g_prev[c*LL + l0 + li] = pv;
            g_cur [c*LL + l0 + li] = cv;
            sx  [c*33 + li] = pv;
            scur[c*33 + li] = cv;
        }
        __syncthreads();
        if (tid < 32){
            float mp = -1e30f, mq = -1e30f;
            for (int c = 0; c < CI; c++){
                mp = fmaxf(mp, sx  [c*33 + tid]);
                mq = fmaxf(mq, scur[c*33 + tid]);
            }
            float ep = 0.f, eq = 0.f;
            for (int c = 0; c < CI; c++){
                ep += __expf(sx  [c*33 + tid] - mp);
                eq += __expf(scur[c*33 + tid] - mq);
            }
            slp[tid] = mp + __logf(ep);
            slq[tid] = mq + __logf(eq);
        }
        __syncthreads();
        for (int j = tid; j < CI*32; j += 128){
            int c = j >> 5, li = j & 31;
            float lp = sx  [c*33+li] - slp[li];
            float lq = scur[c*33+li] - slq[li];
            g_kl[c*LL + l0 + li] = __expf(lp)*(lp - lq);
        }
    } else {
        int t = blockIdx.y - 1;
        for (int j = tid; j < CI*32; j += 128){
            int c = j >> 5, li = j & 31;
            sx[c*33 + li] = img[(t*CI + c)*LL + l0 + li];
        }
        __syncthreads();
        if (tid < 32){
            float s0 = 0.f, s1 = 0.f;
            for (int c = 0; c < CI; c++){ float v = sx[c*33 + tid]; s0 += v; s1 += v*v; }
            float mu = s0*(1.f/CI);
            smu[tid] = mu;
            srs[tid] = rsqrtf(s1*(1.f/CI) - mu*mu + 1e-6f);
        }
        __syncthreads();
        for (int j = tid; j < CI*32; j += 128){
            int c = j >> 5, li = j & 31;
            g_xln[(t*CI + c)*LL + l0 + li] = (sx[c*33+li] - smu[li])*srs[li]*niw[c] + nib[c];
        }
    }
}

// ---------------- in-projection GEMM (combined first wave only); grid(18,8,5), 128 thr ----------------
__global__ void k_inproj(const float* __restrict__ in_w, const float* __restrict__ in_b){
    __shared__ float sx[64*128];
    __shared__ float swT[64*33];
    const int lt = blockIdx.x, dtile = blockIdx.y, fb = blockIdx.z, tid = threadIdx.x;
    const int m = (fb < 4) ? 1 : 0;
    const int slice = fb;
    const float* src = ((fb < 4) ? (g_xln + fb*CI*LL) : g_kl) + lt*128;
    for (int j = tid; j < 64*128; j += 128){
        int c = j >> 7;
        sx[j] = src[c*LL + tid];
    }
    for (int j = tid; j < 32*64; j += 128){
        int dp = j >> 6, c = j & 63;
        swT[c*33 + dp] = __ldg(&in_w[(m*256 + dtile*32 + dp)*64 + c]);
    }
    __syncthreads();
    int lq = tid & 31, dq = tid >> 5;
    float acc[8][4];
    #pragma unroll
    for (int i = 0; i < 8; i++){
        float bb = __ldg(&in_b[m*256 + dtile*32 + dq*8 + i]);
        #pragma unroll
        for (int j = 0; j < 4; j++) acc[i][j] = bb;
    }
    #pragma unroll 4
    for (int c = 0; c < 64; c++){
        float4 xv = *(const float4*)&sx[c*128 + lq*4];
        float xa[4] = {xv.x, xv.y, xv.z, xv.w};
        float wv[8];
        #pragma unroll
        for (int i = 0; i < 8; i++) wv[i] = swT[c*33 + dq*8 + i];
        #pragma unroll
        for (int i = 0; i < 8; i++)
            #pragma unroll
            for (int j = 0; j < 4; j++) acc[i][j] += wv[i]*xa[j];
    }
    #pragma unroll
    for (int i = 0; i < 8; i++){
        int d = dtile*32 + dq*8 + i;
        float* o = g_xz + ((size_t)slice*2*DI + d)*LL + lt*128 + lq*4;
        *(float4*)o = make_float4(acc[i][0], acc[i][1], acc[i][2], acc[i][3]);
    }
}

// ---------------- depthwise 3x3 conv + bias + silu; grid(DI,ny), 256 thr ----------------
__global__ void k_conv(const float* __restrict__ cw, const float* __restrict__ cb, int bofs){
    __shared__ float sin[LL];
    __shared__ float sc[48*49];
    int d = blockIdx.x, slice = blockIdx.y + bofs, tid = threadIdx.x;
    int m = (slice < SB) ? 1 : 0;
    const float* in = g_xz + ((size_t)slice*2*DI + d)*LL;
    for (int i = tid; i < LL; i += 256) sin[i] = in[i];
    float w9[9];
    #pragma unroll
    for (int j = 0; j < 9; j++) w9[j] = __ldg(&cw[(m*DI + d)*9 + j]);
    float bias = __ldg(&cb[m*DI + d]);
    __syncthreads();
    for (int i = tid; i < LL; i += 256){
        int h = i/48, w = i%48;
        float acc = 0.f;
        #pragma unroll
        for (int ky = 0; ky < 3; ky++){
            int hy = h + ky - 1;
            if (hy < 0 || hy >= 48) continue;
            #pragma unroll
            for (int kx = 0; kx < 3; kx++){
                int wx = w + kx - 1;
                if (wx < 0 || wx >= 48) continue;
                acc += w9[ky*3+kx] * sin[hy*48 + wx];
            }
        }
        acc += bias;
        acc = acc / (1.f + __expf(-acc));
        sc[h*49 + w] = acc;
    }
    __syncthreads();
    float* oc = g_xc  + ((size_t)slice*DI + d)*LL;
    float* ot = g_xcT + ((size_t)slice*DI + d)*LL;
    for (int i = tid; i < LL; i += 256){
        int h = i/48, w = i%48;
        oc[i] = sc[h*49 + w];
        ot[i] = sc[w*49 + h];
    }
}

// ---------------- x-projection v3: split-c register-tiled GEMM; grid(24,K,nz), 192 thr ----------
__global__ __launch_bounds__(192) void k_xproj(const float* __restrict__ xpw,
                                               const float* __restrict__ dtw,
                                               const float* __restrict__ dtb,
                                               int bofs){
    extern __shared__ float sm[];
    float* s1  = sm;                     // [64][LTX] half x-tile
    float* s2  = sm + 64*LTX;            // weights [36][DI] -> xdbl[36][LTX]
    float* sdw = s2 + 36*DI;
    float* sdb = sdw + DI*RR;
    int lt = blockIdx.x, k = blockIdx.y, slice = blockIdx.z + bofs, tid = threadIdx.x;
    int m = (slice < SB) ? 1 : 0;
    const float* wk = xpw + (m*KK + k)*36*DI;
    for (int j = tid; j < 36*DI; j += 192) s2[j] = __ldg(&wk[j]);
    const float* dwk = dtw + (m*KK + k)*DI*RR;
    for (int j = tid; j < DI*RR; j += 192) sdw[j] = __ldg(&dwk[j]);
    if (tid < DI) sdb[tid] = __ldg(&dtb[(m*KK + k)*DI + tid]);
    bool fwd = (k < 2);
    const float* src = ((k & 1) ? g_xcT : g_xc) + (size_t)slice*DI*LL;
    int lq = tid % 48, rg = tid / 48;
    const float4* w4 = (const float4*)s2;
    float acc[9][2];
    #pragma unroll
    for (int i = 0; i < 9; i++){ acc[i][0] = 0.f; acc[i][1] = 0.f; }
    #pragma unroll
    for (int half = 0; half < 2; half++){
        __syncthreads();                 // weights staged / prior-half GEMM reads done
        for (int j = tid; j < 64*LTX; j += 192){
            int d = j/LTX, ls = j%LTX;
            int gl = fwd ? (lt*LTX + ls) : (LL-1 - (lt*LTX + ls));
            s1[j] = src[(half*64 + d)*LL + gl];
        }
        __syncthreads();
        #pragma unroll 2
        for (int c4 = 0; c4 < 16; c4++){
            float4 w[9];
            #pragma unroll
            for (int i = 0; i < 9; i++) w[i] = w4[(rg*9 + i)*32 + half*16 + c4];
            float2 x0 = *(const float2*)&s1[(c4*4 + 0)*LTX + lq*2];
            float2 x1 = *(const float2*)&s1[(c4*4 + 1)*LTX + lq*2];
            float2 x2 = *(const float2*)&s1[(c4*4 + 2)*LTX + lq*2];
            float2 x3 = *(const float2*)&s1[(c4*4 + 3)*LTX + lq*2];
            #pragma unroll
            for (int i = 0; i < 9; i++){
                acc[i][0] += w[i].x*x0.x + w[i].y*x1.x + w[i].z*x2.x + w[i].w*x3.x;
                acc[i][1] += w[i].x*x0.y + w[i].y*x1.y + w[i].z*x2.y + w[i].w*x3.y;
            }
        }
    }
    __syncthreads();                     // GEMM reads of weights done; s2 reusable
    float* xdbl = s2;
    #pragma unroll
    for (int i = 0; i < 9; i++){
        xdbl[(rg*9 + i)*LTX + lq*2    ] = acc[i][0];
        xdbl[(rg*9 + i)*LTX + lq*2 + 1] = acc[i][1];
    }
    __syncthreads();
    // dt epilogue; s1 still holds x for d=64..127, d<64 re-read from global
    int ls2 = tid % LTX, rg2 = tid / LTX;
    int gl2 = fwd ? (lt*LTX + ls2) : (LL-1 - (lt*LTX + ls2));
    float* dto  = g_dt  + ((size_t)(slice*KK + k)*DI)*LL + lt*LTX;
    float* dtxo = g_dtx + ((size_t)(slice*KK + k)*DI)*LL + lt*LTX;
    float xr0 = xdbl[0*LTX + ls2], xr1 = xdbl[1*LTX + ls2];
    float xr2 = xdbl[2*LTX + ls2], xr3 = xdbl[3*LTX + ls2];
    #pragma unroll 4
    for (int i = 0; i < 64; i++){
        int d = rg2 + 2*i;
        float v = sdb[d] + sdw[d*4+0]*xr0 + sdw[d*4+1]*xr1 + sdw[d*4+2]*xr2 + sdw[d*4+3]*xr3;
        v = fmaxf(v, 0.f) + log1pf(__expf(-fabsf(v)));
        float xv = (d >= 64) ? s1[(d-64)*LTX + ls2] : __ldg(&src[d*LL + gl2]);
        dto [d*LL + ls2] = v;
        dtxo[d*LL + ls2] = v * xv;
    }
    float* b4 = g_B4 + (size_t)(slice*KK + k)*LL*SS;
    float* c4o = g_C4 + (size_t)(slice*KK + k)*LL*SS;
    for (int j = tid; j < LTX*SS; j += 192){
        int lls = j/SS, s = j%SS;
        int gl = lt*LTX + lls;
        size_t o = (size_t)(gl >> 2)*64 + s*4 + (gl & 3);
        b4 [o] = xdbl[(4 + s)*LTX + lls];
        c4o[o] = xdbl[(20 + s)*LTX + lls];
    }
}

// ---------------- scan: vec4 loads, smem transpose-reduce; grid(DI,K,nz), 256 thr ----------------
__global__ __launch_bounds__(256) void k_scan(const float* __restrict__ A_logs, int bofs){
    __shared__ float pA[256], pH[256], hI[256];
    __shared__ float tv[8][544];
    int d = blockIdx.x, k = blockIdx.y, slice = blockIdx.z + bofs, tid = threadIdx.x;
    int m = (slice < SB) ? 1 : 0;
    int s = tid & 15, c = tid >> 4;
    int w = tid >> 5, g = (tid >> 4) & 1;
    float* tile = &tv[w][g*272];
    float A2 = -__expf(__ldg(&A_logs[((m*KK + k)*DI + d)*SS + s])) * LOG2E;
    const float4* dt4 = (const float4*)(g_dt  + ((size_t)(slice*KK + k)*DI + d)*LL);
    const float4* dx4 = (const float4*)(g_dtx + ((size_t)(slice*KK + k)*DI + d)*LL);
    const float4* b4  = (const float4*)(g_B4 + (size_t)(slice*KK + k)*LL*SS);
    const float4* c4  = (const float4*)(g_C4 + (size_t)(slice*KK + k)*LL*SS);
    int q0 = c*36;
    float ap = 1.f, h = 0.f;
    #pragma unroll 4
    for (int q = 0; q < 36; q++){
        float4 dt = __ldg(&dt4[q0 + q]);
        float4 dx = __ldg(&dx4[q0 + q]);
        float4 bb = __ldg(&b4[(size_t)(q0 + q)*16 + s]);
        float da;
        da = exp2f(A2*dt.x); ap *= da; h = da*h + dx.x*bb.x;
        da = exp2f(A2*dt.y); ap *= da; h = da*h + dx.y*bb.y;
        da = exp2f(A2*dt.z); ap *= da; h = da*h + dx.z*bb.z;
        da = exp2f(A2*dt.w); ap *= da; h = da*h + dx.w*bb.w;
    }
    pA[tid] = ap; pH[tid] = h;
    __syncthreads();
    if (tid < 16){
        float hh = 0.f;
        #pragma unroll
        for (int cc = 0; cc < NCH; cc++){
            hI[cc*16 + tid] = hh;
            hh = pA[cc*16 + tid]*hh + pH[cc*16 + tid];
        }
    }
    __syncthreads();
    h = hI[tid];
    bool fwd = (k < 2);
    float* yrow = g_y + ((size_t)(slice*KK + k)*DI + d)*LL;
    int l0 = c*LCH;
    for (int blk = 0; blk < 9; blk++){
        #pragma unroll
        for (int qq = 0; qq < 4; qq++){
            int q = q0 + blk*4 + qq;
            float4 dt = __ldg(&dt4[q]);
            float4 dx = __ldg(&dx4[q]);
            float4 bb = __ldg(&b4[(size_t)q*16 + s]);
            float4 cc = __ldg(&c4[(size_t)q*16 + s]);
            float da;
            da = exp2f(A2*dt.x); h = da*h + dx.x*bb.x; tile[(qq*4+0)*17 + s] = h*cc.x;
            da = exp2f(A2*dt.y); h = da*h + dx.y*bb.y; tile[(qq*4+1)*17 + s] = h*cc.y;
            da = exp2f(A2*dt.z); h = da*h + dx.z*bb.z; tile[(qq*4+2)*17 + s] = h*cc.z;
            da = exp2f(A2*dt.w); h = da*h + dx.w*bb.w; tile[(qq*4+3)*17 + s] = h*cc.w;
        }
        __syncwarp();
        float sum = 0.f;
        #pragma unroll
        for (int s2 = 0; s2 < 16; s2++) sum += tile[s*17 + s2];
        int l = l0 + blk*16 + s;
        yrow[fwd ? l : (LL-1-l)] = sum;
        __syncwarp();
    }
}

// ---------------- bias merge (frames 0..3, m=1): grid(72,4), 256 thr ----------------
__global__ void k_mergeBias(const float* __restrict__ onw, const float* __restrict__ onb,
                            const float* __restrict__ ow,  const float* __restrict__ ob,
                            const float* __restrict__ Dsp){
    __shared__ float syy[DI*32];
    __shared__ float sow[CI*DI];
    __shared__ float red0[8*32], red1[8*32];
    __shared__ float ssum[DI], sonw[DI], sonb[DI], sob[CI];
    int tid = threadIdx.x;
    int lsub = tid & 31, dg = tid >> 5;
    int fb = blockIdx.y, slice = fb;
    int l = blockIdx.x*32 + lsub;
    int tl = (l % 48)*48 + l/48;
    for (int j = tid; j < CI*DI; j += 256) sow[j] = __ldg(&ow[CI*DI + j]);
    if (tid < DI){
        float s = 0.f;
        #pragma unroll
        for (int k = 0; k < KK; k++) s += __ldg(&Dsp[(KK + k)*DI + tid]);
        ssum[tid] = s;
        sonw[tid] = __ldg(&onw[DI + tid]);
        sonb[tid] = __ldg(&onb[DI + tid]);
    }
    if (tid < CI) sob[tid] = __ldg(&ob[CI + tid]);
    __syncthreads();
    float ps = 0.f, pq = 0.f;
    for (int i = 0; i < 16; i++){
        int d = dg*16 + i;
        const float* y0 = g_y + ((size_t)(slice*KK + 0)*DI + d)*LL;
        const float* y1 = g_y + ((size_t)(slice*KK + 1)*DI + d)*LL;
        const float* y2 = g_y + ((size_t)(slice*KK + 2)*DI + d)*LL;
        const float* y3 = g_y + ((size_t)(slice*KK + 3)*DI + d)*LL;
        float v = y0[l] + y2[l] + y1[tl] + y3[tl]
                + ssum[d] * g_xc[((size_t)slice*DI + d)*LL + l];
        syy[d*32 + lsub] = v;
        ps += v; pq += v*v;
    }
    red0[dg*32 + lsub] = ps; red1[dg*32 + lsub] = pq;
    __syncthreads();
    if (dg == 0){
        float s0 = 0.f, s1 = 0.f;
        #pragma unroll
        for (int j = 0; j < 8; j++){ s0 += red0[j*32 + lsub]; s1 += red1[j*32 + lsub]; }
        float mu  = s0 * (1.f/DI);
        float var = s1 * (1.f/DI) - mu*mu;
        red0[lsub] = mu;
        red1[lsub] = rsqrtf(var + 1e-6f);
    }
    __syncthreads();
    float mu = red0[lsub], rs = red1[lsub];
    for (int i = 0; i < 16; i++){
        int d = dg*16 + i;
        float v  = syy[d*32 + lsub];
        float wn = (v - mu)*rs*sonw[d] + sonb[d];
        float z  = g_xz[((size_t)slice*2*DI + DI + d)*LL + l];
        float sz = z / (1.f + __expf(-z));
        syy[d*32 + lsub] = wn * sz;
    }
    __syncthreads();
    float acc[8];
    #pragma unroll
    for (int i = 0; i < 8; i++) acc[i] = sob[dg*8 + i];
    for (int d = 0; d < DI; d++){
        float v = syy[d*32 + lsub];
        #pragma unroll
        for (int i = 0; i < 8; i++) acc[i] += sow[(dg*8 + i)*DI + d] * v;
    }
    #pragma unroll
    for (int i = 0; i < 8; i++)
        g_bias[(fb*CI + dg*8 + i)*LL + l] = acc[i];
}

// ---------------- sequential merge: update + KL + fused in-projection for t+1 ----------------
// grid(72), 256 thr, dynamic smem
__global__ __launch_bounds__(256) void k_mergeSeq(
        const float* __restrict__ onw, const float* __restrict__ onb,
        const float* __restrict__ ow,  const float* __restrict__ ob,
        const float* __restrict__ Dsp,
        const float* __restrict__ in_w, const float* __restrict__ in_b,
        int t, int last, float* __restrict__ outp){
    extern __shared__ float sm[];
    float* syy  = sm;              // 4096
    float* sow  = syy + 4096;      // 8192
    float* red0 = sow + 8192;      // 256
    float* red1 = red0 + 256;      // 256
    float* ssum = red1 + 256;      // 128
    float* sonw = ssum + 128;      // 128
    float* sonb = sonw + 128;      // 128
    float* sob  = sonb + 128;      // 64
    float* skl  = sob + 64;        // 2048
    float* swT  = skl + 2048;      // 64*260
    float* sbin = swT + 64*260;    // 256
    const int slice = SB;
    int tid = threadIdx.x;
    int lsub = tid & 31, dg = tid >> 5;
    int l = blockIdx.x*32 + lsub;
    int tl = (l % 48)*48 + l/48;
    for (int j = tid; j < CI*DI; j += 256) sow[j] = __ldg(&ow[j]);
    if (tid < DI){
        float s = 0.f;
        #pragma unroll
        for (int k = 0; k < KK; k++) s += __ldg(&Dsp[k*DI + tid]);
        ssum[tid] = s;
        sonw[tid] = __ldg(&onw[tid]);
        sonb[tid] = __ldg(&onb[tid]);
    }
    if (tid < CI) sob[tid] = __ldg(&ob[tid]);
    if (!last){
        for (int j = tid; j < 256*64; j += 256){
            int row = j >> 6, c = j & 63;
            swT[c*260 + row] = __ldg(&in_w[row*64 + c]);
        }
        sbin[tid] = __ldg(&in_b[tid]);
    }
    __syncthreads();
    float ps = 0.f, pq = 0.f;
    for (int i = 0; i < 16; i++){
        int d = dg*16 + i;
        const float* y0 = g_y + ((size_t)(slice*KK + 0)*DI + d)*LL;
        const float* y1 = g_y + ((size_t)(slice*KK + 1)*DI + d)*LL;
        const float* y2 = g_y + ((size_t)(slice*KK + 2)*DI + d)*LL;
        const float* y3 = g_y + ((size_t)(slice*KK + 3)*DI + d)*LL;
        float v = y0[l] + y2[l] + y1[tl] + y3[tl]
                + ssum[d] * g_xc[((size_t)slice*DI + d)*LL + l];
        syy[d*32 + lsub] = v;
        ps += v; pq += v*v;
    }
    red0[dg*32 + lsub] = ps; red1[dg*32 + lsub] = pq;
    __syncthreads();
    if (dg == 0){
        float s0 = 0.f, s1 = 0.f;
        #pragma unroll
        for (int j = 0; j < 8; j++){ s0 += red0[j*32 + lsub]; s1 += red1[j*32 + lsub]; }
        float mu  = s0 * (1.f/DI);
        float var = s1 * (1.f/DI) - mu*mu;
        red0[lsub] = mu;
        red1[lsub] = rsqrtf(var + 1e-6f);
    }
    __syncthreads();
    float mu = red0[lsub], rs = red1[lsub];
    for (int i = 0; i < 16; i++){
        int d = dg*16 + i;
        float v  = syy[d*32 + lsub];
        float wn = (v - mu)*rs*sonw[d] + sonb[d];
        float z  = g_xz[((size_t)slice*2*DI + DI + d)*LL + l];
        float sz = z / (1.f + __expf(-z));
        syy[d*32 + lsub] = wn * sz;
    }
    __syncthreads();
    float acc[8];
    #pragma unroll
    for (int i = 0; i < 8; i++) acc[i] = sob[dg*8 + i];
    for (int d = 0; d < DI; d++){
        float v = syy[d*32 + lsub];
        #pragma unroll
        for (int i = 0; i < 8; i++) acc[i] += sow[(dg*8 + i)*DI + d] * v;
    }
    float co[8], nv[8];
    #pragma unroll
    for (int i = 0; i < 8; i++){
        int cc = dg*8 + i;
        int idx = cc*LL + l;
        co[i] = g_cur[idx];
        g_prev[idx] = co[i];
        nv[i] = co[i] * __expf(acc[i]) + g_bias[(t*CI + cc)*LL + l];
        g_cur[idx] = nv[i];
    }
    if (last){
        #pragma unroll
        for (int i = 0; i < 8; i++) outp[(dg*8 + i)*LL + l] = nv[i];
        return;
    }
    __syncthreads();
    #pragma unroll
    for (int i = 0; i < 8; i++){
        int cc = dg*8 + i;
        syy[cc*32 + lsub]        = co[i];
        syy[2048 + cc*32 + lsub] = nv[i];
    }
    __syncthreads();
    if (tid < 32){
        float mp = -1e30f, mq = -1e30f;
        for (int cc = 0; cc < CI; cc++){
            mp = fmaxf(mp, syy[cc*32 + tid]);
            mq = fmaxf(mq, syy[2048 + cc*32 + tid]);
        }
        float ep = 0.f, eq = 0.f;
        for (int cc = 0; cc < CI; cc++){
            ep += __expf(syy[cc*32 + tid] - mp);
            eq += __expf(syy[2048 + cc*32 + tid] - mq);
        }
        red0[tid] = mp + __logf(ep);
        red1[tid] = mq + __logf(eq);
    }
    __syncthreads();
    float lsep = red0[lsub], lseq = red1[lsub];
    #pragma unroll
    for (int i = 0; i < 8; i++){
        int cc = dg*8 + i;
        float lp = syy[cc*32 + lsub] - lsep;
        float lq = syy[2048 + cc*32 + lsub] - lseq;
        skl[cc*32 + lsub] = __expf(lp)*(lp - lq);
    }
    __syncthreads();
    int rowq = tid >> 2, pixq = tid & 3;
    float a2[4][8];
    #pragma unroll
    for (int i = 0; i < 4; i++){
        float bb = sbin[rowq*4 + i];
        #pragma unroll
        for (int p = 0; p < 8; p++) a2[i][p] = bb;
    }
    #pragma unroll 2
    for (int c4 = 0; c4 < 16; c4++){
        float4 w0 = *(const float4*)&swT[(c4*4+0)*260 + rowq*4];
        float4 w1 = *(const float4*)&swT[(c4*4+1)*260 + rowq*4];
        float4 w2 = *(const float4*)&swT[(c4*4+2)*260 + rowq*4];
        float4 w3 = *(const float4*)&swT[(c4*4+3)*260 + rowq*4];
        float k0[8], k1[8], k2[8], k3[8];
        *(float4*)&k0[0] = *(const float4*)&skl[(c4*4+0)*32 + pixq*8];
        *(float4*)&k0[4] = *(const float4*)&skl[(c4*4+0)*32 + pixq*8 + 4];
        *(float4*)&k1[0] = *(const float4*)&skl[(c4*4+1)*32 + pixq*8];
        *(float4*)&k1[4] = *(const float4*)&skl[(c4*4+1)*32 + pixq*8 + 4];
        *(float4*)&k2[0] = *(const float4*)&skl[(c4*4+2)*32 + pixq*8];
        *(float4*)&k2[4] = *(const float4*)&skl[(c4*4+2)*32 + pixq*8 + 4];
        *(float4*)&k3[0] = *(const float4*)&skl[(c4*4+3)*32 + pixq*8];
        *(float4*)&k3[4] = *(const float4*)&skl[(c4*4+3)*32 + pixq*8 + 4];
        float wr0[4] = {w0.x, w0.y, w0.z, w0.w};
        float wr1[4] = {w1.x, w1.y, w1.z, w1.w};
        float wr2[4] = {w2.x, w2.y, w2.z, w2.w};
        float wr3[4] = {w3.x, w3.y, w3.z, w3.w};
        #pragma unroll
        for (int i = 0; i < 4; i++)
            #pragma unroll
            for (int p = 0; p < 8; p++)
                a2[i][p] += wr0[i]*k0[p] + wr1[i]*k1[p] + wr2[i]*k2[p] + wr3[i]*k3[p];
    }
    #pragma unroll
    for (int i = 0; i < 4; i++){
        int r = rowq*4 + i;
        float* o = g_xz + ((size_t)SB*2*DI + r)*LL + blockIdx.x*32 + pixq*8;
        *(float4*)&o[0] = make_float4(a2[i][0], a2[i][1], a2[i][2], a2[i][3]);
        *(float4*)&o[4] = make_float4(a2[i][4], a2[i][5], a2[i][6], a2[i][7]);
    }
}

// ---------------- launch ----------------
extern "C" void kernel_launch(void* const* d_in, const int* in_sizes, int n_in,
                              void* d_out, int out_size){
    const float* img    = (const float*)d_in[0];
    const float* dz     = (const float*)d_in[1];
    const float* sigma  = (const float*)d_in[2];
    const float* in_w   = (const float*)d_in[3];
    const float* in_b   = (const float*)d_in[4];
    const float* conv_w = (const float*)d_in[5];
    const float* conv_b = (const float*)d_in[6];
    const float* xp_w   = (const float*)d_in[7];
    const float* dt_w   = (const float*)d_in[8];
    const float* dt_b   = (const float*)d_in[9];
    const float* A_logs = (const float*)d_in[10];
    const float* Ds     = (const float*)d_in[11];
    const float* onw    = (const float*)d_in[12];
    const float* onb    = (const float*)d_in[13];
    const float* ow     = (const float*)d_in[14];
    const float* ob     = (const float*)d_in[15];
    const float* niw    = (const float*)d_in[16];
    const float* nib    = (const float*)d_in[17];
    const float* ndw    = (const float*)d_in[18];
    const float* ndb    = (const float*)d_in[19];
    float* outp = (float*)d_out;

    cudaFuncSetAttribute(k_xproj, cudaFuncAttributeMaxDynamicSharedMemorySize, XP_SMEM);
    cudaFuncSetAttribute(k_mergeSeq, cudaFuncAttributeMaxDynamicSharedMemorySize, MS_SMEM);

    k_init<<<dim3(72,5,1), 128>>>(dz, sigma, img, niw, nib, ndw, ndb);

    // combined first wave: frames 0..3 (m=1) + sequential t=0 (m=0)
    k_inproj<<<dim3(18,8,5), 128>>>(in_w, in_b);
    k_conv  <<<dim3(DI,5,1), 256>>>(conv_w, conv_b, 0);
    k_xproj <<<dim3(24,KK,5), 192, XP_SMEM>>>(xp_w, dt_w, dt_b, 0);
    k_scan  <<<dim3(DI,KK,5), 256>>>(A_logs, 0);
    k_mergeBias<<<dim3(72,4,1), 256>>>(onw, onb, ow, ob, Ds);
    k_mergeSeq <<<dim3(72,1,1), 256, MS_SMEM>>>(onw, onb, ow, ob, Ds, in_w, in_b,
                                                0, 0, nullptr);

    // t = 1..3 (4 kernels per step; inproj fused into previous merge)
    for (int t = 1; t < TT; t++){
        k_conv  <<<dim3(DI,1,1), 256>>>(conv_w, conv_b, SB);
        k_xproj <<<dim3(24,KK,1), 192, XP_SMEM>>>(xp_w, dt_w, dt_b, SB);
        k_scan  <<<dim3(DI,KK,1), 256>>>(A_logs, SB);
        k_mergeSeq<<<dim3(72,1,1), 256, MS_SMEM>>>(onw, onb, ow, ob, Ds, in_w, in_b,
                                                   t, (t == TT-1) ? 1 : 0,
                                                   (t == TT-1) ? outp : nullptr);
    }
}

// round 11
// speedup vs baseline: 1.5466x; 1.0550x over previous
#include <cuda_runtime.h>

#define CI 64
#define DI 128
#define SS 16
#define RR 4
#define KK 4
#define HH 48
#define WW 48
#define LL 2304
#define TT 4
#define NB 5          // slices: 0..3 = bias frames, 4 = sequential pipeline
#define SB 4
#define NCH 16
#define LCH 144
#define LOG2E 1.4426950408889634f
#define LTX 48        // xproj l-tile
#define XP_SMEM ((DI*LTX + 36*DI + DI*RR + DI)*4)
#define MS_SMEM ((4096+8192+256+256+128+128+128+64+2048+64*260+256)*4)

// mode: 0 = critical first wave {z0: slice4(seq), z1: slice0(frame0)}
//       1 = frame stream {z: slice z+1}
//       2 = sequential {slice 4}
__device__ __forceinline__ int map_slice(int mode, int z){
    return (mode == 0) ? (z == 0 ? 4 : 0) : ((mode == 1) ? z + 1 : 4);
}

// ---------------- scratch (static device globals; no allocations) ----------------
__device__ float g_prev[CI*LL];
__device__ float g_cur [CI*LL];
__device__ float g_kl  [CI*LL];
__device__ float g_xln [TT*CI*LL];
__device__ float g_bias[TT*CI*LL];
__device__ float g_xz  [NB*2*DI*LL];
__device__ float g_xc  [NB*DI*LL];
__device__ float g_xcT [NB*DI*LL];
__device__ float g_dt  [NB*KK*DI*LL];
__device__ float g_dtx [NB*KK*DI*LL];
__device__ float g_B4  [NB*KK*LL*SS];   // [(slice,k)][l/4][s][4]
__device__ float g_C4  [NB*KK*LL*SS];
__device__ float g_y   [NB*KK*DI*LL];

// ---------------- init: y=0: prev/cur/kl(t0); y=1..4: xln[t]; grid(72,5), 128 thr ----------------
__global__ void k_init(const float* __restrict__ dz, const float* __restrict__ sigma,
                       const float* __restrict__ img,
                       const float* __restrict__ niw, const float* __restrict__ nib,
                       const float* __restrict__ ndw, const float* __restrict__ ndb){
    __shared__ float sx[CI*33];
    __shared__ float scur[CI*33];
    __shared__ float smu[32], srs[32], slp[32], slq[32];
    int l0 = blockIdx.x*32, tid = threadIdx.x;
    if (blockIdx.y == 0){
        for (int j = tid; j < CI*32; j += 128){
            int c = j >> 5, li = j & 31;
            sx[c*33 + li] = dz[c*LL + l0 + li];
        }
        __syncthreads();
        if (tid < 32){
            float s0 = 0.f, s1 = 0.f;
            for (int c = 0; c < CI; c++){ float v = sx[c*33 + tid]; s0 += v; s1 += v*v; }
            float mu = s0*(1.f/CI);
            smu[tid] = mu;
            srs[tid] = rsqrtf(s1*(1.f/CI) - mu*mu + 1e-6f);
        }
        __syncthreads();
        for (int j = tid; j < CI*32; j += 128){
            int c = j >> 5, li = j & 31;
            float pv = (sx[c*33+li] - smu[li])*srs[li]*ndw[c] + ndb[c];
            float cv = pv * __expf(sigma[c*LL + l0 + li]);
            g_prev[c*LL + l0 + li] = pv;
            g_cur [c*LL + l0 + li] = cv;
            sx  [c*33 + li] = pv;
            scur[c*33 + li] = cv;
        }
        __syncthreads();
        if (tid < 32){
            float mp = -1e30f, mq = -1e30f;
            for (int c = 0; c < CI; c++){
                mp = fmaxf(mp, sx  [c*33 + tid]);
                mq = fmaxf(mq, scur[c*33 + tid]);
            }
            float ep = 0.f, eq = 0.f;
            for (int c = 0; c < CI; c++){
                ep += __expf(sx  [c*33 + tid] - mp);
                eq += __expf(scur[c*33 + tid] - mq);
            }
            slp[tid] = mp + __logf(ep);
            slq[tid] = mq + __logf(eq);
        }
        __syncthreads();
        for (int j = tid; j < CI*32; j += 128){
            int c = j >> 5, li = j & 31;
            float lp = sx  [c*33+li] - slp[li];
            float lq = scur[c*33+li] - slq[li];
            g_kl[c*LL + l0 + li] = __expf(lp)*(lp - lq);
        }
    } else {
        int t = blockIdx.y - 1;
        for (int j = tid; j < CI*32; j += 128){
            int c = j >> 5, li = j & 31;
            sx[c*33 + li] = img[(t*CI + c)*LL + l0 + li];
        }
        __syncthreads();
        if (tid < 32){
            float s0 = 0.f, s1 = 0.f;
            for (int c = 0; c < CI; c++){ float v = sx[c*33 + tid]; s0 += v; s1 += v*v; }
            float mu = s0*(1.f/CI);
            smu[tid] = mu;
            srs[tid] = rsqrtf(s1*(1.f/CI) - mu*mu + 1e-6f);
        }
        __syncthreads();
        for (int j = tid; j < CI*32; j += 128){
            int c = j >> 5, li = j & 31;
            g_xln[(t*CI + c)*LL + l0 + li] = (sx[c*33+li] - smu[li])*srs[li]*niw[c] + nib[c];
        }
    }
}

// ---------------- in-projection GEMM; grid(18,8,nz), 128 thr ----------------
__global__ void k_inproj(const float* __restrict__ in_w, const float* __restrict__ in_b,
                         int mode){
    __shared__ float sx[64*128];
    __shared__ float swT[64*33];
    const int lt = blockIdx.x, dtile = blockIdx.y, tid = threadIdx.x;
    const int slice = map_slice(mode, blockIdx.z);
    const int m = (slice == SB) ? 0 : 1;
    const float* src = ((slice == SB) ? g_kl : (g_xln + slice*CI*LL)) + lt*128;
    for (int j = tid; j < 64*128; j += 128){
        int c = j >> 7;
        sx[j] = src[c*LL + tid];
    }
    for (int j = tid; j < 32*64; j += 128){
        int dp = j >> 6, c = j & 63;
        swT[c*33 + dp] = __ldg(&in_w[(m*256 + dtile*32 + dp)*64 + c]);
    }
    __syncthreads();
    int lq = tid & 31, dq = tid >> 5;
    float acc[8][4];
    #pragma unroll
    for (int i = 0; i < 8; i++){
        float bb = __ldg(&in_b[m*256 + dtile*32 + dq*8 + i]);
        #pragma unroll
        for (int j = 0; j < 4; j++) acc[i][j] = bb;
    }
    #pragma unroll 4
    for (int c = 0; c < 64; c++){
        float4 xv = *(const float4*)&sx[c*128 + lq*4];
        float xa[4] = {xv.x, xv.y, xv.z, xv.w};
        float wv[8];
        #pragma unroll
        for (int i = 0; i < 8; i++) wv[i] = swT[c*33 + dq*8 + i];
        #pragma unroll
        for (int i = 0; i < 8; i++)
            #pragma unroll
            for (int j = 0; j < 4; j++) acc[i][j] += wv[i]*xa[j];
    }
    #pragma unroll
    for (int i = 0; i < 8; i++){
        int d = dtile*32 + dq*8 + i;
        float* o = g_xz + ((size_t)slice*2*DI + d)*LL + lt*128 + lq*4;
        *(float4*)o = make_float4(acc[i][0], acc[i][1], acc[i][2], acc[i][3]);
    }
}

// ---------------- depthwise 3x3 conv + bias + silu; grid(DI,nz), 256 thr ----------------
__global__ void k_conv(const float* __restrict__ cw, const float* __restrict__ cb, int mode){
    __shared__ float sin[LL];
    __shared__ float sc[48*49];
    int d = blockIdx.x, tid = threadIdx.x;
    int slice = map_slice(mode, blockIdx.y);
    int m = (slice == SB) ? 0 : 1;
    const float* in = g_xz + ((size_t)slice*2*DI + d)*LL;
    for (int i = tid; i < LL; i += 256) sin[i] = in[i];
    float w9[9];
    #pragma unroll
    for (int j = 0; j < 9; j++) w9[j] = __ldg(&cw[(m*DI + d)*9 + j]);
    float bias = __ldg(&cb[m*DI + d]);
    __syncthreads();
    for (int i = tid; i < LL; i += 256){
        int h = i/48, w = i%48;
        float acc = 0.f;
        #pragma unroll
        for (int ky = 0; ky < 3; ky++){
            int hy = h + ky - 1;
            if (hy < 0 || hy >= 48) continue;
            #pragma unroll
            for (int kx = 0; kx < 3; kx++){
                int wx = w + kx - 1;
                if (wx < 0 || wx >= 48) continue;
                acc += w9[ky*3+kx] * sin[hy*48 + wx];
            }
        }
        acc += bias;
        acc = acc / (1.f + __expf(-acc));
        sc[h*49 + w] = acc;
    }
    __syncthreads();
    float* oc = g_xc  + ((size_t)slice*DI + d)*LL;
    float* ot = g_xcT + ((size_t)slice*DI + d)*LL;
    for (int i = tid; i < LL; i += 256){
        int h = i/48, w = i%48;
        oc[i] = sc[h*49 + w];
        ot[i] = sc[w*49 + h];
    }
}

// ---------------- x-projection v4: LTX=48 register-tiled GEMM; grid(48,K,nz), 192 thr ----------
__global__ __launch_bounds__(192) void k_xproj(const float* __restrict__ xpw,
                                               const float* __restrict__ dtw,
                                               const float* __restrict__ dtb,
                                               int mode){
    extern __shared__ float sm[];
    float* s1  = sm;                     // [DI][48] x-tile
    float* s2  = sm + DI*LTX;            // weights [36][DI] -> xdbl[36][48]
    float* sdw = s2 + 36*DI;
    float* sdb = sdw + DI*RR;
    int lt = blockIdx.x, k = blockIdx.y, tid = threadIdx.x;
    int slice = map_slice(mode, blockIdx.z);
    int m = (slice == SB) ? 0 : 1;
    const float* wk = xpw + (m*KK + k)*36*DI;
    for (int j = tid; j < 36*DI; j += 192) s2[j] = __ldg(&wk[j]);
    const float* dwk = dtw + (m*KK + k)*DI*RR;
    for (int j = tid; j < DI*RR; j += 192) sdw[j] = __ldg(&dwk[j]);
    if (tid < DI) sdb[tid] = __ldg(&dtb[(m*KK + k)*DI + tid]);
    bool fwd = (k < 2);
    const float* src = ((k & 1) ? g_xcT : g_xc) + (size_t)slice*DI*LL;
    for (int j = tid; j < DI*LTX; j += 192){
        int d = j/LTX, ls = j%LTX;
        int gl = fwd ? (lt*LTX + ls) : (LL-1 - (lt*LTX + ls));
        s1[j] = src[d*LL + gl];
    }
    __syncthreads();
    // GEMM: xdbl[36][48] = W[36][128] @ xs[128][48]; thread = (rg 0..3)x(lq 0..47), 9r x 1l
    int lq = tid % 48, rg = tid / 48;
    const float4* w4 = (const float4*)s2;
    float acc[9];
    #pragma unroll
    for (int i = 0; i < 9; i++) acc[i] = 0.f;
    #pragma unroll 4
    for (int c4 = 0; c4 < 32; c4++){
        float4 w[9];
        #pragma unroll
        for (int i = 0; i < 9; i++) w[i] = w4[(rg*9 + i)*32 + c4];
        float x0 = s1[(c4*4 + 0)*LTX + lq];
        float x1 = s1[(c4*4 + 1)*LTX + lq];
        float x2 = s1[(c4*4 + 2)*LTX + lq];
        float x3 = s1[(c4*4 + 3)*LTX + lq];
        #pragma unroll
        for (int i = 0; i < 9; i++)
            acc[i] += w[i].x*x0 + w[i].y*x1 + w[i].z*x2 + w[i].w*x3;
    }
    __syncthreads();                     // weight reads done; s2 reusable
    float* xdbl = s2;
    #pragma unroll
    for (int i = 0; i < 9; i++) xdbl[(rg*9 + i)*LTX + lq] = acc[i];
    __syncthreads();
    // dt/dtx epilogue: x from resident s1
    int ls2 = tid % LTX, rg2 = tid / LTX;
    float* dto  = g_dt  + ((size_t)(slice*KK + k)*DI)*LL + lt*LTX;
    float* dtxo = g_dtx + ((size_t)(slice*KK + k)*DI)*LL + lt*LTX;
    float xr0 = xdbl[0*LTX + ls2], xr1 = xdbl[1*LTX + ls2];
    float xr2 = xdbl[2*LTX + ls2], xr3 = xdbl[3*LTX + ls2];
    #pragma unroll 4
    for (int i = 0; i < 32; i++){
        int d = rg2 + 4*i;
        float v = sdb[d] + sdw[d*4+0]*xr0 + sdw[d*4+1]*xr1 + sdw[d*4+2]*xr2 + sdw[d*4+3]*xr3;
        v = fmaxf(v, 0.f) + log1pf(__expf(-fabsf(v)));
        dto [d*LL + ls2] = v;
        dtxo[d*LL + ls2] = v * s1[d*LTX + ls2];
    }
    float* b4 = g_B4 + (size_t)(slice*KK + k)*LL*SS;
    float* c4o = g_C4 + (size_t)(slice*KK + k)*LL*SS;
    for (int j = tid; j < LTX*SS; j += 192){
        int lls = j/SS, s = j%SS;
        int gl = lt*LTX + lls;
        size_t o = (size_t)(gl >> 2)*64 + s*4 + (gl & 3);
        b4 [o] = xdbl[(4 + s)*LTX + lls];
        c4o[o] = xdbl[(20 + s)*LTX + lls];
    }
}

// ---------------- scan: vec4 loads, smem transpose-reduce; grid(DI,K,nz), 256 thr ----------------
__global__ __launch_bounds__(256) void k_scan(const float* __restrict__ A_logs, int mode){
    __shared__ float pA[256], pH[256], hI[256];
    __shared__ float tv[8][544];
    int d = blockIdx.x, k = blockIdx.y, tid = threadIdx.x;
    int slice = map_slice(mode, blockIdx.z);
    int m = (slice == SB) ? 0 : 1;
    int s = tid & 15, c = tid >> 4;
    int w = tid >> 5, g = (tid >> 4) & 1;
    float* tile = &tv[w][g*272];
    float A2 = -__expf(__ldg(&A_logs[((m*KK + k)*DI + d)*SS + s])) * LOG2E;
    const float4* dt4 = (const float4*)(g_dt  + ((size_t)(slice*KK + k)*DI + d)*LL);
    const float4* dx4 = (const float4*)(g_dtx + ((size_t)(slice*KK + k)*DI + d)*LL);
    const float4* b4  = (const float4*)(g_B4 + (size_t)(slice*KK + k)*LL*SS);
    const float4* c4  = (const float4*)(g_C4 + (size_t)(slice*KK + k)*LL*SS);
    int q0 = c*36;
    float ap = 1.f, h = 0.f;
    #pragma unroll 4
    for (int q = 0; q < 36; q++){
        float4 dt = __ldg(&dt4[q0 + q]);
        float4 dx = __ldg(&dx4[q0 + q]);
        float4 bb = __ldg(&b4[(size_t)(q0 + q)*16 + s]);
        float da;
        da = exp2f(A2*dt.x); ap *= da; h = da*h + dx.x*bb.x;
        da = exp2f(A2*dt.y); ap *= da; h = da*h + dx.y*bb.y;
        da = exp2f(A2*dt.z); ap *= da; h = da*h + dx.z*bb.z;
        da = exp2f(A2*dt.w); ap *= da; h = da*h + dx.w*bb.w;
    }
    pA[tid] = ap; pH[tid] = h;
    __syncthreads();
    if (tid < 16){
        float hh = 0.f;
        #pragma unroll
        for (int cc = 0; cc < NCH; cc++){
            hI[cc*16 + tid] = hh;
            hh = pA[cc*16 + tid]*hh + pH[cc*16 + tid];
        }
    }
    __syncthreads();
    h = hI[tid];
    bool fwd = (k < 2);
    float* yrow = g_y + ((size_t)(slice*KK + k)*DI + d)*LL;
    int l0 = c*LCH;
    for (int blk = 0; blk < 9; blk++){
        #pragma unroll
        for (int qq = 0; qq < 4; qq++){
            int q = q0 + blk*4 + qq;
            float4 dt = __ldg(&dt4[q]);
            float4 dx = __ldg(&dx4[q]);
            float4 bb = __ldg(&b4[(size_t)q*16 + s]);
            float4 cc = __ldg(&c4[(size_t)q*16 + s]);
            float da;
            da = exp2f(A2*dt.x); h = da*h + dx.x*bb.x; tile[(qq*4+0)*17 + s] = h*cc.x;
            da = exp2f(A2*dt.y); h = da*h + dx.y*bb.y; tile[(qq*4+1)*17 + s] = h*cc.y;
            da = exp2f(A2*dt.z); h = da*h + dx.z*bb.z; tile[(qq*4+2)*17 + s] = h*cc.z;
            da = exp2f(A2*dt.w); h = da*h + dx.w*bb.w; tile[(qq*4+3)*17 + s] = h*cc.w;
        }
        __syncwarp();
        float sum = 0.f;
        #pragma unroll
        for (int s2 = 0; s2 < 16; s2++) sum += tile[s*17 + s2];
        int l = l0 + blk*16 + s;
        yrow[fwd ? l : (LL-1-l)] = sum;
        __syncwarp();
    }
}

// ---------------- bias merge (frame fb = blockIdx.y + fofs, m=1): grid(72,nf), 256 thr ----------------
__global__ void k_mergeBias(const float* __restrict__ onw, const float* __restrict__ onb,
                            const float* __restrict__ ow,  const float* __restrict__ ob,
                            const float* __restrict__ Dsp, int fofs){
    __shared__ float syy[DI*32];
    __shared__ float sow[CI*DI];
    __shared__ float red0[8*32], red1[8*32];
    __shared__ float ssum[DI], sonw[DI], sonb[DI], sob[CI];
    int tid = threadIdx.x;
    int lsub = tid & 31, dg = tid >> 5;
    int fb = blockIdx.y + fofs, slice = fb;
    int l = blockIdx.x*32 + lsub;
    int tl = (l % 48)*48 + l/48;
    for (int j = tid; j < CI*DI; j += 256) sow[j] = __ldg(&ow[CI*DI + j]);
    if (tid < DI){
        float s = 0.f;
        #pragma unroll
        for (int k = 0; k < KK; k++) s += __ldg(&Dsp[(KK + k)*DI + tid]);
        ssum[tid] = s;
        sonw[tid] = __ldg(&onw[DI + tid]);
        sonb[tid] = __ldg(&onb[DI + tid]);
    }
    if (tid < CI) sob[tid] = __ldg(&ob[CI + tid]);
    __syncthreads();
    float ps = 0.f, pq = 0.f;
    for (int i = 0; i < 16; i++){
        int d = dg*16 + i;
        const float* y0 = g_y + ((size_t)(slice*KK + 0)*DI + d)*LL;
        const float* y1 = g_y + ((size_t)(slice*KK + 1)*DI + d)*LL;
        const float* y2 = g_y + ((size_t)(slice*KK + 2)*DI + d)*LL;
        const float* y3 = g_y + ((size_t)(slice*KK + 3)*DI + d)*LL;
        float v = y0[l] + y2[l] + y1[tl] + y3[tl]
                + ssum[d] * g_xc[((size_t)slice*DI + d)*LL + l];
        syy[d*32 + lsub] = v;
        ps += v; pq += v*v;
    }
    red0[dg*32 + lsub] = ps; red1[dg*32 + lsub] = pq;
    __syncthreads();
    if (dg == 0){
        float s0 = 0.f, s1 = 0.f;
        #pragma unroll
        for (int j = 0; j < 8; j++){ s0 += red0[j*32 + lsub]; s1 += red1[j*32 + lsub]; }
        float mu  = s0 * (1.f/DI);
        float var = s1 * (1.f/DI) - mu*mu;
        red0[lsub] = mu;
        red1[lsub] = rsqrtf(var + 1e-6f);
    }
    __syncthreads();
    float mu = red0[lsub], rs = red1[lsub];
    for (int i = 0; i < 16; i++){
        int d = dg*16 + i;
        float v  = syy[d*32 + lsub];
        float wn = (v - mu)*rs*sonw[d] + sonb[d];
        float z  = g_xz[((size_t)slice*2*DI + DI + d)*LL + l];
        float sz = z / (1.f + __expf(-z));
        syy[d*32 + lsub] = wn * sz;
    }
    __syncthreads();
    float acc[8];
    #pragma unroll
    for (int i = 0; i < 8; i++) acc[i] = sob[dg*8 + i];
    for (int d = 0; d < DI; d++){
        float v = syy[d*32 + lsub];
        #pragma unroll
        for (int i = 0; i < 8; i++) acc[i] += sow[(dg*8 + i)*DI + d] * v;
    }
    #pragma unroll
    for (int i = 0; i < 8; i++)
        g_bias[(fb*CI + dg*8 + i)*LL + l] = acc[i];
}

// ---------------- sequential merge: update + KL + fused in-projection for t+1 ----------------
__global__ __launch_bounds__(256) void k_mergeSeq(
        const float* __restrict__ onw, const float* __restrict__ onb,
        const float* __restrict__ ow,  const float* __restrict__ ob,
        const float* __restrict__ Dsp,
        const float* __restrict__ in_w, const float* __restrict__ in_b,
        int t, int last, float* __restrict__ outp){
    extern __shared__ float sm[];
    float* syy  = sm;              // 4096
    float* sow  = syy + 4096;      // 8192
    float* red0 = sow + 8192;      // 256
    float* red1 = red0 + 256;      // 256
    float* ssum = red1 + 256;      // 128
    float* sonw = ssum + 128;      // 128
    float* sonb = sonw + 128;      // 128
    float* sob  = sonb + 128;      // 64
    float* skl  = sob + 64;        // 2048
    float* swT  = skl + 2048;      // 64*260
    float* sbin = swT + 64*260;    // 256
    const int slice = SB;
    int tid = threadIdx.x;
    int lsub = tid & 31, dg = tid >> 5;
    int l = blockIdx.x*32 + lsub;
    int tl = (l % 48)*48 + l/48;
    for (int j = tid; j < CI*DI; j += 256) sow[j] = __ldg(&ow[j]);
    if (tid < DI){
        float s = 0.f;
        #pragma unroll
        for (int k = 0; k < KK; k++) s += __ldg(&Dsp[k*DI + tid]);
        ssum[tid] = s;
        sonw[tid] = __ldg(&onw[tid]);
        sonb[tid] = __ldg(&onb[tid]);
    }
    if (tid < CI) sob[tid] = __ldg(&ob[tid]);
    if (!last){
        for (int j = tid; j < 256*64; j += 256){
            int row = j >> 6, c = j & 63;
            swT[c*260 + row] = __ldg(&in_w[row*64 + c]);
        }
        sbin[tid] = __ldg(&in_b[tid]);
    }
    __syncthreads();
    float ps = 0.f, pq = 0.f;
    for (int i = 0; i < 16; i++){
        int d = dg*16 + i;
        const float* y0 = g_y + ((size_t)(slice*KK + 0)*DI + d)*LL;
        const float* y1 = g_y + ((size_t)(slice*KK + 1)*DI + d)*LL;
        const float* y2 = g_y + ((size_t)(slice*KK + 2)*DI + d)*LL;
        const float* y3 = g_y + ((size_t)(slice*KK + 3)*DI + d)*LL;
        float v = y0[l] + y2[l] + y1[tl] + y3[tl]
                + ssum[d] * g_xc[((size_t)slice*DI + d)*LL + l];
        syy[d*32 + lsub] = v;
        ps += v; pq += v*v;
    }
    red0[dg*32 + lsub] = ps; red1[dg*32 + lsub] = pq;
    __syncthreads();
    if (dg == 0){
        float s0 = 0.f, s1 = 0.f;
        #pragma unroll
        for (int j = 0; j < 8; j++){ s0 += red0[j*32 + lsub]; s1 += red1[j*32 + lsub]; }
        float mu  = s0 * (1.f/DI);
        float var = s1 * (1.f/DI) - mu*mu;
        red0[lsub] = mu;
        red1[lsub] = rsqrtf(var + 1e-6f);
    }
    __syncthreads();
    float mu = red0[lsub], rs = red1[lsub];
    for (int i = 0; i < 16; i++){
        int d = dg*16 + i;
        float v  = syy[d*32 + lsub];
        float wn = (v - mu)*rs*sonw[d] + sonb[d];
        float z  = g_xz[((size_t)slice*2*DI + DI + d)*LL + l];
        float sz = z / (1.f + __expf(-z));
        syy[d*32 + lsub] = wn * sz;
    }
    __syncthreads();
    float acc[8];
    #pragma unroll
    for (int i = 0; i < 8; i++) acc[i] = sob[dg*8 + i];
    for (int d = 0; d < DI; d++){
        float v = syy[d*32 + lsub];
        #pragma unroll
        for (int i = 0; i < 8; i++) acc[i] += sow[(dg*8 + i)*DI + d] * v;
    }
    float co[8], nv[8];
    #pragma unroll
    for (int i = 0; i < 8; i++){
        int cc = dg*8 + i;
        int idx = cc*LL + l;
        co[i] = g_cur[idx];
        g_prev[idx] = co[i];
        nv[i] = co[i] * __expf(acc[i]) + g_bias[(t*CI + cc)*LL + l];
        g_cur[idx] = nv[i];
    }
    if (last){
        #pragma unroll
        for (int i = 0; i < 8; i++) outp[(dg*8 + i)*LL + l] = nv[i];
        return;
    }
    __syncthreads();
    #pragma unroll
    for (int i = 0; i < 8; i++){
        int cc = dg*8 + i;
        syy[cc*32 + lsub]        = co[i];
        syy[2048 + cc*32 + lsub] = nv[i];
    }
    __syncthreads();
    if (tid < 32){
        float mp = -1e30f, mq = -1e30f;
        for (int cc = 0; cc < CI; cc++){
            mp = fmaxf(mp, syy[cc*32 + tid]);
            mq = fmaxf(mq, syy[2048 + cc*32 + tid]);
        }
        float ep = 0.f, eq = 0.f;
        for (int cc = 0; cc < CI; cc++){
            ep += __expf(syy[cc*32 + tid] - mp);
            eq += __expf(syy[2048 + cc*32 + tid] - mq);
        }
        red0[tid] = mp + __logf(ep);
        red1[tid] = mq + __logf(eq);
    }
    __syncthreads();
    float lsep = red0[lsub], lseq = red1[lsub];
    #pragma unroll
    for (int i = 0; i < 8; i++){
        int cc = dg*8 + i;
        float lp = syy[cc*32 + lsub] - lsep;
        float lq = syy[2048 + cc*32 + lsub] - lseq;
        skl[cc*32 + lsub] = __expf(lp)*(lp - lq);
    }
    __syncthreads();
    int rowq = tid >> 2, pixq = tid & 3;
    float a2[4][8];
    #pragma unroll
    for (int i = 0; i < 4; i++){
        float bb = sbin[rowq*4 + i];
        #pragma unroll
        for (int p = 0; p < 8; p++) a2[i][p] = bb;
    }
    #pragma unroll 2
    for (int c4 = 0; c4 < 16; c4++){
        float4 w0 = *(const float4*)&swT[(c4*4+0)*260 + rowq*4];
        float4 w1 = *(const float4*)&swT[(c4*4+1)*260 + rowq*4];
        float4 w2 = *(const float4*)&swT[(c4*4+2)*260 + rowq*4];
        float4 w3 = *(const float4*)&swT[(c4*4+3)*260 + rowq*4];
        float k0[8], k1[8], k2[8], k3[8];
        *(float4*)&k0[0] = *(const float4*)&skl[(c4*4+0)*32 + pixq*8];
        *(float4*)&k0[4] = *(const float4*)&skl[(c4*4+0)*32 + pixq*8 + 4];
        *(float4*)&k1[0] = *(const float4*)&skl[(c4*4+1)*32 + pixq*8];
        *(float4*)&k1[4] = *(const float4*)&skl[(c4*4+1)*32 + pixq*8 + 4];
        *(float4*)&k2[0] = *(const float4*)&skl[(c4*4+2)*32 + pixq*8];
        *(float4*)&k2[4] = *(const float4*)&skl[(c4*4+2)*32 + pixq*8 + 4];
        *(float4*)&k3[0] = *(const float4*)&skl[(c4*4+3)*32 + pixq*8];
        *(float4*)&k3[4] = *(const float4*)&skl[(c4*4+3)*32 + pixq*8 + 4];
        float wr0[4] = {w0.x, w0.y, w0.z, w0.w};
        float wr1[4] = {w1.x, w1.y, w1.z, w1.w};
        float wr2[4] = {w2.x, w2.y, w2.z, w2.w};
        float wr3[4] = {w3.x, w3.y, w3.z, w3.w};
        #pragma unroll
        for (int i = 0; i < 4; i++)
            #pragma unroll
            for (int p = 0; p < 8; p++)
                a2[i][p] += wr0[i]*k0[p] + wr1[i]*k1[p] + wr2[i]*k2[p] + wr3[i]*k3[p];
    }
    #pragma unroll
    for (int i = 0; i < 4; i++){
        int r = rowq*4 + i;
        float* o = g_xz + ((size_t)SB*2*DI + r)*LL + blockIdx.x*32 + pixq*8;
        *(float4*)&o[0] = make_float4(a2[i][0], a2[i][1], a2[i][2], a2[i][3]);
        *(float4*)&o[4] = make_float4(a2[i][4], a2[i][5], a2[i][6], a2[i][7]);
    }
}

// ---------------- launch ----------------
extern "C" void kernel_launch(void* const* d_in, const int* in_sizes, int n_in,
                              void* d_out, int out_size){
    const float* img    = (const float*)d_in[0];
    const float* dz     = (const float*)d_in[1];
    const float* sigma  = (const float*)d_in[2];
    const float* in_w   = (const float*)d_in[3];
    const float* in_b   = (const float*)d_in[4];
    const float* conv_w = (const float*)d_in[5];
    const float* conv_b = (const float*)d_in[6];
    const float* xp_w   = (const float*)d_in[7];
    const float* dt_w   = (const float*)d_in[8];
    const float* dt_b   = (const float*)d_in[9];
    const float* A_logs = (const float*)d_in[10];
    const float* Ds     = (const float*)d_in[11];
    const float* onw    = (const float*)d_in[12];
    const float* onb    = (const float*)d_in[13];
    const float* ow     = (const float*)d_in[14];
    const float* ob     = (const float*)d_in[15];
    const float* niw    = (const float*)d_in[16];
    const float* nib    = (const float*)d_in[17];
    const float* ndw    = (const float*)d_in[18];
    const float* ndb    = (const float*)d_in[19];
    float* outp = (float*)d_out;

    cudaFuncSetAttribute(k_xproj, cudaFuncAttributeMaxDynamicSharedMemorySize, XP_SMEM);
    cudaFuncSetAttribute(k_mergeSeq, cudaFuncAttributeMaxDynamicSharedMemorySize, MS_SMEM);

    // fork/join stream for frames 1..3 (fallback: same stream, same-stream order stays correct)
    cudaStream_t s2 = 0;
    cudaEvent_t evF = 0, evJ = 0;
    bool fork = (cudaStreamCreateWithFlags(&s2, cudaStreamNonBlocking) == cudaSuccess);
    if (fork) fork = (cudaEventCreateWithFlags(&evF, cudaEventDisableTiming) == cudaSuccess);
    if (fork) fork = (cudaEventCreateWithFlags(&evJ, cudaEventDisableTiming) == cudaSuccess);
    cudaStream_t sb = fork ? s2 : (cudaStream_t)0;

    k_init<<<dim3(72,5,1), 128>>>(dz, sigma, img, niw, nib, ndw, ndb);

    if (fork){
        cudaEventRecord(evF, 0);
        cudaStreamWaitEvent(s2, evF, 0);
    }

    // critical first wave: {slice4 (t=0 seq), frame 0} (mode 0, nz=2)
    k_inproj<<<dim3(18,8,2), 128>>>(in_w, in_b, 0);
    k_conv  <<<dim3(DI,2,1), 256>>>(conv_w, conv_b, 0);
    k_xproj <<<dim3(48,KK,2), 192, XP_SMEM>>>(xp_w, dt_w, dt_b, 0);
    k_scan  <<<dim3(DI,KK,2), 256>>>(A_logs, 0);
    k_mergeBias<<<dim3(72,1,1), 256>>>(onw, onb, ow, ob, Ds, 0);
    k_mergeSeq <<<dim3(72,1,1), 256, MS_SMEM>>>(onw, onb, ow, ob, Ds, in_w, in_b,
                                                0, 0, nullptr);

    // frame stream: frames 1..3 (mode 1, nz=3)
    k_inproj<<<dim3(18,8,3), 128, 0, sb>>>(in_w, in_b, 1);
    k_conv  <<<dim3(DI,3,1), 256, 0, sb>>>(conv_w, conv_b, 1);
    k_xproj <<<dim3(48,KK,3), 192, XP_SMEM, sb>>>(xp_w, dt_w, dt_b, 1);
    k_scan  <<<dim3(DI,KK,3), 256, 0, sb>>>(A_logs, 1);
    k_mergeBias<<<dim3(72,3,1), 256, 0, sb>>>(onw, onb, ow, ob, Ds, 1);
    if (fork) cudaEventRecord(evJ, s2);

    // t = 1..3 (mode 2)
    for (int t = 1; t < TT; t++){
        k_conv  <<<dim3(DI,1,1), 256>>>(conv_w, conv_b, 2);
        k_xproj <<<dim3(48,KK,1), 192, XP_SMEM>>>(xp_w, dt_w, dt_b, 2);
        k_scan  <<<dim3(DI,KK,1), 256>>>(A_logs, 2);
        if (fork && t == 1) cudaStreamWaitEvent((cudaStream_t)0, evJ, 0);
        k_mergeSeq<<<dim3(72,1,1), 256, MS_SMEM>>>(onw, onb, ow, ob, Ds, in_w, in_b,
                                                   t, (t == TT-1) ? 1 : 0,
                                                   (t == TT-1) ? outp : nullptr);
    }
}

// round 12
// speedup vs baseline: 1.6471x; 1.0650x over previous
#include <cuda_runtime.h>

#define CI 64
#define DI 128
#define SS 16
#define RR 4
#define KK 4
#define HH 48
#define WW 48
#define LL 2304
#define TT 4
#define NB 5          // slices: 0..3 = bias frames, 4 = sequential pipeline
#define SB 4
#define NCH 16
#define LCH 144
#define LOG2E 1.4426950408889634f
#define LTX 48        // xproj l-tile
#define XP_SMEM ((DI*LTX + 36*DI + DI*RR + DI)*4)
// mergeSeq v2 smem: syy 2048 | union 16640 (sowT 128*65 / swT 64*260) | red 512 |
//                   ssum/sonw/sonb 384 | sob 64 | skl 1024 | sbin 256
#define MS_SMEM ((2048 + 16640 + 256 + 256 + 128 + 128 + 128 + 64 + 1024 + 256)*4)

// mode: 0 = critical first wave {z0: slice4(seq), z1: slice0(frame0)}
//       1 = frame stream {z: slice z+1}
//       2 = sequential {slice 4}
__device__ __forceinline__ int map_slice(int mode, int z){
    return (mode == 0) ? (z == 0 ? 4 : 0) : ((mode == 1) ? z + 1 : 4);
}

// ---------------- scratch (static device globals; no allocations) ----------------
__device__ float g_prev[CI*LL];
__device__ float g_cur [CI*LL];
__device__ float g_kl  [CI*LL];
__device__ float g_xln [TT*CI*LL];
__device__ float g_bias[TT*CI*LL];
__device__ float g_xz  [NB*2*DI*LL];
__device__ float g_xc  [NB*DI*LL];
__device__ float g_xcT [NB*DI*LL];
__device__ float g_dt  [NB*KK*DI*LL];
__device__ float g_dtx [NB*KK*DI*LL];
__device__ float g_B4  [NB*KK*LL*SS];   // [(slice,k)][l/4][s][4]
__device__ float g_C4  [NB*KK*LL*SS];
__device__ float g_y   [NB*KK*DI*LL];

// ---------------- init: y=0: prev/cur/kl(t0); y=1..4: xln[t]; grid(72,5), 128 thr ----------------
__global__ void k_init(const float* __restrict__ dz, const float* __restrict__ sigma,
                       const float* __restrict__ img,
                       const float* __restrict__ niw, const float* __restrict__ nib,
                       const float* __restrict__ ndw, const float* __restrict__ ndb){
    __shared__ float sx[CI*33];
    __shared__ float scur[CI*33];
    __shared__ float smu[32], srs[32], slp[32], slq[32];
    int l0 = blockIdx.x*32, tid = threadIdx.x;
    if (blockIdx.y == 0){
        for (int j = tid; j < CI*32; j += 128){
            int c = j >> 5, li = j & 31;
            sx[c*33 + li] = dz[c*LL + l0 + li];
        }
        __syncthreads();
        if (tid < 32){
            float s0 = 0.f, s1 = 0.f;
            for (int c = 0; c < CI; c++){ float v = sx[c*33 + tid]; s0 += v; s1 += v*v; }
            float mu = s0*(1.f/CI);
            smu[tid] = mu;
            srs[tid] = rsqrtf(s1*(1.f/CI) - mu*mu + 1e-6f);
        }
        __syncthreads();
        for (int j = tid; j < CI*32; j += 128){
            int c = j >> 5, li = j & 31;
            float pv = (sx[c*33+li] - smu[li])*srs[li]*ndw[c] + ndb[c];
            float cv = pv * __expf(sigma[c*LL + l0 + li]);
            g_prev[c*LL + l0 + li] = pv;
            g_cur [c*LL + l0 + li] = cv;
            sx  [c*33 + li] = pv;
            scur[c*33 + li] = cv;
        }
        __syncthreads();
        if (tid < 32){
            float mp = -1e30f, mq = -1e30f;
            for (int c = 0; c < CI; c++){
                mp = fmaxf(mp, sx  [c*33 + tid]);
                mq = fmaxf(mq, scur[c*33 + tid]);
            }
            float ep = 0.f, eq = 0.f;
            for (int c = 0; c < CI; c++){
                ep += __expf(sx  [c*33 + tid] - mp);
                eq += __expf(scur[c*33 + tid] - mq);
            }
            slp[tid] = mp + __logf(ep);
            slq[tid] = mq + __logf(eq);
        }
        __syncthreads();
        for (int j = tid; j < CI*32; j += 128){
            int c = j >> 5, li = j & 31;
            float lp = sx  [c*33+li] - slp[li];
            float lq = scur[c*33+li] - slq[li];
            g_kl[c*LL + l0 + li] = __expf(lp)*(lp - lq);
        }
    } else {
        int t = blockIdx.y - 1;
        for (int j = tid; j < CI*32; j += 128){
            int c = j >> 5, li = j & 31;
            sx[c*33 + li] = img[(t*CI + c)*LL + l0 + li];
        }
        __syncthreads();
        if (tid < 32){
            float s0 = 0.f, s1 = 0.f;
            for (int c = 0; c < CI; c++){ float v = sx[c*33 + tid]; s0 += v; s1 += v*v; }
            float mu = s0*(1.f/CI);
            smu[tid] = mu;
            srs[tid] = rsqrtf(s1*(1.f/CI) - mu*mu + 1e-6f);
        }
        __syncthreads();
        for (int j = tid; j < CI*32; j += 128){
            int c = j >> 5, li = j & 31;
            g_xln[(t*CI + c)*LL + l0 + li] = (sx[c*33+li] - smu[li])*srs[li]*niw[c] + nib[c];
        }
    }
}

// ---------------- in-projection GEMM; grid(18,8,nz), 128 thr ----------------
__global__ void k_inproj(const float* __restrict__ in_w, const float* __restrict__ in_b,
                         int mode){
    __shared__ float sx[64*128];
    __shared__ float swT[64*33];
    const int lt = blockIdx.x, dtile = blockIdx.y, tid = threadIdx.x;
    const int slice = map_slice(mode, blockIdx.z);
    const int m = (slice == SB) ? 0 : 1;
    const float* src = ((slice == SB) ? g_kl : (g_xln + slice*CI*LL)) + lt*128;
    for (int j = tid; j < 64*128; j += 128){
        int c = j >> 7;
        sx[j] = src[c*LL + tid];
    }
    for (int j = tid; j < 32*64; j += 128){
        int dp = j >> 6, c = j & 63;
        swT[c*33 + dp] = __ldg(&in_w[(m*256 + dtile*32 + dp)*64 + c]);
    }
    __syncthreads();
    int lq = tid & 31, dq = tid >> 5;
    float acc[8][4];
    #pragma unroll
    for (int i = 0; i < 8; i++){
        float bb = __ldg(&in_b[m*256 + dtile*32 + dq*8 + i]);
        #pragma unroll
        for (int j = 0; j < 4; j++) acc[i][j] = bb;
    }
    #pragma unroll 4
    for (int c = 0; c < 64; c++){
        float4 xv = *(const float4*)&sx[c*128 + lq*4];
        float xa[4] = {xv.x, xv.y, xv.z, xv.w};
        float wv[8];
        #pragma unroll
        for (int i = 0; i < 8; i++) wv[i] = swT[c*33 + dq*8 + i];
        #pragma unroll
        for (int i = 0; i < 8; i++)
            #pragma unroll
            for (int j = 0; j < 4; j++) acc[i][j] += wv[i]*xa[j];
    }
    #pragma unroll
    for (int i = 0; i < 8; i++){
        int d = dtile*32 + dq*8 + i;
        float* o = g_xz + ((size_t)slice*2*DI + d)*LL + lt*128 + lq*4;
        *(float4*)o = make_float4(acc[i][0], acc[i][1], acc[i][2], acc[i][3]);
    }
}

// ---------------- depthwise 3x3 conv v2 (half-plane blocks); grid(DI, 2*nz), 256 thr ----------------
__global__ void k_conv(const float* __restrict__ cw, const float* __restrict__ cb, int mode){
    __shared__ float sin[26*48];
    __shared__ float sc[24*49];
    int d = blockIdx.x, tid = threadIdx.x;
    int zz = blockIdx.y >> 1, half = blockIdx.y & 1;
    int slice = map_slice(mode, zz);
    int m = (slice == SB) ? 0 : 1;
    int h0 = half*24;
    const float* in = g_xz + ((size_t)slice*2*DI + d)*LL;
    for (int j = tid; j < 26*48; j += 256){
        int r = j/48, c = j%48;
        int gr = h0 - 1 + r;
        sin[j] = (gr >= 0 && gr < 48) ? in[gr*48 + c] : 0.f;
    }
    float w9[9];
    #pragma unroll
    for (int j = 0; j < 9; j++) w9[j] = __ldg(&cw[(m*DI + d)*9 + j]);
    float bias = __ldg(&cb[m*DI + d]);
    __syncthreads();
    for (int j = tid; j < 24*48; j += 256){
        int hh = j/48, w = j%48;
        float acc = 0.f;
        #pragma unroll
        for (int ky = 0; ky < 3; ky++){
            #pragma unroll
            for (int kx = 0; kx < 3; kx++){
                int wx = w + kx - 1;
                if (wx < 0 || wx >= 48) continue;
                acc += w9[ky*3+kx] * sin[(hh+ky)*48 + wx];
            }
        }
        acc += bias;
        acc = acc / (1.f + __expf(-acc));
        sc[hh*49 + w] = acc;
    }
    __syncthreads();
    float* oc = g_xc  + ((size_t)slice*DI + d)*LL;
    float* ot = g_xcT + ((size_t)slice*DI + d)*LL;
    for (int j = tid; j < 24*48; j += 256){
        int hh = j/48, w = j%48;
        oc[(h0+hh)*48 + w] = sc[hh*49 + w];
    }
    for (int j = tid; j < 48*24; j += 256){
        int w = j/24, hh = j%24;
        ot[w*48 + h0 + hh] = sc[hh*49 + w];
    }
}

// ---------------- x-projection: LTX=48 register-tiled GEMM; grid(48,K,nz), 192 thr ----------
__global__ __launch_bounds__(192) void k_xproj(const float* __restrict__ xpw,
                                               const float* __restrict__ dtw,
                                               const float* __restrict__ dtb,
                                               int mode){
    extern __shared__ float sm[];
    float* s1  = sm;                     // [DI][48] x-tile
    float* s2  = sm + DI*LTX;            // weights [36][DI] -> xdbl[36][48]
    float* sdw = s2 + 36*DI;
    float* sdb = sdw + DI*RR;
    int lt = blockIdx.x, k = blockIdx.y, tid = threadIdx.x;
    int slice = map_slice(mode, blockIdx.z);
    int m = (slice == SB) ? 0 : 1;
    const float* wk = xpw + (m*KK + k)*36*DI;
    for (int j = tid; j < 36*DI; j += 192) s2[j] = __ldg(&wk[j]);
    const float* dwk = dtw + (m*KK + k)*DI*RR;
    for (int j = tid; j < DI*RR; j += 192) sdw[j] = __ldg(&dwk[j]);
    if (tid < DI) sdb[tid] = __ldg(&dtb[(m*KK + k)*DI + tid]);
    bool fwd = (k < 2);
    const float* src = ((k & 1) ? g_xcT : g_xc) + (size_t)slice*DI*LL;
    for (int j = tid; j < DI*LTX; j += 192){
        int d = j/LTX, ls = j%LTX;
        int gl = fwd ? (lt*LTX + ls) : (LL-1 - (lt*LTX + ls));
        s1[j] = src[d*LL + gl];
    }
    __syncthreads();
    int lq = tid % 48, rg = tid / 48;
    const float4* w4 = (const float4*)s2;
    float acc[9];
    #pragma unroll
    for (int i = 0; i < 9; i++) acc[i] = 0.f;
    #pragma unroll 4
    for (int c4 = 0; c4 < 32; c4++){
        float4 w[9];
        #pragma unroll
        for (int i = 0; i < 9; i++) w[i] = w4[(rg*9 + i)*32 + c4];
        float x0 = s1[(c4*4 + 0)*LTX + lq];
        float x1 = s1[(c4*4 + 1)*LTX + lq];
        float x2 = s1[(c4*4 + 2)*LTX + lq];
        float x3 = s1[(c4*4 + 3)*LTX + lq];
        #pragma unroll
        for (int i = 0; i < 9; i++)
            acc[i] += w[i].x*x0 + w[i].y*x1 + w[i].z*x2 + w[i].w*x3;
    }
    __syncthreads();
    float* xdbl = s2;
    #pragma unroll
    for (int i = 0; i < 9; i++) xdbl[(rg*9 + i)*LTX + lq] = acc[i];
    __syncthreads();
    int ls2 = tid % LTX, rg2 = tid / LTX;
    float* dto  = g_dt  + ((size_t)(slice*KK + k)*DI)*LL + lt*LTX;
    float* dtxo = g_dtx + ((size_t)(slice*KK + k)*DI)*LL + lt*LTX;
    float xr0 = xdbl[0*LTX + ls2], xr1 = xdbl[1*LTX + ls2];
    float xr2 = xdbl[2*LTX + ls2], xr3 = xdbl[3*LTX + ls2];
    #pragma unroll 4
    for (int i = 0; i < 32; i++){
        int d = rg2 + 4*i;
        float v = sdb[d] + sdw[d*4+0]*xr0 + sdw[d*4+1]*xr1 + sdw[d*4+2]*xr2 + sdw[d*4+3]*xr3;
        v = fmaxf(v, 0.f) + log1pf(__expf(-fabsf(v)));
        dto [d*LL + ls2] = v;
        dtxo[d*LL + ls2] = v * s1[d*LTX + ls2];
    }
    float* b4 = g_B4 + (size_t)(slice*KK + k)*LL*SS;
    float* c4o = g_C4 + (size_t)(slice*KK + k)*LL*SS;
    for (int j = tid; j < LTX*SS; j += 192){
        int lls = j/SS, s = j%SS;
        int gl = lt*LTX + lls;
        size_t o = (size_t)(gl >> 2)*64 + s*4 + (gl & 3);
        b4 [o] = xdbl[(4 + s)*LTX + lls];
        c4o[o] = xdbl[(20 + s)*LTX + lls];
    }
}

// ---------------- scan: vec4 loads, smem transpose-reduce; grid(DI,K,nz), 256 thr ----------------
__global__ __launch_bounds__(256) void k_scan(const float* __restrict__ A_logs, int mode){
    __shared__ float pA[256], pH[256], hI[256];
    __shared__ float tv[8][544];
    int d = blockIdx.x, k = blockIdx.y, tid = threadIdx.x;
    int slice = map_slice(mode, blockIdx.z);
    int m = (slice == SB) ? 0 : 1;
    int s = tid & 15, c = tid >> 4;
    int w = tid >> 5, g = (tid >> 4) & 1;
    float* tile = &tv[w][g*272];
    float A2 = -__expf(__ldg(&A_logs[((m*KK + k)*DI + d)*SS + s])) * LOG2E;
    const float4* dt4 = (const float4*)(g_dt  + ((size_t)(slice*KK + k)*DI + d)*LL);
    const float4* dx4 = (const float4*)(g_dtx + ((size_t)(slice*KK + k)*DI + d)*LL);
    const float4* b4  = (const float4*)(g_B4 + (size_t)(slice*KK + k)*LL*SS);
    const float4* c4  = (const float4*)(g_C4 + (size_t)(slice*KK + k)*LL*SS);
    int q0 = c*36;
    float ap = 1.f, h = 0.f;
    #pragma unroll 4
    for (int q = 0; q < 36; q++){
        float4 dt = __ldg(&dt4[q0 + q]);
        float4 dx = __ldg(&dx4[q0 + q]);
        float4 bb = __ldg(&b4[(size_t)(q0 + q)*16 + s]);
        float da;
        da = exp2f(A2*dt.x); ap *= da; h = da*h + dx.x*bb.x;
        da = exp2f(A2*dt.y); ap *= da; h = da*h + dx.y*bb.y;
        da = exp2f(A2*dt.z); ap *= da; h = da*h + dx.z*bb.z;
        da = exp2f(A2*dt.w); ap *= da; h = da*h + dx.w*bb.w;
    }
    pA[tid] = ap; pH[tid] = h;
    __syncthreads();
    if (tid < 16){
        float hh = 0.f;
        #pragma unroll
        for (int cc = 0; cc < NCH; cc++){
            hI[cc*16 + tid] = hh;
            hh = pA[cc*16 + tid]*hh + pH[cc*16 + tid];
        }
    }
    __syncthreads();
    h = hI[tid];
    bool fwd = (k < 2);
    float* yrow = g_y + ((size_t)(slice*KK + k)*DI + d)*LL;
    int l0 = c*LCH;
    for (int blk = 0; blk < 9; blk++){
        #pragma unroll
        for (int qq = 0; qq < 4; qq++){
            int q = q0 + blk*4 + qq;
            float4 dt = __ldg(&dt4[q]);
            float4 dx = __ldg(&dx4[q]);
            float4 bb = __ldg(&b4[(size_t)q*16 + s]);
            float4 cc = __ldg(&c4[(size_t)q*16 + s]);
            float da;
            da = exp2f(A2*dt.x); h = da*h + dx.x*bb.x; tile[(qq*4+0)*17 + s] = h*cc.x;
            da = exp2f(A2*dt.y); h = da*h + dx.y*bb.y; tile[(qq*4+1)*17 + s] = h*cc.y;
            da = exp2f(A2*dt.z); h = da*h + dx.z*bb.z; tile[(qq*4+2)*17 + s] = h*cc.z;
            da = exp2f(A2*dt.w); h = da*h + dx.w*bb.w; tile[(qq*4+3)*17 + s] = h*cc.w;
        }
        __syncwarp();
        float sum = 0.f;
        #pragma unroll
        for (int s2 = 0; s2 < 16; s2++) sum += tile[s*17 + s2];
        int l = l0 + blk*16 + s;
        yrow[fwd ? l : (LL-1-l)] = sum;
        __syncwarp();
    }
}

// ---------------- bias merge (frame fb = blockIdx.y + fofs, m=1): grid(72,nf), 256 thr ----------------
__global__ void k_mergeBias(const float* __restrict__ onw, const float* __restrict__ onb,
                            const float* __restrict__ ow,  const float* __restrict__ ob,
                            const float* __restrict__ Dsp, int fofs){
    __shared__ float syy[DI*32];
    __shared__ float sow[CI*DI];
    __shared__ float red0[8*32], red1[8*32];
    __shared__ float ssum[DI], sonw[DI], sonb[DI], sob[CI];
    int tid = threadIdx.x;
    int lsub = tid & 31, dg = tid >> 5;
    int fb = blockIdx.y + fofs, slice = fb;
    int l = blockIdx.x*32 + lsub;
    int tl = (l % 48)*48 + l/48;
    for (int j = tid; j < CI*DI; j += 256) sow[j] = __ldg(&ow[CI*DI + j]);
    if (tid < DI){
        float s = 0.f;
        #pragma unroll
        for (int k = 0; k < KK; k++) s += __ldg(&Dsp[(KK + k)*DI + tid]);
        ssum[tid] = s;
        sonw[tid] = __ldg(&onw[DI + tid]);
        sonb[tid] = __ldg(&onb[DI + tid]);
    }
    if (tid < CI) sob[tid] = __ldg(&ob[CI + tid]);
    __syncthreads();
    float ps = 0.f, pq = 0.f;
    for (int i = 0; i < 16; i++){
        int d = dg*16 + i;
        const float* y0 = g_y + ((size_t)(slice*KK + 0)*DI + d)*LL;
        const float* y1 = g_y + ((size_t)(slice*KK + 1)*DI + d)*LL;
        const float* y2 = g_y + ((size_t)(slice*KK + 2)*DI + d)*LL;
        const float* y3 = g_y + ((size_t)(slice*KK + 3)*DI + d)*LL;
        float v = y0[l] + y2[l] + y1[tl] + y3[tl]
                + ssum[d] * g_xc[((size_t)slice*DI + d)*LL + l];
        syy[d*32 + lsub] = v;
        ps += v; pq += v*v;
    }
    red0[dg*32 + lsub] = ps; red1[dg*32 + lsub] = pq;
    __syncthreads();
    if (dg == 0){
        float s0 = 0.f, s1 = 0.f;
        #pragma unroll
        for (int j = 0; j < 8; j++){ s0 += red0[j*32 + lsub]; s1 += red1[j*32 + lsub]; }
        float mu  = s0 * (1.f/DI);
        float var = s1 * (1.f/DI) - mu*mu;
        red0[lsub] = mu;
        red1[lsub] = rsqrtf(var + 1e-6f);
    }
    __syncthreads();
    float mu = red0[lsub], rs = red1[lsub];
    for (int i = 0; i < 16; i++){
        int d = dg*16 + i;
        float v  = syy[d*32 + lsub];
        float wn = (v - mu)*rs*sonw[d] + sonb[d];
        float z  = g_xz[((size_t)slice*2*DI + DI + d)*LL + l];
        float sz = z / (1.f + __expf(-z));
        syy[d*32 + lsub] = wn * sz;
    }
    __syncthreads();
    float acc[8];
    #pragma unroll
    for (int i = 0; i < 8; i++) acc[i] = sob[dg*8 + i];
    for (int d = 0; d < DI; d++){
        float v = syy[d*32 + lsub];
        #pragma unroll
        for (int i = 0; i < 8; i++) acc[i] += sow[(dg*8 + i)*DI + d] * v;
    }
    #pragma unroll
    for (int i = 0; i < 8; i++)
        g_bias[(fb*CI + dg*8 + i)*LL + l] = acc[i];
}

// ---------------- sequential merge v2 (16-pixel blocks, smem union): grid(144), 256 thr ----------
__global__ __launch_bounds__(256) void k_mergeSeq(
        const float* __restrict__ onw, const float* __restrict__ onb,
        const float* __restrict__ ow,  const float* __restrict__ ob,
        const float* __restrict__ Dsp,
        const float* __restrict__ in_w, const float* __restrict__ in_b,
        int t, int last, float* __restrict__ outp){
    extern __shared__ float sm[];
    float* syy  = sm;              // 2048 (DI*16)
    float* un   = syy + 2048;      // 16640: sowT[128*65] then swT[64*260]
    float* red0 = un + 16640;      // 256
    float* red1 = red0 + 256;      // 256
    float* ssum = red1 + 256;      // 128
    float* sonw = ssum + 128;      // 128
    float* sonb = sonw + 128;      // 128
    float* sob  = sonb + 128;      // 64
    float* skl  = sob + 64;        // 1024 (CI*16)
    float* sbin = skl + 1024;      // 256
    const int slice = SB;
    int tid = threadIdx.x;
    int lsub = tid & 15, dg = tid >> 4;     // 16 px x 16 groups
    int l = blockIdx.x*16 + lsub;
    int tl = (l % 48)*48 + l/48;
    // stage params; sowT transposed with pad 65 (conflict-free reads)
    for (int j = tid; j < CI*DI; j += 256){
        int row = j >> 7, d = j & 127;      // ow[row*DI + d], coalesced read
        un[d*65 + row] = __ldg(&ow[j]);
    }
    if (tid < DI){
        float s = 0.f;
        #pragma unroll
        for (int k = 0; k < KK; k++) s += __ldg(&Dsp[k*DI + tid]);
        ssum[tid] = s;
        sonw[tid] = __ldg(&onw[tid]);
        sonb[tid] = __ldg(&onb[tid]);
    }
    if (tid < CI) sob[tid] = __ldg(&ob[tid]);
    if (!last) sbin[tid] = __ldg(&in_b[tid]);
    __syncthreads();
    // direction merge + LN stats
    float ps = 0.f, pq = 0.f;
    #pragma unroll
    for (int i = 0; i < 8; i++){
        int d = dg*8 + i;
        const float* y0 = g_y + ((size_t)(slice*KK + 0)*DI + d)*LL;
        const float* y1 = g_y + ((size_t)(slice*KK + 1)*DI + d)*LL;
        const float* y2 = g_y + ((size_t)(slice*KK + 2)*DI + d)*LL;
        const float* y3 = g_y + ((size_t)(slice*KK + 3)*DI + d)*LL;
        float v = y0[l] + y2[l] + y1[tl] + y3[tl]
                + ssum[d] * g_xc[((size_t)slice*DI + d)*LL + l];
        syy[d*16 + lsub] = v;
        ps += v; pq += v*v;
    }
    red0[dg*16 + lsub] = ps; red1[dg*16 + lsub] = pq;
    __syncthreads();
    if (tid < 16){
        float s0 = 0.f, s1 = 0.f;
        #pragma unroll
        for (int j = 0; j < 16; j++){ s0 += red0[j*16 + tid]; s1 += red1[j*16 + tid]; }
        float mu  = s0 * (1.f/DI);
        float var = s1 * (1.f/DI) - mu*mu;
        red0[tid] = mu;
        red1[tid] = rsqrtf(var + 1e-6f);
    }
    __syncthreads();
    float mu = red0[lsub], rs = red1[lsub];
    #pragma unroll
    for (int i = 0; i < 8; i++){
        int d = dg*8 + i;
        float v  = syy[d*16 + lsub];
        float wn = (v - mu)*rs*sonw[d] + sonb[d];
        float z  = g_xz[((size_t)slice*2*DI + DI + d)*LL + l];
        float sz = z / (1.f + __expf(-z));
        syy[d*16 + lsub] = wn * sz;
    }
    __syncthreads();
    // out-projection: thread = 4 rows (cg*4+i) x 1 px (lsub)
    int cg = dg;
    float acc[4];
    #pragma unroll
    for (int i = 0; i < 4; i++) acc[i] = sob[cg*4 + i];
    for (int d = 0; d < DI; d++){
        float v = syy[d*16 + lsub];
        #pragma unroll
        for (int i = 0; i < 4; i++) acc[i] += un[d*65 + cg*4 + i] * v;
    }
    // recurrent update
    float co[4], nv[4];
    #pragma unroll
    for (int i = 0; i < 4; i++){
        int cc = cg*4 + i;
        int idx = cc*LL + l;
        co[i] = g_cur[idx];
        g_prev[idx] = co[i];
        nv[i] = co[i] * __expf(acc[i]) + g_bias[(t*CI + cc)*LL + l];
        g_cur[idx] = nv[i];
    }
    if (last){
        #pragma unroll
        for (int i = 0; i < 4; i++) outp[(cg*4 + i)*LL + l] = nv[i];
        return;
    }
    __syncthreads();        // out-proj reads of un/syy complete
    // KL prep (syy) + swT load (un, overwriting sowT)
    #pragma unroll
    for (int i = 0; i < 4; i++){
        int cc = cg*4 + i;
        syy[cc*16 + lsub]        = co[i];
        syy[1024 + cc*16 + lsub] = nv[i];
    }
    for (int j = tid; j < 256*64; j += 256){
        int row = j >> 6, c = j & 63;
        un[c*260 + row] = __ldg(&in_w[row*64 + c]);
    }
    __syncthreads();
    if (tid < 16){
        float mp = -1e30f, mq = -1e30f;
        for (int cc = 0; cc < CI; cc++){
            mp = fmaxf(mp, syy[cc*16 + tid]);
            mq = fmaxf(mq, syy[1024 + cc*16 + tid]);
        }
        float ep = 0.f, eq = 0.f;
        for (int cc = 0; cc < CI; cc++){
            ep += __expf(syy[cc*16 + tid] - mp);
            eq += __expf(syy[1024 + cc*16 + tid] - mq);
        }
        red0[tid] = mp + __logf(ep);
        red1[tid] = mq + __logf(eq);
    }
    __syncthreads();
    float lsep = red0[lsub], lseq = red1[lsub];
    #pragma unroll
    for (int i = 0; i < 4; i++){
        int cc = cg*4 + i;
        float lp = syy[cc*16 + lsub] - lsep;
        float lq = syy[1024 + cc*16 + lsub] - lseq;
        skl[cc*16 + lsub] = __expf(lp)*(lp - lq);
    }
    __syncthreads();
    // fused in-projection for t+1: thread = 1 row (tid) x 16 px
    float a2[16];
    {
        float bb = sbin[tid];
        #pragma unroll
        for (int p = 0; p < 16; p++) a2[p] = bb;
    }
    for (int c = 0; c < 64; c++){
        float wv = un[c*260 + tid];
        float4 k0 = *(const float4*)&skl[c*16 + 0];
        float4 k1 = *(const float4*)&skl[c*16 + 4];
        float4 k2 = *(const float4*)&skl[c*16 + 8];
        float4 k3 = *(const float4*)&skl[c*16 + 12];
        a2[0]  += wv*k0.x; a2[1]  += wv*k0.y; a2[2]  += wv*k0.z; a2[3]  += wv*k0.w;
        a2[4]  += wv*k1.x; a2[5]  += wv*k1.y; a2[6]  += wv*k1.z; a2[7]  += wv*k1.w;
        a2[8]  += wv*k2.x; a2[9]  += wv*k2.y; a2[10] += wv*k2.z; a2[11] += wv*k2.w;
        a2[12] += wv*k3.x; a2[13] += wv*k3.y; a2[14] += wv*k3.z; a2[15] += wv*k3.w;
    }
    float* o = g_xz + ((size_t)SB*2*DI + tid)*LL + blockIdx.x*16;
    #pragma unroll
    for (int p = 0; p < 16; p += 4)
        *(float4*)&o[p] = make_float4(a2[p], a2[p+1], a2[p+2], a2[p+3]);
}

// ---------------- launch ----------------
extern "C" void kernel_launch(void* const* d_in, const int* in_sizes, int n_in,
                              void* d_out, int out_size){
    const float* img    = (const float*)d_in[0];
    const float* dz     = (const float*)d_in[1];
    const float* sigma  = (const float*)d_in[2];
    const float* in_w   = (const float*)d_in[3];
    const float* in_b   = (const float*)d_in[4];
    const float* conv_w = (const float*)d_in[5];
    const float* conv_b = (const float*)d_in[6];
    const float* xp_w   = (const float*)d_in[7];
    const float* dt_w   = (const float*)d_in[8];
    const float* dt_b   = (const float*)d_in[9];
    const float* A_logs = (const float*)d_in[10];
    const float* Ds     = (const float*)d_in[11];
    const float* onw    = (const float*)d_in[12];
    const float* onb    = (const float*)d_in[13];
    const float* ow     = (const float*)d_in[14];
    const float* ob     = (const float*)d_in[15];
    const float* niw    = (const float*)d_in[16];
    const float* nib    = (const float*)d_in[17];
    const float* ndw    = (const float*)d_in[18];
    const float* ndb    = (const float*)d_in[19];
    float* outp = (float*)d_out;

    cudaFuncSetAttribute(k_xproj, cudaFuncAttributeMaxDynamicSharedMemorySize, XP_SMEM);
    cudaFuncSetAttribute(k_mergeSeq, cudaFuncAttributeMaxDynamicSharedMemorySize, MS_SMEM);

    // fork/join stream for frames 1..3 (fallback: same stream, same-stream order stays correct)
    cudaStream_t s2 = 0;
    cudaEvent_t evF = 0, evJ = 0;
    bool fork = (cudaStreamCreateWithFlags(&s2, cudaStreamNonBlocking) == cudaSuccess);
    if (fork) fork = (cudaEventCreateWithFlags(&evF, cudaEventDisableTiming) == cudaSuccess);
    if (fork) fork = (cudaEventCreateWithFlags(&evJ, cudaEventDisableTiming) == cudaSuccess);
    cudaStream_t sb = fork ? s2 : (cudaStream_t)0;

    k_init<<<dim3(72,5,1), 128>>>(dz, sigma, img, niw, nib, ndw, ndb);

    if (fork){
        cudaEventRecord(evF, 0);
        cudaStreamWaitEvent(s2, evF, 0);
    }

    // critical first wave: {slice4 (t=0 seq), frame 0} (mode 0, nz=2)
    k_inproj<<<dim3(18,8,2), 128>>>(in_w, in_b, 0);
    k_conv  <<<dim3(DI,4,1), 256>>>(conv_w, conv_b, 0);
    k_xproj <<<dim3(48,KK,2), 192, XP_SMEM>>>(xp_w, dt_w, dt_b, 0);
    k_scan  <<<dim3(DI,KK,2), 256>>>(A_logs, 0);
    k_mergeBias<<<dim3(72,1,1), 256>>>(onw, onb, ow, ob, Ds, 0);
    k_mergeSeq <<<dim3(144,1,1), 256, MS_SMEM>>>(onw, onb, ow, ob, Ds, in_w, in_b,
                                                 0, 0, nullptr);

    // frame stream: frames 1..3 (mode 1, nz=3)
    k_inproj<<<dim3(18,8,3), 128, 0, sb>>>(in_w, in_b, 1);
    k_conv  <<<dim3(DI,6,1), 256, 0, sb>>>(conv_w, conv_b, 1);
    k_xproj <<<dim3(48,KK,3), 192, XP_SMEM, sb>>>(xp_w, dt_w, dt_b, 1);
    k_scan  <<<dim3(DI,KK,3), 256, 0, sb>>>(A_logs, 1);
    k_mergeBias<<<dim3(72,3,1), 256, 0, sb>>>(onw, onb, ow, ob, Ds, 1);
    if (fork) cudaEventRecord(evJ, s2);

    // t = 1..3 (mode 2)
    for (int t = 1; t < TT; t++){
        k_conv  <<<dim3(DI,2,1), 256>>>(conv_w, conv_b, 2);
        k_xproj <<<dim3(48,KK,1), 192, XP_SMEM>>>(xp_w, dt_w, dt_b, 2);
        k_scan  <<<dim3(DI,KK,1), 256>>>(A_logs, 2);
        if (fork && t == 1) cudaStreamWaitEvent((cudaStream_t)0, evJ, 0);
        k_mergeSeq<<<dim3(144,1,1), 256, MS_SMEM>>>(onw, onb, ow, ob, Ds, in_w, in_b,
                                                    t, (t == TT-1) ? 1 : 0,
                                                    (t == TT-1) ? outp : nullptr);
    }
}

// round 13
// speedup vs baseline: 1.6999x; 1.0320x over previous
#include <cuda_runtime.h>

#define CI 64
#define DI 128
#define SS 16
#define RR 4
#define KK 4
#define HH 48
#define WW 48
#define LL 2304
#define TT 4
#define NB 5          // slices: 0..3 = bias frames, 4 = sequential pipeline
#define SB 4
#define NCH 16
#define LCH 144
#define LOG2E 1.4426950408889634f
#define LTX 32        // xproj l-tile
#define XP_SMEM ((DI*LTX + 36*DI + DI*RR + DI)*4)
#define MS_SMEM ((2048 + 16640 + 256 + 256 + 128 + 128 + 128 + 64 + 1024 + 256)*4)

// mode: 0 = critical first wave {z0: slice4(seq), z1: slice0(frame0)}
//       1 = frame stream {z: slice z+1}
//       2 = sequential {slice 4}
__device__ __forceinline__ int map_slice(int mode, int z){
    return (mode == 0) ? (z == 0 ? 4 : 0) : ((mode == 1) ? z + 1 : 4);
}

// ---------------- scratch (static device globals; no allocations) ----------------
__device__ float g_prev[CI*LL];
__device__ float g_cur [CI*LL];
__device__ float g_kl  [CI*LL];
__device__ float g_xln [TT*CI*LL];
__device__ float g_bias[TT*CI*LL];
__device__ float g_xz  [NB*2*DI*LL];
__device__ float g_xc  [NB*DI*LL];
__device__ float g_xcT [NB*DI*LL];
__device__ float g_dt  [NB*KK*DI*LL];
__device__ float g_dtx [NB*KK*DI*LL];
__device__ float g_B4  [NB*KK*LL*SS];   // [(slice,k)][l/4][s][4]
__device__ float g_C4  [NB*KK*LL*SS];
__device__ float g_y   [NB*KK*DI*LL];

// ---------------- init: y=0: prev/cur/kl(t0); y=1..4: xln[t]; grid(72,5), 128 thr ----------------
__global__ void k_init(const float* __restrict__ dz, const float* __restrict__ sigma,
                       const float* __restrict__ img,
                       const float* __restrict__ niw, const float* __restrict__ nib,
                       const float* __restrict__ ndw, const float* __restrict__ ndb){
    __shared__ float sx[CI*33];
    __shared__ float scur[CI*33];
    __shared__ float smu[32], srs[32], slp[32], slq[32];
    int l0 = blockIdx.x*32, tid = threadIdx.x;
    if (blockIdx.y == 0){
        for (int j = tid; j < CI*32; j += 128){
            int c = j >> 5, li = j & 31;
            sx[c*33 + li] = dz[c*LL + l0 + li];
        }
        __syncthreads();
        if (tid < 32){
            float s0 = 0.f, s1 = 0.f;
            for (int c = 0; c < CI; c++){ float v = sx[c*33 + tid]; s0 += v; s1 += v*v; }
            float mu = s0*(1.f/CI);
            smu[tid] = mu;
            srs[tid] = rsqrtf(s1*(1.f/CI) - mu*mu + 1e-6f);
        }
        __syncthreads();
        for (int j = tid; j < CI*32; j += 128){
            int c = j >> 5, li = j & 31;
            float pv = (sx[c*33+li] - smu[li])*srs[li]*ndw[c] + ndb[c];
            float cv = pv * __expf(sigma[c*LL + l0 + li]);
            g_prev[c*LL + l0 + li] = pv;
            g_cur [c*LL + l0 + li] = cv;
            sx  [c*33 + li] = pv;
            scur[c*33 + li] = cv;
        }
        __syncthreads();
        if (tid < 32){
            float mp = -1e30f, mq = -1e30f;
            for (int c = 0; c < CI; c++){
                mp = fmaxf(mp, sx  [c*33 + tid]);
                mq = fmaxf(mq, scur[c*33 + tid]);
            }
            float ep = 0.f, eq = 0.f;
            for (int c = 0; c < CI; c++){
                ep += __expf(sx  [c*33 + tid] - mp);
                eq += __expf(scur[c*33 + tid] - mq);
            }
            slp[tid] = mp + __logf(ep);
            slq[tid] = mq + __logf(eq);
        }
        __syncthreads();
        for (int j = tid; j < CI*32; j += 128){
            int c = j >> 5, li = j & 31;
            float lp = sx  [c*33+li] - slp[li];
            float lq = scur[c*33+li] - slq[li];
            g_kl[c*LL + l0 + li] = __expf(lp)*(lp - lq);
        }
    } else {
        int t = blockIdx.y - 1;
        for (int j = tid; j < CI*32; j += 128){
            int c = j >> 5, li = j & 31;
            sx[c*33 + li] = img[(t*CI + c)*LL + l0 + li];
        }
        __syncthreads();
        if (tid < 32){
            float s0 = 0.f, s1 = 0.f;
            for (int c = 0; c < CI; c++){ float v = sx[c*33 + tid]; s0 += v; s1 += v*v; }
            float mu = s0*(1.f/CI);
            smu[tid] = mu;
            srs[tid] = rsqrtf(s1*(1.f/CI) - mu*mu + 1e-6f);
        }
        __syncthreads();
        for (int j = tid; j < CI*32; j += 128){
            int c = j >> 5, li = j & 31;
            g_xln[(t*CI + c)*LL + l0 + li] = (sx[c*33+li] - smu[li])*srs[li]*niw[c] + nib[c];
        }
    }
}

// ---------------- in-projection GEMM; grid(18,8,nz), 128 thr ----------------
__global__ void k_inproj(const float* __restrict__ in_w, const float* __restrict__ in_b,
                         int mode){
    __shared__ float sx[64*128];
    __shared__ float swT[64*33];
    const int lt = blockIdx.x, dtile = blockIdx.y, tid = threadIdx.x;
    const int slice = map_slice(mode, blockIdx.z);
    const int m = (slice == SB) ? 0 : 1;
    const float* src = ((slice == SB) ? g_kl : (g_xln + slice*CI*LL)) + lt*128;
    for (int j = tid; j < 64*128; j += 128){
        int c = j >> 7;
        sx[j] = src[c*LL + tid];
    }
    for (int j = tid; j < 32*64; j += 128){
        int dp = j >> 6, c = j & 63;
        swT[c*33 + dp] = __ldg(&in_w[(m*256 + dtile*32 + dp)*64 + c]);
    }
    __syncthreads();
    int lq = tid & 31, dq = tid >> 5;
    float acc[8][4];
    #pragma unroll
    for (int i = 0; i < 8; i++){
        float bb = __ldg(&in_b[m*256 + dtile*32 + dq*8 + i]);
        #pragma unroll
        for (int j = 0; j < 4; j++) acc[i][j] = bb;
    }
    #pragma unroll 4
    for (int c = 0; c < 64; c++){
        float4 xv = *(const float4*)&sx[c*128 + lq*4];
        float xa[4] = {xv.x, xv.y, xv.z, xv.w};
        float wv[8];
        #pragma unroll
        for (int i = 0; i < 8; i++) wv[i] = swT[c*33 + dq*8 + i];
        #pragma unroll
        for (int i = 0; i < 8; i++)
            #pragma unroll
            for (int j = 0; j < 4; j++) acc[i][j] += wv[i]*xa[j];
    }
    #pragma unroll
    for (int i = 0; i < 8; i++){
        int d = dtile*32 + dq*8 + i;
        float* o = g_xz + ((size_t)slice*2*DI + d)*LL + lt*128 + lq*4;
        *(float4*)o = make_float4(acc[i][0], acc[i][1], acc[i][2], acc[i][3]);
    }
}

// ---------------- depthwise 3x3 conv v2 (half-plane blocks); grid(DI, 2*nz), 256 thr ----------------
__global__ void k_conv(const float* __restrict__ cw, const float* __restrict__ cb, int mode){
    __shared__ float sin[26*48];
    __shared__ float sc[24*49];
    int d = blockIdx.x, tid = threadIdx.x;
    int zz = blockIdx.y >> 1, half = blockIdx.y & 1;
    int slice = map_slice(mode, zz);
    int m = (slice == SB) ? 0 : 1;
    int h0 = half*24;
    const float* in = g_xz + ((size_t)slice*2*DI + d)*LL;
    for (int j = tid; j < 26*48; j += 256){
        int r = j/48, c = j%48;
        int gr = h0 - 1 + r;
        sin[j] = (gr >= 0 && gr < 48) ? in[gr*48 + c] : 0.f;
    }
    float w9[9];
    #pragma unroll
    for (int j = 0; j < 9; j++) w9[j] = __ldg(&cw[(m*DI + d)*9 + j]);
    float bias = __ldg(&cb[m*DI + d]);
    __syncthreads();
    for (int j = tid; j < 24*48; j += 256){
        int hh = j/48, w = j%48;
        float acc = 0.f;
        #pragma unroll
        for (int ky = 0; ky < 3; ky++){
            #pragma unroll
            for (int kx = 0; kx < 3; kx++){
                int wx = w + kx - 1;
                if (wx < 0 || wx >= 48) continue;
                acc += w9[ky*3+kx] * sin[(hh+ky)*48 + wx];
            }
        }
        acc += bias;
        acc = acc / (1.f + __expf(-acc));
        sc[hh*49 + w] = acc;
    }
    __syncthreads();
    float* oc = g_xc  + ((size_t)slice*DI + d)*LL;
    float* ot = g_xcT + ((size_t)slice*DI + d)*LL;
    for (int j = tid; j < 24*48; j += 256){
        int hh = j/48, w = j%48;
        oc[(h0+hh)*48 + w] = sc[hh*49 + w];
    }
    for (int j = tid; j < 48*24; j += 256){
        int w = j/24, hh = j%24;
        ot[w*48 + h0 + hh] = sc[hh*49 + w];
    }
}

// ---------------- x-projection v5: LTX=32 register-tiled GEMM; grid(72,K,nz), 128 thr ----------
__global__ __launch_bounds__(128) void k_xproj(const float* __restrict__ xpw,
                                               const float* __restrict__ dtw,
                                               const float* __restrict__ dtb,
                                               int mode){
    extern __shared__ float sm[];
    float* s1  = sm;                     // [DI][32] x-tile
    float* s2  = sm + DI*LTX;            // weights [36][DI] -> xdbl[36][32]
    float* sdw = s2 + 36*DI;
    float* sdb = sdw + DI*RR;
    int lt = blockIdx.x, k = blockIdx.y, tid = threadIdx.x;
    int slice = map_slice(mode, blockIdx.z);
    int m = (slice == SB) ? 0 : 1;
    const float* wk = xpw + (m*KK + k)*36*DI;
    for (int j = tid; j < 36*DI; j += 128) s2[j] = __ldg(&wk[j]);
    const float* dwk = dtw + (m*KK + k)*DI*RR;
    for (int j = tid; j < DI*RR; j += 128) sdw[j] = __ldg(&dwk[j]);
    if (tid < DI) sdb[tid] = __ldg(&dtb[(m*KK + k)*DI + tid]);
    bool fwd = (k < 2);
    const float* src = ((k & 1) ? g_xcT : g_xc) + (size_t)slice*DI*LL;
    for (int j = tid; j < DI*LTX; j += 128){
        int d = j/LTX, ls = j%LTX;
        int gl = fwd ? (lt*LTX + ls) : (LL-1 - (lt*LTX + ls));
        s1[j] = src[d*LL + gl];
    }
    __syncthreads();
    // GEMM: xdbl[36][32] = W[36][128] @ xs[128][32]; thread = (rg 0..3)x(lq 0..31), 9r x 1l
    int lq = tid & 31, rg = tid >> 5;
    const float4* w4 = (const float4*)s2;
    float acc[9];
    #pragma unroll
    for (int i = 0; i < 9; i++) acc[i] = 0.f;
    #pragma unroll 4
    for (int c4 = 0; c4 < 32; c4++){
        float4 w[9];
        #pragma unroll
        for (int i = 0; i < 9; i++) w[i] = w4[(rg*9 + i)*32 + c4];
        float x0 = s1[(c4*4 + 0)*LTX + lq];
        float x1 = s1[(c4*4 + 1)*LTX + lq];
        float x2 = s1[(c4*4 + 2)*LTX + lq];
        float x3 = s1[(c4*4 + 3)*LTX + lq];
        #pragma unroll
        for (int i = 0; i < 9; i++)
            acc[i] += w[i].x*x0 + w[i].y*x1 + w[i].z*x2 + w[i].w*x3;
    }
    __syncthreads();                     // weight reads done; s2 reusable
    float* xdbl = s2;
    #pragma unroll
    for (int i = 0; i < 9; i++) xdbl[(rg*9 + i)*LTX + lq] = acc[i];
    __syncthreads();
    // dt/dtx epilogue: x from resident s1
    int ls2 = tid & 31, rg2 = tid >> 5;
    float* dto  = g_dt  + ((size_t)(slice*KK + k)*DI)*LL + lt*LTX;
    float* dtxo = g_dtx + ((size_t)(slice*KK + k)*DI)*LL + lt*LTX;
    float xr0 = xdbl[0*LTX + ls2], xr1 = xdbl[1*LTX + ls2];
    float xr2 = xdbl[2*LTX + ls2], xr3 = xdbl[3*LTX + ls2];
    #pragma unroll 4
    for (int i = 0; i < 32; i++){
        int d = rg2 + 4*i;
        float v = sdb[d] + sdw[d*4+0]*xr0 + sdw[d*4+1]*xr1 + sdw[d*4+2]*xr2 + sdw[d*4+3]*xr3;
        v = fmaxf(v, 0.f) + log1pf(__expf(-fabsf(v)));
        dto [d*LL + ls2] = v;
        dtxo[d*LL + ls2] = v * s1[d*LTX + ls2];
    }
    float* b4 = g_B4 + (size_t)(slice*KK + k)*LL*SS;
    float* c4o = g_C4 + (size_t)(slice*KK + k)*LL*SS;
    for (int j = tid; j < LTX*SS; j += 128){
        int lls = j/SS, s = j%SS;
        int gl = lt*LTX + lls;
        size_t o = (size_t)(gl >> 2)*64 + s*4 + (gl & 3);
        b4 [o] = xdbl[(4 + s)*LTX + lls];
        c4o[o] = xdbl[(20 + s)*LTX + lls];
    }
}

// ---------------- scan: vec4 loads, smem transpose-reduce; grid(DI,K,nz), 256 thr ----------------
__global__ __launch_bounds__(256) void k_scan(const float* __restrict__ A_logs, int mode){
    __shared__ float pA[256], pH[256], hI[256];
    __shared__ float tv[8][544];
    int d = blockIdx.x, k = blockIdx.y, tid = threadIdx.x;
    int slice = map_slice(mode, blockIdx.z);
    int m = (slice == SB) ? 0 : 1;
    int s = tid & 15, c = tid >> 4;
    int w = tid >> 5, g = (tid >> 4) & 1;
    float* tile = &tv[w][g*272];
    float A2 = -__expf(__ldg(&A_logs[((m*KK + k)*DI + d)*SS + s])) * LOG2E;
    const float4* dt4 = (const float4*)(g_dt  + ((size_t)(slice*KK + k)*DI + d)*LL);
    const float4* dx4 = (const float4*)(g_dtx + ((size_t)(slice*KK + k)*DI + d)*LL);
    const float4* b4  = (const float4*)(g_B4 + (size_t)(slice*KK + k)*LL*SS);
    const float4* c4  = (const float4*)(g_C4 + (size_t)(slice*KK + k)*LL*SS);
    int q0 = c*36;
    float ap = 1.f, h = 0.f;
    #pragma unroll 4
    for (int q = 0; q < 36; q++){
        float4 dt = __ldg(&dt4[q0 + q]);
        float4 dx = __ldg(&dx4[q0 + q]);
        float4 bb = __ldg(&b4[(size_t)(q0 + q)*16 + s]);
        float da;
        da = exp2f(A2*dt.x); ap *= da; h = da*h + dx.x*bb.x;
        da = exp2f(A2*dt.y); ap *= da; h = da*h + dx.y*bb.y;
        da = exp2f(A2*dt.z); ap *= da; h = da*h + dx.z*bb.z;
        da = exp2f(A2*dt.w); ap *= da; h = da*h + dx.w*bb.w;
    }
    pA[tid] = ap; pH[tid] = h;
    __syncthreads();
    if (tid < 16){
        float hh = 0.f;
        #pragma unroll
        for (int cc = 0; cc < NCH; cc++){
            hI[cc*16 + tid] = hh;
            hh = pA[cc*16 + tid]*hh + pH[cc*16 + tid];
        }
    }
    __syncthreads();
    h = hI[tid];
    bool fwd = (k < 2);
    float* yrow = g_y + ((size_t)(slice*KK + k)*DI + d)*LL;
    int l0 = c*LCH;
    for (int blk = 0; blk < 9; blk++){
        #pragma unroll
        for (int qq = 0; qq < 4; qq++){
            int q = q0 + blk*4 + qq;
            float4 dt = __ldg(&dt4[q]);
            float4 dx = __ldg(&dx4[q]);
            float4 bb = __ldg(&b4[(size_t)q*16 + s]);
            float4 cc = __ldg(&c4[(size_t)q*16 + s]);
            float da;
            da = exp2f(A2*dt.x); h = da*h + dx.x*bb.x; tile[(qq*4+0)*17 + s] = h*cc.x;
            da = exp2f(A2*dt.y); h = da*h + dx.y*bb.y; tile[(qq*4+1)*17 + s] = h*cc.y;
            da = exp2f(A2*dt.z); h = da*h + dx.z*bb.z; tile[(qq*4+2)*17 + s] = h*cc.z;
            da = exp2f(A2*dt.w); h = da*h + dx.w*bb.w; tile[(qq*4+3)*17 + s] = h*cc.w;
        }
        __syncwarp();
        float sum = 0.f;
        #pragma unroll
        for (int s2 = 0; s2 < 16; s2++) sum += tile[s*17 + s2];
        int l = l0 + blk*16 + s;
        yrow[fwd ? l : (LL-1-l)] = sum;
        __syncwarp();
    }
}

// ---------------- bias merge (frame stream, m=1): grid(72,nf), 256 thr ----------------
__global__ void k_mergeBias(const float* __restrict__ onw, const float* __restrict__ onb,
                            const float* __restrict__ ow,  const float* __restrict__ ob,
                            const float* __restrict__ Dsp, int fofs){
    __shared__ float syy[DI*32];
    __shared__ float sow[CI*DI];
    __shared__ float red0[8*32], red1[8*32];
    __shared__ float ssum[DI], sonw[DI], sonb[DI], sob[CI];
    int tid = threadIdx.x;
    int lsub = tid & 31, dg = tid >> 5;
    int fb = blockIdx.y + fofs, slice = fb;
    int l = blockIdx.x*32 + lsub;
    int tl = (l % 48)*48 + l/48;
    for (int j = tid; j < CI*DI; j += 256) sow[j] = __ldg(&ow[CI*DI + j]);
    if (tid < DI){
        float s = 0.f;
        #pragma unroll
        for (int k = 0; k < KK; k++) s += __ldg(&Dsp[(KK + k)*DI + tid]);
        ssum[tid] = s;
        sonw[tid] = __ldg(&onw[DI + tid]);
        sonb[tid] = __ldg(&onb[DI + tid]);
    }
    if (tid < CI) sob[tid] = __ldg(&ob[CI + tid]);
    __syncthreads();
    float ps = 0.f, pq = 0.f;
    for (int i = 0; i < 16; i++){
        int d = dg*16 + i;
        const float* y0 = g_y + ((size_t)(slice*KK + 0)*DI + d)*LL;
        const float* y1 = g_y + ((size_t)(slice*KK + 1)*DI + d)*LL;
        const float* y2 = g_y + ((size_t)(slice*KK + 2)*DI + d)*LL;
        const float* y3 = g_y + ((size_t)(slice*KK + 3)*DI + d)*LL;
        float v = y0[l] + y2[l] + y1[tl] + y3[tl]
                + ssum[d] * g_xc[((size_t)slice*DI + d)*LL + l];
        syy[d*32 + lsub] = v;
        ps += v; pq += v*v;
    }
    red0[dg*32 + lsub] = ps; red1[dg*32 + lsub] = pq;
    __syncthreads();
    if (dg == 0){
        float s0 = 0.f, s1 = 0.f;
        #pragma unroll
        for (int j = 0; j < 8; j++){ s0 += red0[j*32 + lsub]; s1 += red1[j*32 + lsub]; }
        float mu  = s0 * (1.f/DI);
        float var = s1 * (1.f/DI) - mu*mu;
        red0[lsub] = mu;
        red1[lsub] = rsqrtf(var + 1e-6f);
    }
    __syncthreads();
    float mu = red0[lsub], rs = red1[lsub];
    for (int i = 0; i < 16; i++){
        int d = dg*16 + i;
        float v  = syy[d*32 + lsub];
        float wn = (v - mu)*rs*sonw[d] + sonb[d];
        float z  = g_xz[((size_t)slice*2*DI + DI + d)*LL + l];
        float sz = z / (1.f + __expf(-z));
        syy[d*32 + lsub] = wn * sz;
    }
    __syncthreads();
    float acc[8];
    #pragma unroll
    for (int i = 0; i < 8; i++) acc[i] = sob[dg*8 + i];
    for (int d = 0; d < DI; d++){
        float v = syy[d*32 + lsub];
        #pragma unroll
        for (int i = 0; i < 8; i++) acc[i] += sow[(dg*8 + i)*DI + d] * v;
    }
    #pragma unroll
    for (int i = 0; i < 8; i++)
        g_bias[(fb*CI + dg*8 + i)*LL + l] = acc[i];
}

// ---------------- sequential merge v3 (16-px blocks; optional inline frame-0 bias) ----------
// grid(144), 256 thr, dynamic smem
__global__ __launch_bounds__(256) void k_mergeSeq(
        const float* __restrict__ onw, const float* __restrict__ onb,
        const float* __restrict__ ow,  const float* __restrict__ ob,
        const float* __restrict__ Dsp,
        const float* __restrict__ in_w, const float* __restrict__ in_b,
        int t, int last, int biasFrame, float* __restrict__ outp){
    extern __shared__ float sm[];
    float* syy  = sm;              // 2048 (DI*16)
    float* un   = syy + 2048;      // 16640: sowT[128*65] then swT[64*260]
    float* red0 = un + 16640;      // 256
    float* red1 = red0 + 256;      // 256
    float* ssum = red1 + 256;      // 128
    float* sonw = ssum + 128;      // 128
    float* sonb = sonw + 128;      // 128
    float* sob  = sonb + 128;      // 64
    float* skl  = sob + 64;        // 1024 (CI*16)
    float* sbin = skl + 1024;      // 256
    const int slice = SB;
    int tid = threadIdx.x;
    int lsub = tid & 15, dg = tid >> 4;     // 16 px x 16 groups
    int l = blockIdx.x*16 + lsub;
    int tl = (l % 48)*48 + l/48;
    int cg = dg;
    float bacc[4];
    bool hasBias = (biasFrame >= 0);

    // ---- phase A: inline bias merge for frame biasFrame (m = 1) ----
    if (hasBias){
        int sa = biasFrame;
        for (int j = tid; j < CI*DI; j += 256){
            int row = j >> 7, d = j & 127;
            un[d*65 + row] = __ldg(&ow[CI*DI + j]);
        }
        if (tid < DI){
            float s = 0.f;
            #pragma unroll
            for (int k = 0; k < KK; k++) s += __ldg(&Dsp[(KK + k)*DI + tid]);
            ssum[tid] = s;
            sonw[tid] = __ldg(&onw[DI + tid]);
            sonb[tid] = __ldg(&onb[DI + tid]);
        }
        if (tid < CI) sob[tid] = __ldg(&ob[CI + tid]);
        __syncthreads();
        float ps = 0.f, pq = 0.f;
        #pragma unroll
        for (int i = 0; i < 8; i++){
            int d = dg*8 + i;
            const float* y0 = g_y + ((size_t)(sa*KK + 0)*DI + d)*LL;
            const float* y1 = g_y + ((size_t)(sa*KK + 1)*DI + d)*LL;
            const float* y2 = g_y + ((size_t)(sa*KK + 2)*DI + d)*LL;
            const float* y3 = g_y + ((size_t)(sa*KK + 3)*DI + d)*LL;
            float v = y0[l] + y2[l] + y1[tl] + y3[tl]
                    + ssum[d] * g_xc[((size_t)sa*DI + d)*LL + l];
            syy[d*16 + lsub] = v;
            ps += v; pq += v*v;
        }
        red0[dg*16 + lsub] = ps; red1[dg*16 + lsub] = pq;
        __syncthreads();
        if (tid < 16){
            float s0 = 0.f, s1 = 0.f;
            #pragma unroll
            for (int j = 0; j < 16; j++){ s0 += red0[j*16 + tid]; s1 += red1[j*16 + tid]; }
            float mu  = s0 * (1.f/DI);
            float var = s1 * (1.f/DI) - mu*mu;
            red0[tid] = mu;
            red1[tid] = rsqrtf(var + 1e-6f);
        }
        __syncthreads();
        float muA = red0[lsub], rsA = red1[lsub];
        #pragma unroll
        for (int i = 0; i < 8; i++){
            int d = dg*8 + i;
            float v  = syy[d*16 + lsub];
            float wn = (v - muA)*rsA*sonw[d] + sonb[d];
            float z  = g_xz[((size_t)sa*2*DI + DI + d)*LL + l];
            float sz = z / (1.f + __expf(-z));
            syy[d*16 + lsub] = wn * sz;
        }
        __syncthreads();
        #pragma unroll
        for (int i = 0; i < 4; i++) bacc[i] = sob[cg*4 + i];
        for (int d = 0; d < DI; d++){
            float v = syy[d*16 + lsub];
            #pragma unroll
            for (int i = 0; i < 4; i++) bacc[i] += un[d*65 + cg*4 + i] * v;
        }
        __syncthreads();   // phase-A reads of un/syy complete
    }

    // ---- stage m=0 params ----
    for (int j = tid; j < CI*DI; j += 256){
        int row = j >> 7, d = j & 127;
        un[d*65 + row] = __ldg(&ow[j]);
    }
    if (tid < DI){
        float s = 0.f;
        #pragma unroll
        for (int k = 0; k < KK; k++) s += __ldg(&Dsp[k*DI + tid]);
        ssum[tid] = s;
        sonw[tid] = __ldg(&onw[tid]);
        sonb[tid] = __ldg(&onb[tid]);
    }
    if (tid < CI) sob[tid] = __ldg(&ob[tid]);
    if (!last) sbin[tid] = __ldg(&in_b[tid]);
    __syncthreads();
    // direction merge + LN stats
    float ps = 0.f, pq = 0.f;
    #pragma unroll
    for (int i = 0; i < 8; i++){
        int d = dg*8 + i;
        const float* y0 = g_y + ((size_t)(slice*KK + 0)*DI + d)*LL;
        const float* y1 = g_y + ((size_t)(slice*KK + 1)*DI + d)*LL;
        const float* y2 = g_y + ((size_t)(slice*KK + 2)*DI + d)*LL;
        const float* y3 = g_y + ((size_t)(slice*KK + 3)*DI + d)*LL;
        float v = y0[l] + y2[l] + y1[tl] + y3[tl]
                + ssum[d] * g_xc[((size_t)slice*DI + d)*LL + l];
        syy[d*16 + lsub] = v;
        ps += v; pq += v*v;
    }
    red0[dg*16 + lsub] = ps; red1[dg*16 + lsub] = pq;
    __syncthreads();
    if (tid < 16){
        float s0 = 0.f, s1 = 0.f;
        #pragma unroll
        for (int j = 0; j < 16; j++){ s0 += red0[j*16 + tid]; s1 += red1[j*16 + tid]; }
        float mu  = s0 * (1.f/DI);
        float var = s1 * (1.f/DI) - mu*mu;
        red0[tid] = mu;
        red1[tid] = rsqrtf(var + 1e-6f);
    }
    __syncthreads();
    float mu = red0[lsub], rs = red1[lsub];
    #pragma unroll
    for (int i = 0; i < 8; i++){
        int d = dg*8 + i;
        float v  = syy[d*16 + lsub];
        float wn = (v - mu)*rs*sonw[d] + sonb[d];
        float z  = g_xz[((size_t)slice*2*DI + DI + d)*LL + l];
        float sz = z / (1.f + __expf(-z));
        syy[d*16 + lsub] = wn * sz;
    }
    __syncthreads();
    // out-projection: thread = 4 rows (cg*4+i) x 1 px (lsub)
    float acc[4];
    #pragma unroll
    for (int i = 0; i < 4; i++) acc[i] = sob[cg*4 + i];
    for (int d = 0; d < DI; d++){
        float v = syy[d*16 + lsub];
        #pragma unroll
        for (int i = 0; i < 4; i++) acc[i] += un[d*65 + cg*4 + i] * v;
    }
    // recurrent update
    float co[4], nv[4];
    #pragma unroll
    for (int i = 0; i < 4; i++){
        int cc = cg*4 + i;
        int idx = cc*LL + l;
        co[i] = g_cur[idx];
        g_prev[idx] = co[i];
        float bb = hasBias ? bacc[i] : g_bias[(t*CI + cc)*LL + l];
        nv[i] = co[i] * __expf(acc[i]) + bb;
        g_cur[idx] = nv[i];
    }
    if (last){
        #pragma unroll
        for (int i = 0; i < 4; i++) outp[(cg*4 + i)*LL + l] = nv[i];
        return;
    }
    __syncthreads();        // out-proj reads of un/syy complete
    // KL prep (syy) + swT load (un, overwriting sowT)
    #pragma unroll
    for (int i = 0; i < 4; i++){
        int cc = cg*4 + i;
        syy[cc*16 + lsub]        = co[i];
        syy[1024 + cc*16 + lsub] = nv[i];
    }
    for (int j = tid; j < 256*64; j += 256){
        int row = j >> 6, c = j & 63;
        un[c*260 + row] = __ldg(&in_w[row*64 + c]);
    }
    __syncthreads();
    if (tid < 16){
        float mp = -1e30f, mq = -1e30f;
        for (int cc = 0; cc < CI; cc++){
            mp = fmaxf(mp, syy[cc*16 + tid]);
            mq = fmaxf(mq, syy[1024 + cc*16 + tid]);
        }
        float ep = 0.f, eq = 0.f;
        for (int cc = 0; cc < CI; cc++){
            ep += __expf(syy[cc*16 + tid] - mp);
            eq += __expf(syy[1024 + cc*16 + tid] - mq);
        }
        red0[tid] = mp + __logf(ep);
        red1[tid] = mq + __logf(eq);
    }
    __syncthreads();
    float lsep = red0[lsub], lseq = red1[lsub];
    #pragma unroll
    for (int i = 0; i < 4; i++){
        int cc = cg*4 + i;
        float lp = syy[cc*16 + lsub] - lsep;
        float lq = syy[1024 + cc*16 + lsub] - lseq;
        skl[cc*16 + lsub] = __expf(lp)*(lp - lq);
    }
    __syncthreads();
    // fused in-projection for t+1: thread = 1 row (tid) x 16 px
    float a2[16];
    {
        float bb = sbin[tid];
        #pragma unroll
        for (int p = 0; p < 16; p++) a2[p] = bb;
    }
    for (int c = 0; c < 64; c++){
        float wv = un[c*260 + tid];
        float4 k0 = *(const float4*)&skl[c*16 + 0];
        float4 k1 = *(const float4*)&skl[c*16 + 4];
        float4 k2 = *(const float4*)&skl[c*16 + 8];
        float4 k3 = *(const float4*)&skl[c*16 + 12];
        a2[0]  += wv*k0.x; a2[1]  += wv*k0.y; a2[2]  += wv*k0.z; a2[3]  += wv*k0.w;
        a2[4]  += wv*k1.x; a2[5]  += wv*k1.y; a2[6]  += wv*k1.z; a2[7]  += wv*k1.w;
        a2[8]  += wv*k2.x; a2[9]  += wv*k2.y; a2[10] += wv*k2.z; a2[11] += wv*k2.w;
        a2[12] += wv*k3.x; a2[13] += wv*k3.y; a2[14] += wv*k3.z; a2[15] += wv*k3.w;
    }
    float* o = g_xz + ((size_t)SB*2*DI + tid)*LL + blockIdx.x*16;
    #pragma unroll
    for (int p = 0; p < 16; p += 4)
        *(float4*)&o[p] = make_float4(a2[p], a2[p+1], a2[p+2], a2[p+3]);
}

// ---------------- launch ----------------
extern "C" void kernel_launch(void* const* d_in, const int* in_sizes, int n_in,
                              void* d_out, int out_size){
    const float* img    = (const float*)d_in[0];
    const float* dz     = (const float*)d_in[1];
    const float* sigma  = (const float*)d_in[2];
    const float* in_w   = (const float*)d_in[3];
    const float* in_b   = (const float*)d_in[4];
    const float* conv_w = (const float*)d_in[5];
    const float* conv_b = (const float*)d_in[6];
    const float* xp_w   = (const float*)d_in[7];
    const float* dt_w   = (const float*)d_in[8];
    const float* dt_b   = (const float*)d_in[9];
    const float* A_logs = (const float*)d_in[10];
    const float* Ds     = (const float*)d_in[11];
    const float* onw    = (const float*)d_in[12];
    const float* onb    = (const float*)d_in[13];
    const float* ow     = (const float*)d_in[14];
    const float* ob     = (const float*)d_in[15];
    const float* niw    = (const float*)d_in[16];
    const float* nib    = (const float*)d_in[17];
    const float* ndw    = (const float*)d_in[18];
    const float* ndb    = (const float*)d_in[19];
    float* outp = (float*)d_out;

    cudaFuncSetAttribute(k_xproj, cudaFuncAttributeMaxDynamicSharedMemorySize, XP_SMEM);
    cudaFuncSetAttribute(k_mergeSeq, cudaFuncAttributeMaxDynamicSharedMemorySize, MS_SMEM);

    // fork/join stream for frames 1..3 (fallback: same stream, same-stream order stays correct)
    cudaStream_t s2 = 0;
    cudaEvent_t evF = 0, evJ = 0;
    bool fork = (cudaStreamCreateWithFlags(&s2, cudaStreamNonBlocking) == cudaSuccess);
    if (fork) fork = (cudaEventCreateWithFlags(&evF, cudaEventDisableTiming) == cudaSuccess);
    if (fork) fork = (cudaEventCreateWithFlags(&evJ, cudaEventDisableTiming) == cudaSuccess);
    cudaStream_t sb = fork ? s2 : (cudaStream_t)0;

    k_init<<<dim3(72,5,1), 128>>>(dz, sigma, img, niw, nib, ndw, ndb);

    if (fork){
        cudaEventRecord(evF, 0);
        cudaStreamWaitEvent(s2, evF, 0);
    }

    // critical first wave: {slice4 (t=0 seq), frame 0} (mode 0, nz=2)
    k_inproj<<<dim3(18,8,2), 128>>>(in_w, in_b, 0);
    k_conv  <<<dim3(DI,4,1), 256>>>(conv_w, conv_b, 0);
    k_xproj <<<dim3(72,KK,2), 128, XP_SMEM>>>(xp_w, dt_w, dt_b, 0);
    k_scan  <<<dim3(DI,KK,2), 256>>>(A_logs, 0);
    k_mergeSeq <<<dim3(144,1,1), 256, MS_SMEM>>>(onw, onb, ow, ob, Ds, in_w, in_b,
                                                 0, 0, 0, nullptr);

    // frame stream: frames 1..3 (mode 1, nz=3)
    k_inproj<<<dim3(18,8,3), 128, 0, sb>>>(in_w, in_b, 1);
    k_conv  <<<dim3(DI,6,1), 256, 0, sb>>>(conv_w, conv_b, 1);
    k_xproj <<<dim3(72,KK,3), 128, XP_SMEM, sb>>>(xp_w, dt_w, dt_b, 1);
    k_scan  <<<dim3(DI,KK,3), 256, 0, sb>>>(A_logs, 1);
    k_mergeBias<<<dim3(72,3,1), 256, 0, sb>>>(onw, onb, ow, ob, Ds, 1);
    if (fork) cudaEventRecord(evJ, s2);

    // t = 1..3 (mode 2)
    for (int t = 1; t < TT; t++){
        k_conv  <<<dim3(DI,2,1), 256>>>(conv_w, conv_b, 2);
        k_xproj <<<dim3(72,KK,1), 128, XP_SMEM>>>(xp_w, dt_w, dt_b, 2);
        k_scan  <<<dim3(DI,KK,1), 256>>>(A_logs, 2);
        if (fork && t == 1) cudaStreamWaitEvent((cudaStream_t)0, evJ, 0);
        k_mergeSeq<<<dim3(144,1,1), 256, MS_SMEM>>>(onw, onb, ow, ob, Ds, in_w, in_b,
                                                    t, (t == TT-1) ? 1 : 0, -1,
                                                    (t == TT-1) ? outp : nullptr);
    }
}